// round 11
// baseline (speedup 1.0000x reference)
#include <cuda_runtime.h>
#include <cuda_bf16.h>
#include <math.h>
#include <cstdint>

#define DEV_INLINE __device__ __forceinline__

constexpr int B_  = 8;
constexpr int N_  = 2048;
constexpr int D_  = 384;
constexpr int H_  = 6;
constexpr int DK_ = 64;
constexpr int BN_ = B_ * N_;       // 16384
constexpr int E3_ = 3 * D_;        // 1152
constexpr int FF_ = 2 * D_;        // 768
constexpr int CH_ = 3 + D_;        // 387
constexpr int D2_ = D_ / 2;        // 192 u32 per row

// ---------------- scratch (device globals) ----------------------------------
__device__ float    g_feats[BN_ * D_];
__device__ float    g_x[BN_ * D_];
__device__ uint32_t g_hh[BN_ * D2_],   g_hl[BN_ * D2_];       // LN out split
__device__ uint32_t g_qh[BN_ * D2_],   g_ql[BN_ * D2_];       // Q split
__device__ uint32_t g_ksh[BN_ * D2_],  g_ksl[BN_ * D2_];      // K split
__device__ uint16_t g_vth[(size_t)B_ * H_ * DK_ * N_];        // V^T hi bf16 [bh][dk][n]
__device__ uint16_t g_vtl[(size_t)B_ * H_ * DK_ * N_];        // V^T lo bf16
__device__ uint32_t g_ctxh[BN_ * D2_], g_ctxl[BN_ * D2_];     // attn ctx split
__device__ uint32_t g_ffh[BN_ * FF_ / 2], g_ffl[BN_ * FF_ / 2];
__device__ uint32_t g_wqh[E3_ * D2_],  g_wql[E3_ * D2_];
__device__ uint32_t g_woh[D_ * D2_],   g_wol[D_ * D2_];
__device__ uint32_t g_w1h[FF_ * D2_],  g_w1l[FF_ * D2_];
__device__ uint32_t g_w2h[D_ * FF_/2], g_w2l[D_ * FF_/2];

// ---------------- PTX helpers (sm_80-level only: target-safe) ---------------
DEV_INLINE uint32_t smem_u32(const void* p) {
    uint32_t a;
    asm("{ .reg .u64 t; cvta.to.shared.u64 t, %1; cvt.u32.u64 %0, t; }" : "=r"(a) : "l"(p));
    return a;
}
DEV_INLINE void ldsm4(uint32_t* r, uint32_t addr) {
    asm volatile("ldmatrix.sync.aligned.m8n8.x4.shared.b16 {%0,%1,%2,%3}, [%4];"
        : "=r"(r[0]), "=r"(r[1]), "=r"(r[2]), "=r"(r[3]) : "r"(addr));
}
DEV_INLINE void mma16(float* c, const uint32_t* a, uint32_t b0, uint32_t b1) {
    asm volatile("mma.sync.aligned.m16n8k16.row.col.f32.bf16.bf16.f32 "
        "{%0,%1,%2,%3}, {%4,%5,%6,%7}, {%8,%9}, {%0,%1,%2,%3};"
        : "+f"(c[0]), "+f"(c[1]), "+f"(c[2]), "+f"(c[3])
        : "r"(a[0]), "r"(a[1]), "r"(a[2]), "r"(a[3]), "r"(b0), "r"(b1));
}
DEV_INLINE float bf_hi(float x) { return __bfloat162float(__float2bfloat16_rn(x)); }
DEV_INLINE uint32_t pack_bf(float a, float b) {
    __nv_bfloat162 t = __floats2bfloat162_rn(a, b);
    return *reinterpret_cast<uint32_t*>(&t);
}
DEV_INLINE uint16_t bf_bits(float x) {
    __nv_bfloat16 t = __float2bfloat16_rn(x);
    return *reinterpret_cast<uint16_t*>(&t);
}

// ---------------- fast exp2 (FMA pipe) --------------------------------------
DEV_INLINE float fexp2(float x) {
    x = fmaxf(x, -125.0f);
    float r = rintf(x);
    float f = x - r;
    float p = 1.535336188319500e-4f;
    p = fmaf(p, f, 1.339887440266574e-3f);
    p = fmaf(p, f, 9.618437357674640e-3f);
    p = fmaf(p, f, 5.550332471162809e-2f);
    p = fmaf(p, f, 2.402264791363012e-1f);
    p = fmaf(p, f, 6.931472028550421e-1f);
    p = fmaf(p, f, 1.0f);
    return __int_as_float(((int)r + 127) << 23) * p;
}

// ---------------- weight split (single launch, range-dispatched) ------------
// Destination device globals bound in device code (host-side __device__ symbol
// args give the ATS-dereferenceable host shadow — the R7/R9 silent-zero bug).
__global__ void k_split_all(const float* __restrict__ wq, const float* __restrict__ wo,
                            const float* __restrict__ w1, const float* __restrict__ w2) {
    constexpr int n0 = E3_ * D2_;
    constexpr int n1 = n0 + D_ * D2_;
    constexpr int n2 = n1 + FF_ * D2_;
    constexpr int n3 = n2 + D_ * FF_ / 2;
    int i = blockIdx.x * 256 + threadIdx.x;
    const float* src; uint32_t* dh; uint32_t* dl; int off;
    if (i < n0)      { src = wq; dh = g_wqh; dl = g_wql; off = i; }
    else if (i < n1) { src = wo; dh = g_woh; dl = g_wol; off = i - n0; }
    else if (i < n2) { src = w1; dh = g_w1h; dl = g_w1l; off = i - n1; }
    else if (i < n3) { src = w2; dh = g_w2h; dl = g_w2l; off = i - n2; }
    else return;
    float2 v = *(const float2*)&src[(size_t)off * 2];
    float h0 = bf_hi(v.x), h1 = bf_hi(v.y);
    dh[off] = pack_bf(h0, h1);
    dl[off] = pack_bf(v.x - h0, v.y - h1);
}
constexpr int SPLIT_TOT = E3_ * D2_ + D_ * D2_ + FF_ * D2_ + D_ * FF_ / 2;

// ---------------- kernel 1: transpose + LN1 + coords ------------------------
__global__ void k_pre_ln(const float* __restrict__ pts,
                         const float* __restrict__ g1,
                         const float* __restrict__ b1,
                         float* __restrict__ out) {
    __shared__ float S[32][D_];
    int b  = blockIdx.x >> 6;
    int n0 = (blockIdx.x & 63) << 5;
    const float* base = pts + (size_t)b * CH_ * N_;
    int tid = threadIdx.x;

    for (int idx = tid; idx < 32 * D_; idx += 256) {
        int nl = idx & 31, d = idx >> 5;
        S[nl][d] = base[(size_t)(3 + d) * N_ + n0 + nl];
    }
    for (int idx = tid; idx < 96; idx += 256) {
        int nl = idx & 31, c = idx >> 5;
        out[(size_t)b * CH_ * N_ + (size_t)c * N_ + n0 + nl] = base[(size_t)c * N_ + n0 + nl];
    }
    __syncthreads();

    int w = tid >> 5, lane = tid & 31;
    #pragma unroll
    for (int i = 0; i < 4; i++) {
        int nl = w * 4 + i;
        float va[6], vb[6];
        float s = 0.f, ss = 0.f;
        #pragma unroll
        for (int j = 0; j < 6; j++) {
            int d = (lane + j * 32) * 2;
            va[j] = S[nl][d]; vb[j] = S[nl][d + 1];
            s += va[j] + vb[j];
            ss = fmaf(va[j], va[j], ss); ss = fmaf(vb[j], vb[j], ss);
        }
        #pragma unroll
        for (int o = 16; o; o >>= 1) {
            s  += __shfl_xor_sync(0xffffffffu, s,  o);
            ss += __shfl_xor_sync(0xffffffffu, ss, o);
        }
        float mu   = s * (1.0f / D_);
        float var  = ss * (1.0f / D_) - mu * mu;
        float rstd = rsqrtf(var + 1e-5f);
        size_t row = (size_t)b * N_ + n0 + nl;
        #pragma unroll
        for (int j = 0; j < 6; j++) {
            int d = (lane + j * 32) * 2;
            *(float2*)&g_feats[row * D_ + d] = make_float2(va[j], vb[j]);
            float2 gg = *(const float2*)&g1[d];
            float2 bb = *(const float2*)&b1[d];
            float ha = (va[j] - mu) * rstd * gg.x + bb.x;
            float hb = (vb[j] - mu) * rstd * gg.y + bb.y;
            float h0 = bf_hi(ha), h1 = bf_hi(hb);
            g_hh[row * D2_ + lane + j * 32] = pack_bf(h0, h1);
            g_hl[row * D2_ + lane + j * 32] = pack_bf(ha - h0, hb - h1);
        }
    }
}

// ---------------- bf16x3 GEMM, pre-split operands, double-buffered ----------
// C[m,e] = sum_k A[m,k] W[e,k]; tile 128x128, BK=32, 256 thr (8 warps m32n64)
constexpr int GEMM_SMEM = 2 * 4 * 2048 * 4;   // 65536 B

template <int KD, int EPI>
__global__ __launch_bounds__(256, 2) void k_gemm_mma(const float* __restrict__ bias,
                                                     float* __restrict__ out) {
    extern __shared__ uint32_t smu[];
    const uint32_t sb = smem_u32(smu);
    constexpr int KD2 = KD / 2;

    const uint32_t *Ahg, *Alg, *Bhg, *Blg;
    if constexpr (EPI == 0)      { Ahg = g_hh;   Alg = g_hl;   Bhg = g_wqh; Blg = g_wql; }
    else if constexpr (EPI == 1) { Ahg = g_ctxh; Alg = g_ctxl; Bhg = g_woh; Blg = g_wol; }
    else if constexpr (EPI == 2) { Ahg = g_hh;   Alg = g_hl;   Bhg = g_w1h; Blg = g_w1l; }
    else                         { Ahg = g_ffh;  Alg = g_ffl;  Bhg = g_w2h; Blg = g_w2l; }

    int m0 = blockIdx.y * 128;
    int e0 = blockIdx.x * 128;
    int tid = threadIdx.x;
    int wid = tid >> 5, l = tid & 31;
    int mq = wid & 3, nh = wid >> 2;
    int lr8 = l & 7, mat = l >> 3;

    float c[2][8][4];
    #pragma unroll
    for (int i = 0; i < 2; i++)
        #pragma unroll
        for (int j = 0; j < 8; j++)
            #pragma unroll
            for (int k = 0; k < 4; k++) c[i][j][k] = 0.f;

    constexpr int KT = KD / 32;

    uint2 pah[4], pal[4], pbh[4], pbl[4];
    #pragma unroll
    for (int i = 0; i < 4; i++) {
        int idx = tid + i * 256;
        int row = idx >> 3, c2 = (idx & 7) << 1;
        size_t ao = (size_t)(m0 + row) * KD2 + c2;
        size_t bo = (size_t)(e0 + row) * KD2 + c2;
        pah[i] = *(const uint2*)&Ahg[ao];
        pal[i] = *(const uint2*)&Alg[ao];
        pbh[i] = *(const uint2*)&Bhg[bo];
        pbl[i] = *(const uint2*)&Blg[bo];
    }

    for (int kt = 0; kt < KT; kt++) {
        uint32_t* Ah = smu + (kt & 1) * 8192;
        uint32_t* Al = Ah + 2048;
        uint32_t* Bh = Ah + 4096;
        uint32_t* Bl = Ah + 6144;
        #pragma unroll
        for (int i = 0; i < 4; i++) {
            int idx = tid + i * 256;
            int row = idx >> 3, c2 = (idx & 7) << 1;
            int u = row * 16 + (((c2 >> 2) ^ ((row >> 1) & 3)) << 2) + (c2 & 3);
            *(uint2*)&Ah[u] = pah[i];
            *(uint2*)&Al[u] = pal[i];
            *(uint2*)&Bh[u] = pbh[i];
            *(uint2*)&Bl[u] = pbl[i];
        }
        if (kt + 1 < KT) {
            int k2 = (kt + 1) * 16;
            #pragma unroll
            for (int i = 0; i < 4; i++) {
                int idx = tid + i * 256;
                int row = idx >> 3, c2 = (idx & 7) << 1;
                size_t ao = (size_t)(m0 + row) * KD2 + k2 + c2;
                size_t bo = (size_t)(e0 + row) * KD2 + k2 + c2;
                pah[i] = *(const uint2*)&Ahg[ao];
                pal[i] = *(const uint2*)&Alg[ao];
                pbh[i] = *(const uint2*)&Bhg[bo];
                pbl[i] = *(const uint2*)&Blg[bo];
            }
        }
        __syncthreads();

        uint32_t stg = sb + (uint32_t)(kt & 1) * 32768u;
        uint32_t ah_u = stg, al_u = stg + 8192, bh_u = stg + 16384, bl_u = stg + 24576;
        #pragma unroll
        for (int kc = 0; kc < 2; kc++) {
            uint32_t fah[2][4], fal[2][4];
            #pragma unroll
            for (int mt = 0; mt < 2; mt++) {
                int r = mq * 32 + mt * 16 + ((mat & 1) << 3) + lr8;
                int cch = kc * 2 + (mat >> 1);
                uint32_t off = (uint32_t)((r * 16 + ((cch ^ ((r >> 1) & 3)) << 2)) * 4);
                ldsm4(fah[mt], ah_u + off);
                ldsm4(fal[mt], al_u + off);
            }
            uint32_t fbh[4][4], fbl[4][4];
            #pragma unroll
            for (int g = 0; g < 4; g++) {
                int r = nh * 64 + g * 16 + ((mat >> 1) << 3) + lr8;
                int cch = kc * 2 + (mat & 1);
                uint32_t off = (uint32_t)((r * 16 + ((cch ^ ((r >> 1) & 3)) << 2)) * 4);
                ldsm4(fbh[g], bh_u + off);
                ldsm4(fbl[g], bl_u + off);
            }
            #pragma unroll
            for (int mt = 0; mt < 2; mt++)
                #pragma unroll
                for (int nt = 0; nt < 8; nt++) {
                    uint32_t b0h = fbh[nt >> 1][(nt & 1) * 2], b1h = fbh[nt >> 1][(nt & 1) * 2 + 1];
                    uint32_t b0l = fbl[nt >> 1][(nt & 1) * 2], b1l = fbl[nt >> 1][(nt & 1) * 2 + 1];
                    mma16(c[mt][nt], fah[mt], b0h, b1h);
                    mma16(c[mt][nt], fal[mt], b0h, b1h);
                    mma16(c[mt][nt], fah[mt], b0l, b1l);
                }
        }
    }

    // epilogue
    int r0 = l >> 2, cq = (l & 3) * 2;
    #pragma unroll
    for (int mt = 0; mt < 2; mt++) {
        #pragma unroll
        for (int mi = 0; mi < 2; mi++) {
            int m  = m0 + mq * 32 + mt * 16 + r0 + mi * 8;
            int bb = m >> 11;
            int n  = m & 2047;
            #pragma unroll
            for (int nt = 0; nt < 8; nt++) {
                int e = e0 + nh * 64 + nt * 8 + cq;
                float v0 = c[mt][nt][mi * 2 + 0];
                float v1 = c[mt][nt][mi * 2 + 1];
                if (EPI == 0) {
                    if (e < 2 * D_) {
                        float h0 = bf_hi(v0), h1 = bf_hi(v1);
                        uint32_t ph = pack_bf(h0, h1);
                        uint32_t pl = pack_bf(v0 - h0, v1 - h1);
                        if (e < D_) {
                            g_qh[(size_t)m * D2_ + (e >> 1)] = ph;
                            g_ql[(size_t)m * D2_ + (e >> 1)] = pl;
                        } else {
                            g_ksh[(size_t)m * D2_ + ((e - D_) >> 1)] = ph;
                            g_ksl[(size_t)m * D2_ + ((e - D_) >> 1)] = pl;
                        }
                    } else {
                        int eh = e - 2 * D_;
                        int hh = eh >> 6, dk = eh & 63;
                        size_t base = ((size_t)(bb * H_ + hh) * DK_ + dk) * N_ + n;
                        float h0 = bf_hi(v0);
                        g_vth[base] = bf_bits(v0);
                        g_vtl[base] = bf_bits(v0 - h0);
                        float h1 = bf_hi(v1);
                        g_vth[base + N_] = bf_bits(v1);
                        g_vtl[base + N_] = bf_bits(v1 - h1);
                    }
                } else if (EPI == 1) {
                    size_t idx = (size_t)m * D_ + e;
                    float2 f  = *(const float2*)&g_feats[idx];
                    float2 bv = *(const float2*)&bias[e];
                    *(float2*)&g_x[idx] = make_float2(v0 + bv.x + f.x, v1 + bv.y + f.y);
                } else if (EPI == 2) {
                    float2 bv = *(const float2*)&bias[e];
                    float t0 = v0 + bv.x, t1 = v1 + bv.y;
                    float u0 = 0.5f * t0 * (1.0f + erff(t0 * 0.70710678118f));
                    float u1 = 0.5f * t1 * (1.0f + erff(t1 * 0.70710678118f));
                    float h0 = bf_hi(u0), h1 = bf_hi(u1);
                    g_ffh[(size_t)m * (FF_/2) + (e >> 1)] = pack_bf(h0, h1);
                    g_ffl[(size_t)m * (FF_/2) + (e >> 1)] = pack_bf(u0 - h0, u1 - h1);
                } else {
                    size_t idx = (size_t)m * D_ + e;
                    float2 xv = *(const float2*)&g_x[idx];
                    float2 bv = *(const float2*)&bias[e];
                    size_t ob = (size_t)bb * CH_ * N_;
                    out[ob + (size_t)(3 + e)     * N_ + n] = v0 + bv.x + xv.x;
                    out[ob + (size_t)(3 + e + 1) * N_ + n] = v1 + bv.y + xv.y;
                }
            }
        }
    }
}

// ---------------- flash attention, q-tile 128 (8 warps), pre-split ----------
// grid (N/128, B*H), 256 thr; warp = 16 query rows vs shared K/V tiles.
// smem u32: Kh 0, Kl 2048, Vh 4096, Vl 6144, Psh 8192(4096), Psl 12288(4096)
constexpr int ATT_SMEM = 16384 * 4;   // 64 KB

__global__ __launch_bounds__(256) void k_attn_mma() {
    extern __shared__ uint32_t smu[];
    uint32_t* Kh  = smu;
    uint32_t* Kl  = smu + 2048;
    uint32_t* Vh  = smu + 4096;
    uint32_t* Vl  = smu + 6144;
    uint32_t* Psh = smu + 8192;
    uint32_t* Psl = smu + 12288;
    const uint32_t kh_u = smem_u32(Kh), kl_u = smem_u32(Kl);
    const uint32_t vh_u = smem_u32(Vh), vl_u = smem_u32(Vl);
    const uint32_t ph_u = smem_u32(Psh), pl_u = smem_u32(Psl);

    int bh = blockIdx.y;
    int b  = bh / H_, h = bh - b * H_;
    int q0 = blockIdx.x * 128;
    int tid = threadIdx.x;
    int wid = tid >> 5, l = tid & 31;
    int lr8 = l & 7, mat = l >> 3;
    int r0 = l >> 2, cq = (l & 3) * 2;

    const float SC = 0.125f * 1.44269504f;
    const size_t vtb = (size_t)(b * H_ + h) * DK_ * N_;

    // ---- stage Q (pre-split) through the P region (idle pre-loop) ----------
    #pragma unroll
    for (int i = 0; i < 8; i++) {
        int idx = tid + i * 256;
        int row = idx >> 4, c2 = (idx & 15) << 1;
        int u = row * 32 + (((c2 >> 2) ^ (row & 7)) << 2) + (c2 & 3);
        size_t so = (size_t)(b * N_ + q0 + row) * D2_ + h * 32 + c2;
        *(uint2*)&Psh[u] = *(const uint2*)&g_qh[so];
        *(uint2*)&Psl[u] = *(const uint2*)&g_ql[so];
    }
    __syncthreads();
    uint32_t qh[4][4], ql[4][4];
    #pragma unroll
    for (int kc = 0; kc < 4; kc++) {
        int r = wid * 16 + ((mat & 1) << 3) + lr8;
        int cch = kc * 2 + (mat >> 1);
        uint32_t off = (uint32_t)((r * 32 + ((cch ^ (r & 7)) << 2)) * 4);
        ldsm4(qh[kc], ph_u + off);
        ldsm4(ql[kc], pl_u + off);
    }
    __syncthreads();

    float o[8][4];
    #pragma unroll
    for (int i = 0; i < 8; i++)
        #pragma unroll
        for (int j = 0; j < 4; j++) o[i][j] = 0.f;
    float m0 = -1e30f, m1 = -1e30f, l0 = 0.f, l1 = 0.f;

    for (int kt0 = 0; kt0 < N_; kt0 += 64) {
        // ---- load K + V^T tiles (pre-split) --------------------------------
        uint2 rkh[4], rkl[4], rvh[4], rvl[4];
        #pragma unroll
        for (int i = 0; i < 4; i++) {
            int idx = tid + i * 256;
            int row = idx >> 4, c2 = (idx & 15) << 1, c4 = (idx & 15) << 2;
            size_t so = (size_t)(b * N_ + kt0 + row) * D2_ + h * 32 + c2;
            rkh[i] = *(const uint2*)&g_ksh[so];
            rkl[i] = *(const uint2*)&g_ksl[so];
            size_t vo = vtb + (size_t)row * N_ + kt0 + c4;
            rvh[i] = *(const uint2*)&g_vth[vo];
            rvl[i] = *(const uint2*)&g_vtl[vo];
        }
        __syncthreads();   // prior iteration's compute done
        #pragma unroll
        for (int i = 0; i < 4; i++) {
            int idx = tid + i * 256;
            int row = idx >> 4, c2 = (idx & 15) << 1;
            int u = row * 32 + (((c2 >> 2) ^ (row & 7)) << 2) + (c2 & 3);
            *(uint2*)&Kh[u] = rkh[i];
            *(uint2*)&Kl[u] = rkl[i];
            *(uint2*)&Vh[u] = rvh[i];
            *(uint2*)&Vl[u] = rvl[i];
        }
        __syncthreads();

        // ---- S = Q K^T (3xBF16), scale post-MMA ----------------------------
        float s[8][4];
        #pragma unroll
        for (int i = 0; i < 8; i++)
            #pragma unroll
            for (int j = 0; j < 4; j++) s[i][j] = 0.f;
        #pragma unroll
        for (int kc = 0; kc < 4; kc++) {
            uint32_t fbh[4][4], fbl[4][4];
            #pragma unroll
            for (int g = 0; g < 4; g++) {
                int r = g * 16 + ((mat >> 1) << 3) + lr8;
                int cch = kc * 2 + (mat & 1);
                uint32_t off = (uint32_t)((r * 32 + ((cch ^ (r & 7)) << 2)) * 4);
                ldsm4(fbh[g], kh_u + off);
                ldsm4(fbl[g], kl_u + off);
            }
            #pragma unroll
            for (int nt = 0; nt < 8; nt++) {
                uint32_t b0h = fbh[nt >> 1][(nt & 1) * 2], b1h = fbh[nt >> 1][(nt & 1) * 2 + 1];
                uint32_t b0l = fbl[nt >> 1][(nt & 1) * 2], b1l = fbl[nt >> 1][(nt & 1) * 2 + 1];
                mma16(s[nt], qh[kc], b0h, b1h);
                mma16(s[nt], ql[kc], b0h, b1h);
                mma16(s[nt], qh[kc], b0l, b1l);
            }
        }
        #pragma unroll
        for (int nt = 0; nt < 8; nt++) {
            s[nt][0] *= SC; s[nt][1] *= SC; s[nt][2] *= SC; s[nt][3] *= SC;
        }

        // ---- online softmax + P split store --------------------------------
        float mx0 = -1e30f, mx1 = -1e30f;
        #pragma unroll
        for (int nt = 0; nt < 8; nt++) {
            mx0 = fmaxf(mx0, fmaxf(s[nt][0], s[nt][1]));
            mx1 = fmaxf(mx1, fmaxf(s[nt][2], s[nt][3]));
        }
        mx0 = fmaxf(mx0, __shfl_xor_sync(0xffffffffu, mx0, 1));
        mx0 = fmaxf(mx0, __shfl_xor_sync(0xffffffffu, mx0, 2));
        mx1 = fmaxf(mx1, __shfl_xor_sync(0xffffffffu, mx1, 1));
        mx1 = fmaxf(mx1, __shfl_xor_sync(0xffffffffu, mx1, 2));
        float nm0 = fmaxf(m0, mx0), nm1 = fmaxf(m1, mx1);
        float f0 = fexp2(m0 - nm0), f1 = fexp2(m1 - nm1);
        m0 = nm0; m1 = nm1;
        float sum0 = 0.f, sum1 = 0.f;
        int wbase = wid * 512;
        int u0 = wbase + r0 * 32 + (l & 3);
        int u1 = wbase + (r0 + 8) * 32 + (l & 3);
        #pragma unroll
        for (int nt = 0; nt < 8; nt++) {
            float p0 = fexp2(s[nt][0] - m0);
            float p1 = fexp2(s[nt][1] - m0);
            float p2 = fexp2(s[nt][2] - m1);
            float p3 = fexp2(s[nt][3] - m1);
            sum0 += p0 + p1; sum1 += p2 + p3;
            float h0 = bf_hi(p0), h1 = bf_hi(p1), h2 = bf_hi(p2), h3 = bf_hi(p3);
            int sw0 = (nt ^ (r0 & 7)) << 2;
            Psh[u0 + sw0] = pack_bf(h0, h1);
            Psl[u0 + sw0] = pack_bf(p0 - h0, p1 - h1);
            Psh[u1 + sw0] = pack_bf(h2, h3);
            Psl[u1 + sw0] = pack_bf(p2 - h2, p3 - h3);
            o[nt][0] *= f0; o[nt][1] *= f0; o[nt][2] *= f1; o[nt][3] *= f1;
        }
        sum0 += __shfl_xor_sync(0xffffffffu, sum0, 1);
        sum0 += __shfl_xor_sync(0xffffffffu, sum0, 2);
        sum1 += __shfl_xor_sync(0xffffffffu, sum1, 1);
        sum1 += __shfl_xor_sync(0xffffffffu, sum1, 2);
        l0 = l0 * f0 + sum0;
        l1 = l1 * f1 + sum1;
        __syncwarp();

        // ---- O += P V (3xBF16) ---------------------------------------------
        #pragma unroll
        for (int kc = 0; kc < 4; kc++) {
            int rl = ((mat & 1) << 3) + lr8;
            int cch = kc * 2 + (mat >> 1);
            uint32_t poff = (uint32_t)((wbase + rl * 32 + ((cch ^ (rl & 7)) << 2)) * 4);
            uint32_t fph[4], fpl[4];
            ldsm4(fph, ph_u + poff);
            ldsm4(fpl, pl_u + poff);
            uint32_t fvh[4][4], fvl[4][4];
            #pragma unroll
            for (int g = 0; g < 4; g++) {
                int r = g * 16 + ((mat >> 1) << 3) + lr8;
                int cc2 = kc * 2 + (mat & 1);
                uint32_t off = (uint32_t)((r * 32 + ((cc2 ^ (r & 7)) << 2)) * 4);
                ldsm4(fvh[g], vh_u + off);
                ldsm4(fvl[g], vl_u + off);
            }
            #pragma unroll
            for (int nt = 0; nt < 8; nt++) {
                uint32_t b0h = fvh[nt >> 1][(nt & 1) * 2], b1h = fvh[nt >> 1][(nt & 1) * 2 + 1];
                uint32_t b0l = fvl[nt >> 1][(nt & 1) * 2], b1l = fvl[nt >> 1][(nt & 1) * 2 + 1];
                mma16(o[nt], fph, b0h, b1h);
                mma16(o[nt], fpl, b0h, b1h);
                mma16(o[nt], fph, b0l, b1l);
            }
        }
        __syncthreads();
    }

    // ---- finalize: write split ctx -----------------------------------------
    float inv0 = 1.0f / l0, inv1 = 1.0f / l1;
    int qa = q0 + wid * 16 + r0;
    #pragma unroll
    for (int nt = 0; nt < 8; nt++) {
        int d2 = (h * 64 + nt * 8 + cq) >> 1;
        float a0 = o[nt][0] * inv0, a1 = o[nt][1] * inv0;
        float h0 = bf_hi(a0), h1 = bf_hi(a1);
        g_ctxh[(size_t)(b * N_ + qa) * D2_ + d2] = pack_bf(h0, h1);
        g_ctxl[(size_t)(b * N_ + qa) * D2_ + d2] = pack_bf(a0 - h0, a1 - h1);
        float a2 = o[nt][2] * inv1, a3 = o[nt][3] * inv1;
        float h2 = bf_hi(a2), h3 = bf_hi(a3);
        g_ctxh[(size_t)(b * N_ + qa + 8) * D2_ + d2] = pack_bf(h2, h3);
        g_ctxl[(size_t)(b * N_ + qa + 8) * D2_ + d2] = pack_bf(a2 - h2, a3 - h3);
    }
}

// ---------------- LN2: read g_x f32, write split ----------------------------
__global__ void k_ln2(const float* __restrict__ g2, const float* __restrict__ b2) {
    int row  = blockIdx.x * 8 + (threadIdx.x >> 5);
    int lane = threadIdx.x & 31;
    const float* xr = g_x + (size_t)row * D_;
    float va[6], vb[6];
    float s = 0.f, ss = 0.f;
    #pragma unroll
    for (int j = 0; j < 6; j++) {
        float2 t = *(const float2*)&xr[(lane + j * 32) * 2];
        va[j] = t.x; vb[j] = t.y;
        s += t.x + t.y;
        ss = fmaf(t.x, t.x, ss); ss = fmaf(t.y, t.y, ss);
    }
    #pragma unroll
    for (int o = 16; o; o >>= 1) {
        s  += __shfl_xor_sync(0xffffffffu, s,  o);
        ss += __shfl_xor_sync(0xffffffffu, ss, o);
    }
    float mu   = s * (1.0f / D_);
    float var  = ss * (1.0f / D_) - mu * mu;
    float rstd = rsqrtf(var + 1e-5f);
    #pragma unroll
    for (int j = 0; j < 6; j++) {
        int d = (lane + j * 32) * 2;
        float2 gg = *(const float2*)&g2[d];
        float2 bb = *(const float2*)&b2[d];
        float ha = (va[j] - mu) * rstd * gg.x + bb.x;
        float hb = (vb[j] - mu) * rstd * gg.y + bb.y;
        float h0 = bf_hi(ha), h1 = bf_hi(hb);
        g_hh[(size_t)row * D2_ + lane + j * 32] = pack_bf(h0, h1);
        g_hl[(size_t)row * D2_ + lane + j * 32] = pack_bf(ha - h0, hb - h1);
    }
}

// ---------------- launch ----------------------------------------------------
extern "C" void kernel_launch(void* const* d_in, const int* in_sizes, int n_in,
                              void* d_out, int out_size) {
    const float* pts   = (const float*)d_in[0];
    const float* ln1_g = (const float*)d_in[1];
    const float* ln1_b = (const float*)d_in[2];
    const float* w_qkv = (const float*)d_in[3];
    const float* w_o   = (const float*)d_in[4];
    const float* b_o   = (const float*)d_in[5];
    const float* ln2_g = (const float*)d_in[6];
    const float* ln2_b = (const float*)d_in[7];
    const float* w1    = (const float*)d_in[8];
    const float* b1    = (const float*)d_in[9];
    const float* w2    = (const float*)d_in[10];
    const float* b2    = (const float*)d_in[11];
    float* out = (float*)d_out;

    cudaFuncSetAttribute(k_gemm_mma<D_, 0>,  cudaFuncAttributeMaxDynamicSharedMemorySize, GEMM_SMEM);
    cudaFuncSetAttribute(k_gemm_mma<D_, 1>,  cudaFuncAttributeMaxDynamicSharedMemorySize, GEMM_SMEM);
    cudaFuncSetAttribute(k_gemm_mma<D_, 2>,  cudaFuncAttributeMaxDynamicSharedMemorySize, GEMM_SMEM);
    cudaFuncSetAttribute(k_gemm_mma<FF_, 3>, cudaFuncAttributeMaxDynamicSharedMemorySize, GEMM_SMEM);
    cudaFuncSetAttribute(k_attn_mma,         cudaFuncAttributeMaxDynamicSharedMemorySize, ATT_SMEM);

    k_split_all<<<(SPLIT_TOT + 255) / 256, 256>>>(w_qkv, w_o, w1, w2);
    k_pre_ln<<<512, 256>>>(pts, ln1_g, ln1_b, out);
    k_gemm_mma<D_, 0><<<dim3(E3_ / 128, BN_ / 128), 256, GEMM_SMEM>>>(nullptr, nullptr);
    k_attn_mma<<<dim3(N_ / 128, B_ * H_), 256, ATT_SMEM>>>();
    k_gemm_mma<D_, 1><<<dim3(D_ / 128, BN_ / 128), 256, GEMM_SMEM>>>(b_o, nullptr);
    k_ln2<<<BN_ / 8, 256>>>(ln2_g, ln2_b);
    k_gemm_mma<D_, 2><<<dim3(FF_ / 128, BN_ / 128), 256, GEMM_SMEM>>>(b1, nullptr);
    k_gemm_mma<FF_, 3><<<dim3(D_ / 128, BN_ / 128), 256, GEMM_SMEM>>>(b2, out);
}

// round 12
// speedup vs baseline: 1.1439x; 1.1439x over previous
#include <cuda_runtime.h>
#include <cuda_bf16.h>
#include <math.h>
#include <cstdint>

#define DEV_INLINE __device__ __forceinline__

constexpr int B_  = 8;
constexpr int N_  = 2048;
constexpr int D_  = 384;
constexpr int H_  = 6;
constexpr int DK_ = 64;
constexpr int BN_ = B_ * N_;       // 16384
constexpr int E3_ = 3 * D_;        // 1152
constexpr int FF_ = 2 * D_;        // 768
constexpr int CH_ = 3 + D_;        // 387
constexpr int D2_ = D_ / 2;        // 192 u32 per row

// ---------------- scratch (device globals) ----------------------------------
__device__ float    g_feats[BN_ * D_];
__device__ float    g_x[BN_ * D_];
__device__ uint32_t g_hh[BN_ * D2_],   g_hl[BN_ * D2_];       // LN out split
__device__ uint32_t g_qh[BN_ * D2_],   g_ql[BN_ * D2_];       // Q split
__device__ uint32_t g_ksh[BN_ * D2_],  g_ksl[BN_ * D2_];      // K split
__device__ uint16_t g_vth[(size_t)B_ * H_ * DK_ * N_];        // V^T hi bf16 [bh][dk][n]
__device__ uint16_t g_vtl[(size_t)B_ * H_ * DK_ * N_];        // V^T lo bf16
__device__ uint32_t g_ctxh[BN_ * D2_], g_ctxl[BN_ * D2_];     // attn ctx split
__device__ uint32_t g_ffh[BN_ * FF_ / 2], g_ffl[BN_ * FF_ / 2];
__device__ uint32_t g_wqh[E3_ * D2_],  g_wql[E3_ * D2_];
__device__ uint32_t g_woh[D_ * D2_],   g_wol[D_ * D2_];
__device__ uint32_t g_w1h[FF_ * D2_],  g_w1l[FF_ * D2_];
__device__ uint32_t g_w2h[D_ * FF_/2], g_w2l[D_ * FF_/2];

// ---------------- PTX helpers (sm_80-level only: target-safe) ---------------
DEV_INLINE uint32_t smem_u32(const void* p) {
    uint32_t a;
    asm("{ .reg .u64 t; cvta.to.shared.u64 t, %1; cvt.u32.u64 %0, t; }" : "=r"(a) : "l"(p));
    return a;
}
DEV_INLINE void ldsm4(uint32_t* r, uint32_t addr) {
    asm volatile("ldmatrix.sync.aligned.m8n8.x4.shared.b16 {%0,%1,%2,%3}, [%4];"
        : "=r"(r[0]), "=r"(r[1]), "=r"(r[2]), "=r"(r[3]) : "r"(addr));
}
DEV_INLINE void mma16(float* c, const uint32_t* a, uint32_t b0, uint32_t b1) {
    asm volatile("mma.sync.aligned.m16n8k16.row.col.f32.bf16.bf16.f32 "
        "{%0,%1,%2,%3}, {%4,%5,%6,%7}, {%8,%9}, {%0,%1,%2,%3};"
        : "+f"(c[0]), "+f"(c[1]), "+f"(c[2]), "+f"(c[3])
        : "r"(a[0]), "r"(a[1]), "r"(a[2]), "r"(a[3]), "r"(b0), "r"(b1));
}
DEV_INLINE float bf_hi(float x) { return __bfloat162float(__float2bfloat16_rn(x)); }
DEV_INLINE uint32_t pack_bf(float a, float b) {
    __nv_bfloat162 t = __floats2bfloat162_rn(a, b);
    return *reinterpret_cast<uint32_t*>(&t);
}
DEV_INLINE uint16_t bf_bits(float x) {
    __nv_bfloat16 t = __float2bfloat16_rn(x);
    return *reinterpret_cast<uint16_t*>(&t);
}

// ---------------- fast exp2 (FMA pipe) --------------------------------------
DEV_INLINE float fexp2(float x) {
    x = fmaxf(x, -125.0f);
    float r = rintf(x);
    float f = x - r;
    float p = 1.535336188319500e-4f;
    p = fmaf(p, f, 1.339887440266574e-3f);
    p = fmaf(p, f, 9.618437357674640e-3f);
    p = fmaf(p, f, 5.550332471162809e-2f);
    p = fmaf(p, f, 2.402264791363012e-1f);
    p = fmaf(p, f, 6.931472028550421e-1f);
    p = fmaf(p, f, 1.0f);
    return __int_as_float(((int)r + 127) << 23) * p;
}

// ---------------- weight split (single launch, range-dispatched) ------------
// Destinations bound in device code (host-side __device__ symbol args give the
// ATS-dereferenceable host shadow — the R7/R9 silent-zero bug).
__global__ void k_split_all(const float* __restrict__ wq, const float* __restrict__ wo,
                            const float* __restrict__ w1, const float* __restrict__ w2) {
    constexpr int n0 = E3_ * D2_;
    constexpr int n1 = n0 + D_ * D2_;
    constexpr int n2 = n1 + FF_ * D2_;
    constexpr int n3 = n2 + D_ * FF_ / 2;
    int i = blockIdx.x * 256 + threadIdx.x;
    const float* src; uint32_t* dh; uint32_t* dl; int off;
    if (i < n0)      { src = wq; dh = g_wqh; dl = g_wql; off = i; }
    else if (i < n1) { src = wo; dh = g_woh; dl = g_wol; off = i - n0; }
    else if (i < n2) { src = w1; dh = g_w1h; dl = g_w1l; off = i - n1; }
    else if (i < n3) { src = w2; dh = g_w2h; dl = g_w2l; off = i - n2; }
    else return;
    float2 v = *(const float2*)&src[(size_t)off * 2];
    float h0 = bf_hi(v.x), h1 = bf_hi(v.y);
    dh[off] = pack_bf(h0, h1);
    dl[off] = pack_bf(v.x - h0, v.y - h1);
}
constexpr int SPLIT_TOT = E3_ * D2_ + D_ * D2_ + FF_ * D2_ + D_ * FF_ / 2;

// ---------------- kernel 1: transpose + LN1 + coords ------------------------
__global__ void k_pre_ln(const float* __restrict__ pts,
                         const float* __restrict__ g1,
                         const float* __restrict__ b1,
                         float* __restrict__ out) {
    __shared__ float S[32][D_];
    int b  = blockIdx.x >> 6;
    int n0 = (blockIdx.x & 63) << 5;
    const float* base = pts + (size_t)b * CH_ * N_;
    int tid = threadIdx.x;

    for (int idx = tid; idx < 32 * D_; idx += 256) {
        int nl = idx & 31, d = idx >> 5;
        S[nl][d] = base[(size_t)(3 + d) * N_ + n0 + nl];
    }
    for (int idx = tid; idx < 96; idx += 256) {
        int nl = idx & 31, c = idx >> 5;
        out[(size_t)b * CH_ * N_ + (size_t)c * N_ + n0 + nl] = base[(size_t)c * N_ + n0 + nl];
    }
    __syncthreads();

    int w = tid >> 5, lane = tid & 31;
    #pragma unroll
    for (int i = 0; i < 4; i++) {
        int nl = w * 4 + i;
        float va[6], vb[6];
        float s = 0.f, ss = 0.f;
        #pragma unroll
        for (int j = 0; j < 6; j++) {
            int d = (lane + j * 32) * 2;
            va[j] = S[nl][d]; vb[j] = S[nl][d + 1];
            s += va[j] + vb[j];
            ss = fmaf(va[j], va[j], ss); ss = fmaf(vb[j], vb[j], ss);
        }
        #pragma unroll
        for (int o = 16; o; o >>= 1) {
            s  += __shfl_xor_sync(0xffffffffu, s,  o);
            ss += __shfl_xor_sync(0xffffffffu, ss, o);
        }
        float mu   = s * (1.0f / D_);
        float var  = ss * (1.0f / D_) - mu * mu;
        float rstd = rsqrtf(var + 1e-5f);
        size_t row = (size_t)b * N_ + n0 + nl;
        #pragma unroll
        for (int j = 0; j < 6; j++) {
            int d = (lane + j * 32) * 2;
            *(float2*)&g_feats[row * D_ + d] = make_float2(va[j], vb[j]);
            float2 gg = *(const float2*)&g1[d];
            float2 bb = *(const float2*)&b1[d];
            float ha = (va[j] - mu) * rstd * gg.x + bb.x;
            float hb = (vb[j] - mu) * rstd * gg.y + bb.y;
            float h0 = bf_hi(ha), h1 = bf_hi(hb);
            g_hh[row * D2_ + lane + j * 32] = pack_bf(h0, h1);
            g_hl[row * D2_ + lane + j * 32] = pack_bf(ha - h0, hb - h1);
        }
    }
}

// ---------------- bf16x3 GEMM, pre-split operands, double-buffered ----------
// C[m,e] = sum_k A[m,k] W[e,k]; tile 128x128, BK=32, 256 thr (8 warps m32n64)
constexpr int GEMM_SMEM = 2 * 4 * 2048 * 4;   // 65536 B

template <int KD, int EPI>
__global__ __launch_bounds__(256, 2) void k_gemm_mma(const float* __restrict__ bias,
                                                     float* __restrict__ out) {
    extern __shared__ uint32_t smu[];
    const uint32_t sb = smem_u32(smu);
    constexpr int KD2 = KD / 2;

    const uint32_t *Ahg, *Alg, *Bhg, *Blg;
    if constexpr (EPI == 0)      { Ahg = g_hh;   Alg = g_hl;   Bhg = g_wqh; Blg = g_wql; }
    else if constexpr (EPI == 1) { Ahg = g_ctxh; Alg = g_ctxl; Bhg = g_woh; Blg = g_wol; }
    else if constexpr (EPI == 2) { Ahg = g_hh;   Alg = g_hl;   Bhg = g_w1h; Blg = g_w1l; }
    else                         { Ahg = g_ffh;  Alg = g_ffl;  Bhg = g_w2h; Blg = g_w2l; }

    int m0 = blockIdx.y * 128;
    int e0 = blockIdx.x * 128;
    int tid = threadIdx.x;
    int wid = tid >> 5, l = tid & 31;
    int mq = wid & 3, nh = wid >> 2;
    int lr8 = l & 7, mat = l >> 3;

    float c[2][8][4];
    #pragma unroll
    for (int i = 0; i < 2; i++)
        #pragma unroll
        for (int j = 0; j < 8; j++)
            #pragma unroll
            for (int k = 0; k < 4; k++) c[i][j][k] = 0.f;

    constexpr int KT = KD / 32;

    uint2 pah[4], pal[4], pbh[4], pbl[4];
    #pragma unroll
    for (int i = 0; i < 4; i++) {
        int idx = tid + i * 256;
        int row = idx >> 3, c2 = (idx & 7) << 1;
        size_t ao = (size_t)(m0 + row) * KD2 + c2;
        size_t bo = (size_t)(e0 + row) * KD2 + c2;
        pah[i] = *(const uint2*)&Ahg[ao];
        pal[i] = *(const uint2*)&Alg[ao];
        pbh[i] = *(const uint2*)&Bhg[bo];
        pbl[i] = *(const uint2*)&Blg[bo];
    }

    for (int kt = 0; kt < KT; kt++) {
        uint32_t* Ah = smu + (kt & 1) * 8192;
        uint32_t* Al = Ah + 2048;
        uint32_t* Bh = Ah + 4096;
        uint32_t* Bl = Ah + 6144;
        #pragma unroll
        for (int i = 0; i < 4; i++) {
            int idx = tid + i * 256;
            int row = idx >> 3, c2 = (idx & 7) << 1;
            int u = row * 16 + (((c2 >> 2) ^ ((row >> 1) & 3)) << 2) + (c2 & 3);
            *(uint2*)&Ah[u] = pah[i];
            *(uint2*)&Al[u] = pal[i];
            *(uint2*)&Bh[u] = pbh[i];
            *(uint2*)&Bl[u] = pbl[i];
        }
        if (kt + 1 < KT) {
            int k2 = (kt + 1) * 16;
            #pragma unroll
            for (int i = 0; i < 4; i++) {
                int idx = tid + i * 256;
                int row = idx >> 3, c2 = (idx & 7) << 1;
                size_t ao = (size_t)(m0 + row) * KD2 + k2 + c2;
                size_t bo = (size_t)(e0 + row) * KD2 + k2 + c2;
                pah[i] = *(const uint2*)&Ahg[ao];
                pal[i] = *(const uint2*)&Alg[ao];
                pbh[i] = *(const uint2*)&Bhg[bo];
                pbl[i] = *(const uint2*)&Blg[bo];
            }
        }
        __syncthreads();

        uint32_t stg = sb + (uint32_t)(kt & 1) * 32768u;
        uint32_t ah_u = stg, al_u = stg + 8192, bh_u = stg + 16384, bl_u = stg + 24576;
        #pragma unroll
        for (int kc = 0; kc < 2; kc++) {
            uint32_t fah[2][4], fal[2][4];
            #pragma unroll
            for (int mt = 0; mt < 2; mt++) {
                int r = mq * 32 + mt * 16 + ((mat & 1) << 3) + lr8;
                int cch = kc * 2 + (mat >> 1);
                uint32_t off = (uint32_t)((r * 16 + ((cch ^ ((r >> 1) & 3)) << 2)) * 4);
                ldsm4(fah[mt], ah_u + off);
                ldsm4(fal[mt], al_u + off);
            }
            uint32_t fbh[4][4], fbl[4][4];
            #pragma unroll
            for (int g = 0; g < 4; g++) {
                int r = nh * 64 + g * 16 + ((mat >> 1) << 3) + lr8;
                int cch = kc * 2 + (mat & 1);
                uint32_t off = (uint32_t)((r * 16 + ((cch ^ ((r >> 1) & 3)) << 2)) * 4);
                ldsm4(fbh[g], bh_u + off);
                ldsm4(fbl[g], bl_u + off);
            }
            #pragma unroll
            for (int mt = 0; mt < 2; mt++)
                #pragma unroll
                for (int nt = 0; nt < 8; nt++) {
                    uint32_t b0h = fbh[nt >> 1][(nt & 1) * 2], b1h = fbh[nt >> 1][(nt & 1) * 2 + 1];
                    uint32_t b0l = fbl[nt >> 1][(nt & 1) * 2], b1l = fbl[nt >> 1][(nt & 1) * 2 + 1];
                    mma16(c[mt][nt], fah[mt], b0h, b1h);
                    mma16(c[mt][nt], fal[mt], b0h, b1h);
                    mma16(c[mt][nt], fah[mt], b0l, b1l);
                }
        }
    }

    // epilogue
    int r0 = l >> 2, cq = (l & 3) * 2;
    #pragma unroll
    for (int mt = 0; mt < 2; mt++) {
        #pragma unroll
        for (int mi = 0; mi < 2; mi++) {
            int m  = m0 + mq * 32 + mt * 16 + r0 + mi * 8;
            int bb = m >> 11;
            int n  = m & 2047;
            #pragma unroll
            for (int nt = 0; nt < 8; nt++) {
                int e = e0 + nh * 64 + nt * 8 + cq;
                float v0 = c[mt][nt][mi * 2 + 0];
                float v1 = c[mt][nt][mi * 2 + 1];
                if (EPI == 0) {
                    if (e < 2 * D_) {
                        float h0 = bf_hi(v0), h1 = bf_hi(v1);
                        uint32_t ph = pack_bf(h0, h1);
                        uint32_t pl = pack_bf(v0 - h0, v1 - h1);
                        if (e < D_) {
                            g_qh[(size_t)m * D2_ + (e >> 1)] = ph;
                            g_ql[(size_t)m * D2_ + (e >> 1)] = pl;
                        } else {
                            g_ksh[(size_t)m * D2_ + ((e - D_) >> 1)] = ph;
                            g_ksl[(size_t)m * D2_ + ((e - D_) >> 1)] = pl;
                        }
                    } else {
                        int eh = e - 2 * D_;
                        int hh = eh >> 6, dk = eh & 63;
                        size_t base = ((size_t)(bb * H_ + hh) * DK_ + dk) * N_ + n;
                        float h0 = bf_hi(v0);
                        g_vth[base] = bf_bits(v0);
                        g_vtl[base] = bf_bits(v0 - h0);
                        float h1 = bf_hi(v1);
                        g_vth[base + N_] = bf_bits(v1);
                        g_vtl[base + N_] = bf_bits(v1 - h1);
                    }
                } else if (EPI == 1) {
                    size_t idx = (size_t)m * D_ + e;
                    float2 f  = *(const float2*)&g_feats[idx];
                    float2 bv = *(const float2*)&bias[e];
                    *(float2*)&g_x[idx] = make_float2(v0 + bv.x + f.x, v1 + bv.y + f.y);
                } else if (EPI == 2) {
                    float2 bv = *(const float2*)&bias[e];
                    float t0 = v0 + bv.x, t1 = v1 + bv.y;
                    float u0 = 0.5f * t0 * (1.0f + erff(t0 * 0.70710678118f));
                    float u1 = 0.5f * t1 * (1.0f + erff(t1 * 0.70710678118f));
                    float h0 = bf_hi(u0), h1 = bf_hi(u1);
                    g_ffh[(size_t)m * (FF_/2) + (e >> 1)] = pack_bf(h0, h1);
                    g_ffl[(size_t)m * (FF_/2) + (e >> 1)] = pack_bf(u0 - h0, u1 - h1);
                } else {
                    size_t idx = (size_t)m * D_ + e;
                    float2 xv = *(const float2*)&g_x[idx];
                    float2 bv = *(const float2*)&bias[e];
                    size_t ob = (size_t)bb * CH_ * N_;
                    out[ob + (size_t)(3 + e)     * N_ + n] = v0 + bv.x + xv.x;
                    out[ob + (size_t)(3 + e + 1) * N_ + n] = v1 + bv.y + xv.y;
                }
            }
        }
    }
}

// ---------------- flash attention, q-tile 64, 128 thr (round-10 proven) -----
constexpr int ATT_SMEM = 12288 * 4;   // Kh,Kl,Vh,Vl,Psh,Psl (2048 u32 each)

__global__ __launch_bounds__(128) void k_attn_mma() {
    extern __shared__ uint32_t smu[];
    uint32_t* Kh  = smu;
    uint32_t* Kl  = smu + 2048;
    uint32_t* Vh  = smu + 4096;
    uint32_t* Vl  = smu + 6144;
    uint32_t* Psh = smu + 8192;
    uint32_t* Psl = smu + 10240;
    const uint32_t kh_u = smem_u32(Kh), kl_u = smem_u32(Kl);
    const uint32_t vh_u = smem_u32(Vh), vl_u = smem_u32(Vl);
    const uint32_t ph_u = smem_u32(Psh), pl_u = smem_u32(Psl);

    int bh = blockIdx.y;
    int b  = bh / H_, h = bh - b * H_;
    int q0 = blockIdx.x * 64;
    int tid = threadIdx.x;
    int wid = tid >> 5, l = tid & 31;
    int lr8 = l & 7, mat = l >> 3;
    int r0 = l >> 2, cq = (l & 3) * 2;

    const float SC = 0.125f * 1.44269504f;
    const size_t vtb = (size_t)(b * H_ + h) * DK_ * N_;

    // ---- stage Q (pre-split) into Kh/Kl, build register fragments ----------
    #pragma unroll
    for (int i = 0; i < 8; i++) {
        int idx = tid + i * 128;
        int row = idx >> 4, c2 = (idx & 15) << 1;
        int u = row * 32 + (((c2 >> 2) ^ (row & 7)) << 2) + (c2 & 3);
        size_t so = (size_t)(b * N_ + q0 + row) * D2_ + h * 32 + c2;
        *(uint2*)&Kh[u] = *(const uint2*)&g_qh[so];
        *(uint2*)&Kl[u] = *(const uint2*)&g_ql[so];
    }
    __syncthreads();
    uint32_t qh[4][4], ql[4][4];
    #pragma unroll
    for (int kc = 0; kc < 4; kc++) {
        int r = wid * 16 + ((mat & 1) << 3) + lr8;
        int cch = kc * 2 + (mat >> 1);
        uint32_t off = (uint32_t)((r * 32 + ((cch ^ (r & 7)) << 2)) * 4);
        ldsm4(qh[kc], kh_u + off);
        ldsm4(ql[kc], kl_u + off);
    }
    __syncthreads();

    float o[8][4];
    #pragma unroll
    for (int i = 0; i < 8; i++)
        #pragma unroll
        for (int j = 0; j < 4; j++) o[i][j] = 0.f;
    float m0 = -1e30f, m1 = -1e30f, l0 = 0.f, l1 = 0.f;

    for (int kt0 = 0; kt0 < N_; kt0 += 64) {
        // ---- load K + V^T tiles (pre-split) --------------------------------
        uint2 rkh[8], rkl[8], rvh[8], rvl[8];
        #pragma unroll
        for (int i = 0; i < 8; i++) {
            int idx = tid + i * 128;
            int row = idx >> 4, c2 = (idx & 15) << 1, c4 = (idx & 15) << 2;
            size_t so = (size_t)(b * N_ + kt0 + row) * D2_ + h * 32 + c2;
            rkh[i] = *(const uint2*)&g_ksh[so];
            rkl[i] = *(const uint2*)&g_ksl[so];
            size_t vo = vtb + (size_t)row * N_ + kt0 + c4;
            rvh[i] = *(const uint2*)&g_vth[vo];
            rvl[i] = *(const uint2*)&g_vtl[vo];
        }
        __syncthreads();   // prior iteration's compute done
        #pragma unroll
        for (int i = 0; i < 8; i++) {
            int idx = tid + i * 128;
            int row = idx >> 4, c2 = (idx & 15) << 1;
            int u = row * 32 + (((c2 >> 2) ^ (row & 7)) << 2) + (c2 & 3);
            *(uint2*)&Kh[u] = rkh[i];
            *(uint2*)&Kl[u] = rkl[i];
            *(uint2*)&Vh[u] = rvh[i];
            *(uint2*)&Vl[u] = rvl[i];
        }
        __syncthreads();

        // ---- S = Q K^T (3xBF16), scale post-MMA ----------------------------
        float s[8][4];
        #pragma unroll
        for (int i = 0; i < 8; i++)
            #pragma unroll
            for (int j = 0; j < 4; j++) s[i][j] = 0.f;
        #pragma unroll
        for (int kc = 0; kc < 4; kc++) {
            uint32_t fbh[4][4], fbl[4][4];
            #pragma unroll
            for (int g = 0; g < 4; g++) {
                int r = g * 16 + ((mat >> 1) << 3) + lr8;
                int cch = kc * 2 + (mat & 1);
                uint32_t off = (uint32_t)((r * 32 + ((cch ^ (r & 7)) << 2)) * 4);
                ldsm4(fbh[g], kh_u + off);
                ldsm4(fbl[g], kl_u + off);
            }
            #pragma unroll
            for (int nt = 0; nt < 8; nt++) {
                uint32_t b0h = fbh[nt >> 1][(nt & 1) * 2], b1h = fbh[nt >> 1][(nt & 1) * 2 + 1];
                uint32_t b0l = fbl[nt >> 1][(nt & 1) * 2], b1l = fbl[nt >> 1][(nt & 1) * 2 + 1];
                mma16(s[nt], qh[kc], b0h, b1h);
                mma16(s[nt], ql[kc], b0h, b1h);
                mma16(s[nt], qh[kc], b0l, b1l);
            }
        }
        #pragma unroll
        for (int nt = 0; nt < 8; nt++) {
            s[nt][0] *= SC; s[nt][1] *= SC; s[nt][2] *= SC; s[nt][3] *= SC;
        }

        // ---- online softmax + P split store --------------------------------
        float mx0 = -1e30f, mx1 = -1e30f;
        #pragma unroll
        for (int nt = 0; nt < 8; nt++) {
            mx0 = fmaxf(mx0, fmaxf(s[nt][0], s[nt][1]));
            mx1 = fmaxf(mx1, fmaxf(s[nt][2], s[nt][3]));
        }
        mx0 = fmaxf(mx0, __shfl_xor_sync(0xffffffffu, mx0, 1));
        mx0 = fmaxf(mx0, __shfl_xor_sync(0xffffffffu, mx0, 2));
        mx1 = fmaxf(mx1, __shfl_xor_sync(0xffffffffu, mx1, 1));
        mx1 = fmaxf(mx1, __shfl_xor_sync(0xffffffffu, mx1, 2));
        float nm0 = fmaxf(m0, mx0), nm1 = fmaxf(m1, mx1);
        float f0 = fexp2(m0 - nm0), f1 = fexp2(m1 - nm1);
        m0 = nm0; m1 = nm1;
        float sum0 = 0.f, sum1 = 0.f;
        int wbase = wid * 512;
        int u0 = wbase + r0 * 32 + (l & 3);
        int u1 = wbase + (r0 + 8) * 32 + (l & 3);
        #pragma unroll
        for (int nt = 0; nt < 8; nt++) {
            float p0 = fexp2(s[nt][0] - m0);
            float p1 = fexp2(s[nt][1] - m0);
            float p2 = fexp2(s[nt][2] - m1);
            float p3 = fexp2(s[nt][3] - m1);
            sum0 += p0 + p1; sum1 += p2 + p3;
            float h0 = bf_hi(p0), h1 = bf_hi(p1), h2 = bf_hi(p2), h3 = bf_hi(p3);
            int sw0 = (nt ^ (r0 & 7)) << 2;
            Psh[u0 + sw0] = pack_bf(h0, h1);
            Psl[u0 + sw0] = pack_bf(p0 - h0, p1 - h1);
            Psh[u1 + sw0] = pack_bf(h2, h3);
            Psl[u1 + sw0] = pack_bf(p2 - h2, p3 - h3);
            o[nt][0] *= f0; o[nt][1] *= f0; o[nt][2] *= f1; o[nt][3] *= f1;
        }
        sum0 += __shfl_xor_sync(0xffffffffu, sum0, 1);
        sum0 += __shfl_xor_sync(0xffffffffu, sum0, 2);
        sum1 += __shfl_xor_sync(0xffffffffu, sum1, 1);
        sum1 += __shfl_xor_sync(0xffffffffu, sum1, 2);
        l0 = l0 * f0 + sum0;
        l1 = l1 * f1 + sum1;
        __syncwarp();

        // ---- O += P V (3xBF16) ---------------------------------------------
        #pragma unroll
        for (int kc = 0; kc < 4; kc++) {
            int rl = ((mat & 1) << 3) + lr8;
            int cch = kc * 2 + (mat >> 1);
            uint32_t poff = (uint32_t)((wbase + rl * 32 + ((cch ^ (rl & 7)) << 2)) * 4);
            uint32_t fph[4], fpl[4];
            ldsm4(fph, ph_u + poff);
            ldsm4(fpl, pl_u + poff);
            uint32_t fvh[4][4], fvl[4][4];
            #pragma unroll
            for (int g = 0; g < 4; g++) {
                int r = g * 16 + ((mat >> 1) << 3) + lr8;
                int cc2 = kc * 2 + (mat & 1);
                uint32_t off = (uint32_t)((r * 32 + ((cc2 ^ (r & 7)) << 2)) * 4);
                ldsm4(fvh[g], vh_u + off);
                ldsm4(fvl[g], vl_u + off);
            }
            #pragma unroll
            for (int nt = 0; nt < 8; nt++) {
                uint32_t b0h = fvh[nt >> 1][(nt & 1) * 2], b1h = fvh[nt >> 1][(nt & 1) * 2 + 1];
                uint32_t b0l = fvl[nt >> 1][(nt & 1) * 2], b1l = fvl[nt >> 1][(nt & 1) * 2 + 1];
                mma16(o[nt], fph, b0h, b1h);
                mma16(o[nt], fpl, b0h, b1h);
                mma16(o[nt], fph, b0l, b1l);
            }
        }
        __syncthreads();
    }

    // ---- finalize: write split ctx -----------------------------------------
    float inv0 = 1.0f / l0, inv1 = 1.0f / l1;
    int qa = q0 + wid * 16 + r0;
    #pragma unroll
    for (int nt = 0; nt < 8; nt++) {
        int d2 = (h * 64 + nt * 8 + cq) >> 1;
        float a0 = o[nt][0] * inv0, a1 = o[nt][1] * inv0;
        float h0 = bf_hi(a0), h1 = bf_hi(a1);
        g_ctxh[(size_t)(b * N_ + qa) * D2_ + d2] = pack_bf(h0, h1);
        g_ctxl[(size_t)(b * N_ + qa) * D2_ + d2] = pack_bf(a0 - h0, a1 - h1);
        float a2 = o[nt][2] * inv1, a3 = o[nt][3] * inv1;
        float h2 = bf_hi(a2), h3 = bf_hi(a3);
        g_ctxh[(size_t)(b * N_ + qa + 8) * D2_ + d2] = pack_bf(h2, h3);
        g_ctxl[(size_t)(b * N_ + qa + 8) * D2_ + d2] = pack_bf(a2 - h2, a3 - h3);
    }
}

// ---------------- LN2: read g_x f32, write split ----------------------------
__global__ void k_ln2(const float* __restrict__ g2, const float* __restrict__ b2) {
    int row  = blockIdx.x * 8 + (threadIdx.x >> 5);
    int lane = threadIdx.x & 31;
    const float* xr = g_x + (size_t)row * D_;
    float va[6], vb[6];
    float s = 0.f, ss = 0.f;
    #pragma unroll
    for (int j = 0; j < 6; j++) {
        float2 t = *(const float2*)&xr[(lane + j * 32) * 2];
        va[j] = t.x; vb[j] = t.y;
        s += t.x + t.y;
        ss = fmaf(t.x, t.x, ss); ss = fmaf(t.y, t.y, ss);
    }
    #pragma unroll
    for (int o = 16; o; o >>= 1) {
        s  += __shfl_xor_sync(0xffffffffu, s,  o);
        ss += __shfl_xor_sync(0xffffffffu, ss, o);
    }
    float mu   = s * (1.0f / D_);
    float var  = ss * (1.0f / D_) - mu * mu;
    float rstd = rsqrtf(var + 1e-5f);
    #pragma unroll
    for (int j = 0; j < 6; j++) {
        int d = (lane + j * 32) * 2;
        float2 gg = *(const float2*)&g2[d];
        float2 bb = *(const float2*)&b2[d];
        float ha = (va[j] - mu) * rstd * gg.x + bb.x;
        float hb = (vb[j] - mu) * rstd * gg.y + bb.y;
        float h0 = bf_hi(ha), h1 = bf_hi(hb);
        g_hh[(size_t)row * D2_ + lane + j * 32] = pack_bf(h0, h1);
        g_hl[(size_t)row * D2_ + lane + j * 32] = pack_bf(ha - h0, hb - h1);
    }
}

// ---------------- launch ----------------------------------------------------
extern "C" void kernel_launch(void* const* d_in, const int* in_sizes, int n_in,
                              void* d_out, int out_size) {
    const float* pts   = (const float*)d_in[0];
    const float* ln1_g = (const float*)d_in[1];
    const float* ln1_b = (const float*)d_in[2];
    const float* w_qkv = (const float*)d_in[3];
    const float* w_o   = (const float*)d_in[4];
    const float* b_o   = (const float*)d_in[5];
    const float* ln2_g = (const float*)d_in[6];
    const float* ln2_b = (const float*)d_in[7];
    const float* w1    = (const float*)d_in[8];
    const float* b1    = (const float*)d_in[9];
    const float* w2    = (const float*)d_in[10];
    const float* b2    = (const float*)d_in[11];
    float* out = (float*)d_out;

    cudaFuncSetAttribute(k_gemm_mma<D_, 0>,  cudaFuncAttributeMaxDynamicSharedMemorySize, GEMM_SMEM);
    cudaFuncSetAttribute(k_gemm_mma<D_, 1>,  cudaFuncAttributeMaxDynamicSharedMemorySize, GEMM_SMEM);
    cudaFuncSetAttribute(k_gemm_mma<D_, 2>,  cudaFuncAttributeMaxDynamicSharedMemorySize, GEMM_SMEM);
    cudaFuncSetAttribute(k_gemm_mma<FF_, 3>, cudaFuncAttributeMaxDynamicSharedMemorySize, GEMM_SMEM);
    cudaFuncSetAttribute(k_attn_mma,         cudaFuncAttributeMaxDynamicSharedMemorySize, ATT_SMEM);

    k_split_all<<<(SPLIT_TOT + 255) / 256, 256>>>(w_qkv, w_o, w1, w2);
    k_pre_ln<<<512, 256>>>(pts, ln1_g, ln1_b, out);
    k_gemm_mma<D_, 0><<<dim3(E3_ / 128, BN_ / 128), 256, GEMM_SMEM>>>(nullptr, nullptr);
    k_attn_mma<<<dim3(N_ / 64, B_ * H_), 128, ATT_SMEM>>>();
    k_gemm_mma<D_, 1><<<dim3(D_ / 128, BN_ / 128), 256, GEMM_SMEM>>>(b_o, nullptr);
    k_ln2<<<BN_ / 8, 256>>>(ln2_g, ln2_b);
    k_gemm_mma<D_, 2><<<dim3(FF_ / 128, BN_ / 128), 256, GEMM_SMEM>>>(b1, nullptr);
    k_gemm_mma<FF_, 3><<<dim3(D_ / 128, BN_ / 128), 256, GEMM_SMEM>>>(b2, out);
}

// round 13
// speedup vs baseline: 1.2190x; 1.0657x over previous
#include <cuda_runtime.h>
#include <cuda_bf16.h>
#include <math.h>
#include <cstdint>

#define DEV_INLINE __device__ __forceinline__

constexpr int B_  = 8;
constexpr int N_  = 2048;
constexpr int D_  = 384;
constexpr int H_  = 6;
constexpr int DK_ = 64;
constexpr int BN_ = B_ * N_;       // 16384
constexpr int E3_ = 3 * D_;        // 1152
constexpr int FF_ = 2 * D_;        // 768
constexpr int CH_ = 3 + D_;        // 387
constexpr int D2_ = D_ / 2;        // 192 u32 per row

// ---------------- scratch (device globals) ----------------------------------
__device__ float    g_feats[BN_ * D_];
__device__ float    g_x[BN_ * D_];
__device__ uint32_t g_hh[BN_ * D2_],   g_hl[BN_ * D2_];       // LN out split
__device__ uint32_t g_qh[BN_ * D2_],   g_ql[BN_ * D2_];       // Q split
__device__ __align__(16) uint32_t g_ksh[BN_ * D2_];           // K split (16B for cp.async)
__device__ __align__(16) uint32_t g_ksl[BN_ * D2_];
__device__ __align__(16) uint16_t g_vth[(size_t)B_ * H_ * DK_ * N_];  // V^T hi [bh][dk][n]
__device__ __align__(16) uint16_t g_vtl[(size_t)B_ * H_ * DK_ * N_];  // V^T lo
__device__ uint32_t g_ctxh[BN_ * D2_], g_ctxl[BN_ * D2_];     // attn ctx split
__device__ uint32_t g_ffh[BN_ * FF_ / 2], g_ffl[BN_ * FF_ / 2];
__device__ uint32_t g_wqh[E3_ * D2_],  g_wql[E3_ * D2_];
__device__ uint32_t g_woh[D_ * D2_],   g_wol[D_ * D2_];
__device__ uint32_t g_w1h[FF_ * D2_],  g_w1l[FF_ * D2_];
__device__ uint32_t g_w2h[D_ * FF_/2], g_w2l[D_ * FF_/2];

// ---------------- PTX helpers (sm_80-level only: target-safe) ---------------
DEV_INLINE uint32_t smem_u32(const void* p) {
    uint32_t a;
    asm("{ .reg .u64 t; cvta.to.shared.u64 t, %1; cvt.u32.u64 %0, t; }" : "=r"(a) : "l"(p));
    return a;
}
DEV_INLINE void ldsm4(uint32_t* r, uint32_t addr) {
    asm volatile("ldmatrix.sync.aligned.m8n8.x4.shared.b16 {%0,%1,%2,%3}, [%4];"
        : "=r"(r[0]), "=r"(r[1]), "=r"(r[2]), "=r"(r[3]) : "r"(addr));
}
DEV_INLINE void mma16(float* c, const uint32_t* a, uint32_t b0, uint32_t b1) {
    asm volatile("mma.sync.aligned.m16n8k16.row.col.f32.bf16.bf16.f32 "
        "{%0,%1,%2,%3}, {%4,%5,%6,%7}, {%8,%9}, {%0,%1,%2,%3};"
        : "+f"(c[0]), "+f"(c[1]), "+f"(c[2]), "+f"(c[3])
        : "r"(a[0]), "r"(a[1]), "r"(a[2]), "r"(a[3]), "r"(b0), "r"(b1));
}
DEV_INLINE void cp16(uint32_t saddr, const void* gptr) {
    asm volatile("cp.async.ca.shared.global [%0], [%1], 16;" :: "r"(saddr), "l"(gptr));
}
#define CP_COMMIT() asm volatile("cp.async.commit_group;" ::: "memory")
#define CP_WAIT0()  asm volatile("cp.async.wait_group 0;" ::: "memory")
#define CP_WAIT1()  asm volatile("cp.async.wait_group 1;" ::: "memory")

DEV_INLINE float bf_hi(float x) { return __bfloat162float(__float2bfloat16_rn(x)); }
DEV_INLINE uint32_t pack_bf(float a, float b) {
    __nv_bfloat162 t = __floats2bfloat162_rn(a, b);
    return *reinterpret_cast<uint32_t*>(&t);
}
DEV_INLINE uint16_t bf_bits(float x) {
    __nv_bfloat16 t = __float2bfloat16_rn(x);
    return *reinterpret_cast<uint16_t*>(&t);
}

// ---------------- fast exp2 (FMA pipe) --------------------------------------
DEV_INLINE float fexp2(float x) {
    x = fmaxf(x, -125.0f);
    float r = rintf(x);
    float f = x - r;
    float p = 1.535336188319500e-4f;
    p = fmaf(p, f, 1.339887440266574e-3f);
    p = fmaf(p, f, 9.618437357674640e-3f);
    p = fmaf(p, f, 5.550332471162809e-2f);
    p = fmaf(p, f, 2.402264791363012e-1f);
    p = fmaf(p, f, 6.931472028550421e-1f);
    p = fmaf(p, f, 1.0f);
    return __int_as_float(((int)r + 127) << 23) * p;
}

// ---------------- weight split (single launch, range-dispatched) ------------
// Destinations bound in device code (host-side __device__ symbol args give the
// ATS-dereferenceable host shadow — the R7/R9 silent-zero bug).
__global__ void k_split_all(const float* __restrict__ wq, const float* __restrict__ wo,
                            const float* __restrict__ w1, const float* __restrict__ w2) {
    constexpr int n0 = E3_ * D2_;
    constexpr int n1 = n0 + D_ * D2_;
    constexpr int n2 = n1 + FF_ * D2_;
    constexpr int n3 = n2 + D_ * FF_ / 2;
    int i = blockIdx.x * 256 + threadIdx.x;
    const float* src; uint32_t* dh; uint32_t* dl; int off;
    if (i < n0)      { src = wq; dh = g_wqh; dl = g_wql; off = i; }
    else if (i < n1) { src = wo; dh = g_woh; dl = g_wol; off = i - n0; }
    else if (i < n2) { src = w1; dh = g_w1h; dl = g_w1l; off = i - n1; }
    else if (i < n3) { src = w2; dh = g_w2h; dl = g_w2l; off = i - n2; }
    else return;
    float2 v = *(const float2*)&src[(size_t)off * 2];
    float h0 = bf_hi(v.x), h1 = bf_hi(v.y);
    dh[off] = pack_bf(h0, h1);
    dl[off] = pack_bf(v.x - h0, v.y - h1);
}
constexpr int SPLIT_TOT = E3_ * D2_ + D_ * D2_ + FF_ * D2_ + D_ * FF_ / 2;

// ---------------- kernel 1: transpose + LN1 + coords ------------------------
__global__ void k_pre_ln(const float* __restrict__ pts,
                         const float* __restrict__ g1,
                         const float* __restrict__ b1,
                         float* __restrict__ out) {
    __shared__ float S[32][D_];
    int b  = blockIdx.x >> 6;
    int n0 = (blockIdx.x & 63) << 5;
    const float* base = pts + (size_t)b * CH_ * N_;
    int tid = threadIdx.x;

    for (int idx = tid; idx < 32 * D_; idx += 256) {
        int nl = idx & 31, d = idx >> 5;
        S[nl][d] = base[(size_t)(3 + d) * N_ + n0 + nl];
    }
    for (int idx = tid; idx < 96; idx += 256) {
        int nl = idx & 31, c = idx >> 5;
        out[(size_t)b * CH_ * N_ + (size_t)c * N_ + n0 + nl] = base[(size_t)c * N_ + n0 + nl];
    }
    __syncthreads();

    int w = tid >> 5, lane = tid & 31;
    #pragma unroll
    for (int i = 0; i < 4; i++) {
        int nl = w * 4 + i;
        float va[6], vb[6];
        float s = 0.f, ss = 0.f;
        #pragma unroll
        for (int j = 0; j < 6; j++) {
            int d = (lane + j * 32) * 2;
            va[j] = S[nl][d]; vb[j] = S[nl][d + 1];
            s += va[j] + vb[j];
            ss = fmaf(va[j], va[j], ss); ss = fmaf(vb[j], vb[j], ss);
        }
        #pragma unroll
        for (int o = 16; o; o >>= 1) {
            s  += __shfl_xor_sync(0xffffffffu, s,  o);
            ss += __shfl_xor_sync(0xffffffffu, ss, o);
        }
        float mu   = s * (1.0f / D_);
        float var  = ss * (1.0f / D_) - mu * mu;
        float rstd = rsqrtf(var + 1e-5f);
        size_t row = (size_t)b * N_ + n0 + nl;
        #pragma unroll
        for (int j = 0; j < 6; j++) {
            int d = (lane + j * 32) * 2;
            *(float2*)&g_feats[row * D_ + d] = make_float2(va[j], vb[j]);
            float2 gg = *(const float2*)&g1[d];
            float2 bb = *(const float2*)&b1[d];
            float ha = (va[j] - mu) * rstd * gg.x + bb.x;
            float hb = (vb[j] - mu) * rstd * gg.y + bb.y;
            float h0 = bf_hi(ha), h1 = bf_hi(hb);
            g_hh[row * D2_ + lane + j * 32] = pack_bf(h0, h1);
            g_hl[row * D2_ + lane + j * 32] = pack_bf(ha - h0, hb - h1);
        }
    }
}

// ---------------- bf16x3 GEMM, pre-split operands, double-buffered ----------
// C[m,e] = sum_k A[m,k] W[e,k]; tile 128x128, BK=32, 256 thr (8 warps m32n64)
constexpr int GEMM_SMEM = 2 * 4 * 2048 * 4;   // 65536 B

template <int KD, int EPI>
__global__ __launch_bounds__(256, 2) void k_gemm_mma(const float* __restrict__ bias,
                                                     float* __restrict__ out) {
    extern __shared__ uint32_t smu[];
    const uint32_t sb = smem_u32(smu);
    constexpr int KD2 = KD / 2;

    const uint32_t *Ahg, *Alg, *Bhg, *Blg;
    if constexpr (EPI == 0)      { Ahg = g_hh;   Alg = g_hl;   Bhg = g_wqh; Blg = g_wql; }
    else if constexpr (EPI == 1) { Ahg = g_ctxh; Alg = g_ctxl; Bhg = g_woh; Blg = g_wol; }
    else if constexpr (EPI == 2) { Ahg = g_hh;   Alg = g_hl;   Bhg = g_w1h; Blg = g_w1l; }
    else                         { Ahg = g_ffh;  Alg = g_ffl;  Bhg = g_w2h; Blg = g_w2l; }

    int m0 = blockIdx.y * 128;
    int e0 = blockIdx.x * 128;
    int tid = threadIdx.x;
    int wid = tid >> 5, l = tid & 31;
    int mq = wid & 3, nh = wid >> 2;
    int lr8 = l & 7, mat = l >> 3;

    float c[2][8][4];
    #pragma unroll
    for (int i = 0; i < 2; i++)
        #pragma unroll
        for (int j = 0; j < 8; j++)
            #pragma unroll
            for (int k = 0; k < 4; k++) c[i][j][k] = 0.f;

    constexpr int KT = KD / 32;

    uint2 pah[4], pal[4], pbh[4], pbl[4];
    #pragma unroll
    for (int i = 0; i < 4; i++) {
        int idx = tid + i * 256;
        int row = idx >> 3, c2 = (idx & 7) << 1;
        size_t ao = (size_t)(m0 + row) * KD2 + c2;
        size_t bo = (size_t)(e0 + row) * KD2 + c2;
        pah[i] = *(const uint2*)&Ahg[ao];
        pal[i] = *(const uint2*)&Alg[ao];
        pbh[i] = *(const uint2*)&Bhg[bo];
        pbl[i] = *(const uint2*)&Blg[bo];
    }

    for (int kt = 0; kt < KT; kt++) {
        uint32_t* Ah = smu + (kt & 1) * 8192;
        uint32_t* Al = Ah + 2048;
        uint32_t* Bh = Ah + 4096;
        uint32_t* Bl = Ah + 6144;
        #pragma unroll
        for (int i = 0; i < 4; i++) {
            int idx = tid + i * 256;
            int row = idx >> 3, c2 = (idx & 7) << 1;
            int u = row * 16 + (((c2 >> 2) ^ ((row >> 1) & 3)) << 2) + (c2 & 3);
            *(uint2*)&Ah[u] = pah[i];
            *(uint2*)&Al[u] = pal[i];
            *(uint2*)&Bh[u] = pbh[i];
            *(uint2*)&Bl[u] = pbl[i];
        }
        if (kt + 1 < KT) {
            int k2 = (kt + 1) * 16;
            #pragma unroll
            for (int i = 0; i < 4; i++) {
                int idx = tid + i * 256;
                int row = idx >> 3, c2 = (idx & 7) << 1;
                size_t ao = (size_t)(m0 + row) * KD2 + k2 + c2;
                size_t bo = (size_t)(e0 + row) * KD2 + k2 + c2;
                pah[i] = *(const uint2*)&Ahg[ao];
                pal[i] = *(const uint2*)&Alg[ao];
                pbh[i] = *(const uint2*)&Bhg[bo];
                pbl[i] = *(const uint2*)&Blg[bo];
            }
        }
        __syncthreads();

        uint32_t stg = sb + (uint32_t)(kt & 1) * 32768u;
        uint32_t ah_u = stg, al_u = stg + 8192, bh_u = stg + 16384, bl_u = stg + 24576;
        #pragma unroll
        for (int kc = 0; kc < 2; kc++) {
            uint32_t fah[2][4], fal[2][4];
            #pragma unroll
            for (int mt = 0; mt < 2; mt++) {
                int r = mq * 32 + mt * 16 + ((mat & 1) << 3) + lr8;
                int cch = kc * 2 + (mat >> 1);
                uint32_t off = (uint32_t)((r * 16 + ((cch ^ ((r >> 1) & 3)) << 2)) * 4);
                ldsm4(fah[mt], ah_u + off);
                ldsm4(fal[mt], al_u + off);
            }
            uint32_t fbh[4][4], fbl[4][4];
            #pragma unroll
            for (int g = 0; g < 4; g++) {
                int r = nh * 64 + g * 16 + ((mat >> 1) << 3) + lr8;
                int cch = kc * 2 + (mat & 1);
                uint32_t off = (uint32_t)((r * 16 + ((cch ^ ((r >> 1) & 3)) << 2)) * 4);
                ldsm4(fbh[g], bh_u + off);
                ldsm4(fbl[g], bl_u + off);
            }
            #pragma unroll
            for (int mt = 0; mt < 2; mt++)
                #pragma unroll
                for (int nt = 0; nt < 8; nt++) {
                    uint32_t b0h = fbh[nt >> 1][(nt & 1) * 2], b1h = fbh[nt >> 1][(nt & 1) * 2 + 1];
                    uint32_t b0l = fbl[nt >> 1][(nt & 1) * 2], b1l = fbl[nt >> 1][(nt & 1) * 2 + 1];
                    mma16(c[mt][nt], fah[mt], b0h, b1h);
                    mma16(c[mt][nt], fal[mt], b0h, b1h);
                    mma16(c[mt][nt], fah[mt], b0l, b1l);
                }
        }
    }

    // epilogue
    int r0 = l >> 2, cq = (l & 3) * 2;
    #pragma unroll
    for (int mt = 0; mt < 2; mt++) {
        #pragma unroll
        for (int mi = 0; mi < 2; mi++) {
            int m  = m0 + mq * 32 + mt * 16 + r0 + mi * 8;
            int bb = m >> 11;
            int n  = m & 2047;
            #pragma unroll
            for (int nt = 0; nt < 8; nt++) {
                int e = e0 + nh * 64 + nt * 8 + cq;
                float v0 = c[mt][nt][mi * 2 + 0];
                float v1 = c[mt][nt][mi * 2 + 1];
                if (EPI == 0) {
                    if (e < 2 * D_) {
                        float h0 = bf_hi(v0), h1 = bf_hi(v1);
                        uint32_t ph = pack_bf(h0, h1);
                        uint32_t pl = pack_bf(v0 - h0, v1 - h1);
                        if (e < D_) {
                            g_qh[(size_t)m * D2_ + (e >> 1)] = ph;
                            g_ql[(size_t)m * D2_ + (e >> 1)] = pl;
                        } else {
                            g_ksh[(size_t)m * D2_ + ((e - D_) >> 1)] = ph;
                            g_ksl[(size_t)m * D2_ + ((e - D_) >> 1)] = pl;
                        }
                    } else {
                        int eh = e - 2 * D_;
                        int hh = eh >> 6, dk = eh & 63;
                        size_t base = ((size_t)(bb * H_ + hh) * DK_ + dk) * N_ + n;
                        float h0 = bf_hi(v0);
                        g_vth[base] = bf_bits(v0);
                        g_vtl[base] = bf_bits(v0 - h0);
                        float h1 = bf_hi(v1);
                        g_vth[base + N_] = bf_bits(v1);
                        g_vtl[base + N_] = bf_bits(v1 - h1);
                    }
                } else if (EPI == 1) {
                    size_t idx = (size_t)m * D_ + e;
                    float2 f  = *(const float2*)&g_feats[idx];
                    float2 bv = *(const float2*)&bias[e];
                    *(float2*)&g_x[idx] = make_float2(v0 + bv.x + f.x, v1 + bv.y + f.y);
                } else if (EPI == 2) {
                    float2 bv = *(const float2*)&bias[e];
                    float t0 = v0 + bv.x, t1 = v1 + bv.y;
                    float u0 = 0.5f * t0 * (1.0f + erff(t0 * 0.70710678118f));
                    float u1 = 0.5f * t1 * (1.0f + erff(t1 * 0.70710678118f));
                    float h0 = bf_hi(u0), h1 = bf_hi(u1);
                    g_ffh[(size_t)m * (FF_/2) + (e >> 1)] = pack_bf(h0, h1);
                    g_ffl[(size_t)m * (FF_/2) + (e >> 1)] = pack_bf(u0 - h0, u1 - h1);
                } else {
                    size_t idx = (size_t)m * D_ + e;
                    float2 xv = *(const float2*)&g_x[idx];
                    float2 bv = *(const float2*)&bias[e];
                    size_t ob = (size_t)bb * CH_ * N_;
                    out[ob + (size_t)(3 + e)     * N_ + n] = v0 + bv.x + xv.x;
                    out[ob + (size_t)(3 + e + 1) * N_ + n] = v1 + bv.y + xv.y;
                }
            }
        }
    }
}

// ---------------- flash attention: cp.async double-buffer, Ps aliased -------
// grid (N/64, B*H), 128 thr (4 warps); warp = 16 query rows.
// smem u32 map (stage s in {0,1}):
//   Kh[s] = s*4096,  Kl[s] = s*4096 + 2048
//   Vh[s] = 8192 + s*4096,  Vl[s] = 8192 + s*4096 + 2048
// Ps aliases the CURRENT K stage (K fully consumed by QK before P stores).
constexpr int ATT_SMEM = 16384 * 4;   // 64 KB

__global__ __launch_bounds__(128, 3) void k_attn_mma() {
    extern __shared__ uint32_t smu[];
    const uint32_t sb = smem_u32(smu);

    int bh = blockIdx.y;
    int b  = bh / H_, h = bh - b * H_;
    int q0 = blockIdx.x * 64;
    int tid = threadIdx.x;
    int wid = tid >> 5, l = tid & 31;
    int lr8 = l & 7, mat = l >> 3;
    int r0 = l >> 2, cq = (l & 3) * 2;

    const float SC = 0.125f * 1.44269504f;
    const size_t vtb = (size_t)(b * H_ + h) * DK_ * N_;

    auto load_tile = [&](int kt0, int s) {
        uint32_t kb = sb + (uint32_t)s * 16384u;
        uint32_t vb = sb + 32768u + (uint32_t)s * 16384u;
        #pragma unroll
        for (int t = 0; t < 4; t++) {
            int idx = tid + t * 128;          // 0..511
            int row = idx >> 3, ch = idx & 7;
            uint32_t du = (uint32_t)((row * 32 + ((ch ^ (row & 7)) << 2)) * 4);
            size_t so = (size_t)(b * N_ + kt0 + row) * D2_ + h * 32 + ch * 4;
            cp16(kb + du,        g_ksh + so);
            cp16(kb + 8192 + du, g_ksl + so);
            size_t vo = vtb + (size_t)row * N_ + kt0 + ch * 8;
            cp16(vb + du,        g_vth + vo);
            cp16(vb + 8192 + du, g_vtl + vo);
        }
    };

    // ---- prologue: tile 0 async; Q staged via stage-1 K region -------------
    load_tile(0, 0);
    CP_COMMIT();
    {
        uint32_t* Qh = smu + 4096;
        uint32_t* Ql = smu + 6144;
        #pragma unroll
        for (int i = 0; i < 8; i++) {
            int idx = tid + i * 128;
            int row = idx >> 4, c2 = (idx & 15) << 1;
            int u = row * 32 + (((c2 >> 2) ^ (row & 7)) << 2) + (c2 & 3);
            size_t so = (size_t)(b * N_ + q0 + row) * D2_ + h * 32 + c2;
            *(uint2*)&Qh[u] = *(const uint2*)&g_qh[so];
            *(uint2*)&Ql[u] = *(const uint2*)&g_ql[so];
        }
    }
    __syncthreads();
    uint32_t qh[4][4], ql[4][4];
    #pragma unroll
    for (int kc = 0; kc < 4; kc++) {
        int r = wid * 16 + ((mat & 1) << 3) + lr8;
        int cch = kc * 2 + (mat >> 1);
        uint32_t off = (uint32_t)((r * 32 + ((cch ^ (r & 7)) << 2)) * 4);
        ldsm4(qh[kc], sb + 16384u + off);
        ldsm4(ql[kc], sb + 24576u + off);
    }
    __syncthreads();   // stage-1 K region now free for tile-1 cp.async

    float o[8][4];
    #pragma unroll
    for (int i = 0; i < 8; i++)
        #pragma unroll
        for (int j = 0; j < 4; j++) o[i][j] = 0.f;
    float m0 = -1e30f, m1 = -1e30f, l0 = 0.f, l1 = 0.f;

    constexpr int NT = N_ / 64;   // 32 tiles
    for (int it = 0; it < NT; it++) {
        int p = it & 1;
        // prefetch next tile into the other stage (its last readers finished
        // at the previous iteration's tail barrier)
        if (it + 1 < NT) { load_tile((it + 1) * 64, p ^ 1); CP_COMMIT(); CP_WAIT1(); }
        else             { CP_WAIT0(); }
        __syncthreads();   // tile 'it' visible to all threads

        uint32_t khs = sb + (uint32_t)p * 16384u;
        uint32_t kls = khs + 8192u;

        // ---- S = Q K^T (3xBF16) --------------------------------------------
        float s[8][4];
        #pragma unroll
        for (int i = 0; i < 8; i++)
            #pragma unroll
            for (int j = 0; j < 4; j++) s[i][j] = 0.f;
        #pragma unroll
        for (int kc = 0; kc < 4; kc++) {
            uint32_t fbh[4][4], fbl[4][4];
            #pragma unroll
            for (int g = 0; g < 4; g++) {
                int r = g * 16 + ((mat >> 1) << 3) + lr8;
                int cch = kc * 2 + (mat & 1);
                uint32_t off = (uint32_t)((r * 32 + ((cch ^ (r & 7)) << 2)) * 4);
                ldsm4(fbh[g], khs + off);
                ldsm4(fbl[g], kls + off);
            }
            #pragma unroll
            for (int nt = 0; nt < 8; nt++) {
                uint32_t b0h = fbh[nt >> 1][(nt & 1) * 2], b1h = fbh[nt >> 1][(nt & 1) * 2 + 1];
                uint32_t b0l = fbl[nt >> 1][(nt & 1) * 2], b1l = fbl[nt >> 1][(nt & 1) * 2 + 1];
                mma16(s[nt], qh[kc], b0h, b1h);
                mma16(s[nt], ql[kc], b0h, b1h);
                mma16(s[nt], qh[kc], b0l, b1l);
            }
        }
        __syncthreads();   // all warps done reading K stage p -> reuse as Ps

        #pragma unroll
        for (int nt = 0; nt < 8; nt++) {
            s[nt][0] *= SC; s[nt][1] *= SC; s[nt][2] *= SC; s[nt][3] *= SC;
        }

        // ---- online softmax + P split store (into K stage p region) --------
        float mx0 = -1e30f, mx1 = -1e30f;
        #pragma unroll
        for (int nt = 0; nt < 8; nt++) {
            mx0 = fmaxf(mx0, fmaxf(s[nt][0], s[nt][1]));
            mx1 = fmaxf(mx1, fmaxf(s[nt][2], s[nt][3]));
        }
        mx0 = fmaxf(mx0, __shfl_xor_sync(0xffffffffu, mx0, 1));
        mx0 = fmaxf(mx0, __shfl_xor_sync(0xffffffffu, mx0, 2));
        mx1 = fmaxf(mx1, __shfl_xor_sync(0xffffffffu, mx1, 1));
        mx1 = fmaxf(mx1, __shfl_xor_sync(0xffffffffu, mx1, 2));
        float nm0 = fmaxf(m0, mx0), nm1 = fmaxf(m1, mx1);
        float f0 = fexp2(m0 - nm0), f1 = fexp2(m1 - nm1);
        m0 = nm0; m1 = nm1;
        float sum0 = 0.f, sum1 = 0.f;
        uint32_t* Psh = smu + p * 4096;
        uint32_t* Psl = Psh + 2048;
        int wbase = wid * 512;
        int u0 = wbase + r0 * 32 + (l & 3);
        int u1 = wbase + (r0 + 8) * 32 + (l & 3);
        #pragma unroll
        for (int nt = 0; nt < 8; nt++) {
            float p0 = fexp2(s[nt][0] - m0);
            float p1 = fexp2(s[nt][1] - m0);
            float p2 = fexp2(s[nt][2] - m1);
            float p3 = fexp2(s[nt][3] - m1);
            sum0 += p0 + p1; sum1 += p2 + p3;
            float h0 = bf_hi(p0), h1 = bf_hi(p1), h2 = bf_hi(p2), h3 = bf_hi(p3);
            int sw0 = (nt ^ (r0 & 7)) << 2;
            Psh[u0 + sw0] = pack_bf(h0, h1);
            Psl[u0 + sw0] = pack_bf(p0 - h0, p1 - h1);
            Psh[u1 + sw0] = pack_bf(h2, h3);
            Psl[u1 + sw0] = pack_bf(p2 - h2, p3 - h3);
            o[nt][0] *= f0; o[nt][1] *= f0; o[nt][2] *= f1; o[nt][3] *= f1;
        }
        sum0 += __shfl_xor_sync(0xffffffffu, sum0, 1);
        sum0 += __shfl_xor_sync(0xffffffffu, sum0, 2);
        sum1 += __shfl_xor_sync(0xffffffffu, sum1, 1);
        sum1 += __shfl_xor_sync(0xffffffffu, sum1, 2);
        l0 = l0 * f0 + sum0;
        l1 = l1 * f1 + sum1;
        __syncwarp();      // each warp reads only its own 16 Ps rows

        // ---- O += P V (3xBF16) ---------------------------------------------
        uint32_t vhs = sb + 32768u + (uint32_t)p * 16384u;
        uint32_t vls = vhs + 8192u;
        #pragma unroll
        for (int kc = 0; kc < 4; kc++) {
            int rl = ((mat & 1) << 3) + lr8;
            int cch = kc * 2 + (mat >> 1);
            uint32_t poff = (uint32_t)((wbase + rl * 32 + ((cch ^ (rl & 7)) << 2)) * 4);
            uint32_t fph[4], fpl[4];
            ldsm4(fph, khs + poff);
            ldsm4(fpl, kls + poff);
            uint32_t fvh[4][4], fvl[4][4];
            #pragma unroll
            for (int g = 0; g < 4; g++) {
                int r = g * 16 + ((mat >> 1) << 3) + lr8;
                int cc2 = kc * 2 + (mat & 1);
                uint32_t off = (uint32_t)((r * 32 + ((cc2 ^ (r & 7)) << 2)) * 4);
                ldsm4(fvh[g], vhs + off);
                ldsm4(fvl[g], vls + off);
            }
            #pragma unroll
            for (int nt = 0; nt < 8; nt++) {
                uint32_t b0h = fvh[nt >> 1][(nt & 1) * 2], b1h = fvh[nt >> 1][(nt & 1) * 2 + 1];
                uint32_t b0l = fvl[nt >> 1][(nt & 1) * 2], b1l = fvl[nt >> 1][(nt & 1) * 2 + 1];
                mma16(o[nt], fph, b0h, b1h);
                mma16(o[nt], fpl, b0h, b1h);
                mma16(o[nt], fph, b0l, b1l);
            }
        }
        __syncthreads();   // tail: stage p^1 free for next iteration's cp.async
    }

    // ---- finalize: write split ctx -----------------------------------------
    float inv0 = 1.0f / l0, inv1 = 1.0f / l1;
    int qa = q0 + wid * 16 + r0;
    #pragma unroll
    for (int nt = 0; nt < 8; nt++) {
        int d2 = (h * 64 + nt * 8 + cq) >> 1;
        float a0 = o[nt][0] * inv0, a1 = o[nt][1] * inv0;
        float h0 = bf_hi(a0), h1 = bf_hi(a1);
        g_ctxh[(size_t)(b * N_ + qa) * D2_ + d2] = pack_bf(h0, h1);
        g_ctxl[(size_t)(b * N_ + qa) * D2_ + d2] = pack_bf(a0 - h0, a1 - h1);
        float a2 = o[nt][2] * inv1, a3 = o[nt][3] * inv1;
        float h2 = bf_hi(a2), h3 = bf_hi(a3);
        g_ctxh[(size_t)(b * N_ + qa + 8) * D2_ + d2] = pack_bf(h2, h3);
        g_ctxl[(size_t)(b * N_ + qa + 8) * D2_ + d2] = pack_bf(a2 - h2, a3 - h3);
    }
}

// ---------------- LN2: read g_x f32, write split ----------------------------
__global__ void k_ln2(const float* __restrict__ g2, const float* __restrict__ b2) {
    int row  = blockIdx.x * 8 + (threadIdx.x >> 5);
    int lane = threadIdx.x & 31;
    const float* xr = g_x + (size_t)row * D_;
    float va[6], vb[6];
    float s = 0.f, ss = 0.f;
    #pragma unroll
    for (int j = 0; j < 6; j++) {
        float2 t = *(const float2*)&xr[(lane + j * 32) * 2];
        va[j] = t.x; vb[j] = t.y;
        s += t.x + t.y;
        ss = fmaf(t.x, t.x, ss); ss = fmaf(t.y, t.y, ss);
    }
    #pragma unroll
    for (int o = 16; o; o >>= 1) {
        s  += __shfl_xor_sync(0xffffffffu, s,  o);
        ss += __shfl_xor_sync(0xffffffffu, ss, o);
    }
    float mu   = s * (1.0f / D_);
    float var  = ss * (1.0f / D_) - mu * mu;
    float rstd = rsqrtf(var + 1e-5f);
    #pragma unroll
    for (int j = 0; j < 6; j++) {
        int d = (lane + j * 32) * 2;
        float2 gg = *(const float2*)&g2[d];
        float2 bb = *(const float2*)&b2[d];
        float ha = (va[j] - mu) * rstd * gg.x + bb.x;
        float hb = (vb[j] - mu) * rstd * gg.y + bb.y;
        float h0 = bf_hi(ha), h1 = bf_hi(hb);
        g_hh[(size_t)row * D2_ + lane + j * 32] = pack_bf(h0, h1);
        g_hl[(size_t)row * D2_ + lane + j * 32] = pack_bf(ha - h0, hb - h1);
    }
}

// ---------------- launch ----------------------------------------------------
extern "C" void kernel_launch(void* const* d_in, const int* in_sizes, int n_in,
                              void* d_out, int out_size) {
    const float* pts   = (const float*)d_in[0];
    const float* ln1_g = (const float*)d_in[1];
    const float* ln1_b = (const float*)d_in[2];
    const float* w_qkv = (const float*)d_in[3];
    const float* w_o   = (const float*)d_in[4];
    const float* b_o   = (const float*)d_in[5];
    const float* ln2_g = (const float*)d_in[6];
    const float* ln2_b = (const float*)d_in[7];
    const float* w1    = (const float*)d_in[8];
    const float* b1    = (const float*)d_in[9];
    const float* w2    = (const float*)d_in[10];
    const float* b2    = (const float*)d_in[11];
    float* out = (float*)d_out;

    cudaFuncSetAttribute(k_gemm_mma<D_, 0>,  cudaFuncAttributeMaxDynamicSharedMemorySize, GEMM_SMEM);
    cudaFuncSetAttribute(k_gemm_mma<D_, 1>,  cudaFuncAttributeMaxDynamicSharedMemorySize, GEMM_SMEM);
    cudaFuncSetAttribute(k_gemm_mma<D_, 2>,  cudaFuncAttributeMaxDynamicSharedMemorySize, GEMM_SMEM);
    cudaFuncSetAttribute(k_gemm_mma<FF_, 3>, cudaFuncAttributeMaxDynamicSharedMemorySize, GEMM_SMEM);
    cudaFuncSetAttribute(k_attn_mma,         cudaFuncAttributeMaxDynamicSharedMemorySize, ATT_SMEM);

    k_split_all<<<(SPLIT_TOT + 255) / 256, 256>>>(w_qkv, w_o, w1, w2);
    k_pre_ln<<<512, 256>>>(pts, ln1_g, ln1_b, out);
    k_gemm_mma<D_, 0><<<dim3(E3_ / 128, BN_ / 128), 256, GEMM_SMEM>>>(nullptr, nullptr);
    k_attn_mma<<<dim3(N_ / 64, B_ * H_), 128, ATT_SMEM>>>();
    k_gemm_mma<D_, 1><<<dim3(D_ / 128, BN_ / 128), 256, GEMM_SMEM>>>(b_o, nullptr);
    k_ln2<<<BN_ / 8, 256>>>(ln2_g, ln2_b);
    k_gemm_mma<D_, 2><<<dim3(FF_ / 128, BN_ / 128), 256, GEMM_SMEM>>>(b1, nullptr);
    k_gemm_mma<FF_, 3><<<dim3(D_ / 128, BN_ / 128), 256, GEMM_SMEM>>>(b2, out);
}

// round 14
// speedup vs baseline: 1.2620x; 1.0353x over previous
#include <cuda_runtime.h>
#include <cuda_bf16.h>
#include <math.h>
#include <cstdint>

#define DEV_INLINE __device__ __forceinline__

constexpr int B_  = 8;
constexpr int N_  = 2048;
constexpr int D_  = 384;
constexpr int H_  = 6;
constexpr int DK_ = 64;
constexpr int BN_ = B_ * N_;       // 16384
constexpr int E3_ = 3 * D_;        // 1152
constexpr int FF_ = 2 * D_;        // 768
constexpr int CH_ = 3 + D_;        // 387
constexpr int D2_ = D_ / 2;        // 192 u32 per row

// ---------------- scratch (device globals) ----------------------------------
__device__ float    g_feats[BN_ * D_];
__device__ float    g_x[BN_ * D_];
__device__ uint32_t g_hh[BN_ * D2_],   g_hl[BN_ * D2_];       // LN out split
__device__ uint32_t g_qh[BN_ * D2_],   g_ql[BN_ * D2_];       // Q split
__device__ __align__(16) uint32_t g_ksh[BN_ * D2_];           // K split (16B for cp.async)
__device__ __align__(16) uint32_t g_ksl[BN_ * D2_];
__device__ __align__(16) uint16_t g_vth[(size_t)B_ * H_ * DK_ * N_];  // V^T hi [bh][dk][n]
__device__ __align__(16) uint16_t g_vtl[(size_t)B_ * H_ * DK_ * N_];  // V^T lo
__device__ uint32_t g_ctxh[BN_ * D2_], g_ctxl[BN_ * D2_];     // attn ctx split
__device__ uint32_t g_ffh[BN_ * FF_ / 2], g_ffl[BN_ * FF_ / 2];
__device__ uint32_t g_wqh[E3_ * D2_],  g_wql[E3_ * D2_];
__device__ uint32_t g_woh[D_ * D2_],   g_wol[D_ * D2_];
__device__ uint32_t g_w1h[FF_ * D2_],  g_w1l[FF_ * D2_];
__device__ uint32_t g_w2h[D_ * FF_/2], g_w2l[D_ * FF_/2];

// ---------------- PTX helpers (sm_80-level only: target-safe) ---------------
DEV_INLINE uint32_t smem_u32(const void* p) {
    uint32_t a;
    asm("{ .reg .u64 t; cvta.to.shared.u64 t, %1; cvt.u32.u64 %0, t; }" : "=r"(a) : "l"(p));
    return a;
}
DEV_INLINE void ldsm4(uint32_t* r, uint32_t addr) {
    asm volatile("ldmatrix.sync.aligned.m8n8.x4.shared.b16 {%0,%1,%2,%3}, [%4];"
        : "=r"(r[0]), "=r"(r[1]), "=r"(r[2]), "=r"(r[3]) : "r"(addr));
}
DEV_INLINE void mma16(float* c, const uint32_t* a, uint32_t b0, uint32_t b1) {
    asm volatile("mma.sync.aligned.m16n8k16.row.col.f32.bf16.bf16.f32 "
        "{%0,%1,%2,%3}, {%4,%5,%6,%7}, {%8,%9}, {%0,%1,%2,%3};"
        : "+f"(c[0]), "+f"(c[1]), "+f"(c[2]), "+f"(c[3])
        : "r"(a[0]), "r"(a[1]), "r"(a[2]), "r"(a[3]), "r"(b0), "r"(b1));
}
DEV_INLINE void cp16(uint32_t saddr, const void* gptr) {
    asm volatile("cp.async.ca.shared.global [%0], [%1], 16;" :: "r"(saddr), "l"(gptr));
}
#define CP_COMMIT() asm volatile("cp.async.commit_group;" ::: "memory")
#define CP_WAIT0()  asm volatile("cp.async.wait_group 0;" ::: "memory")
#define CP_WAIT1()  asm volatile("cp.async.wait_group 1;" ::: "memory")

DEV_INLINE float bf_hi(float x) { return __bfloat162float(__float2bfloat16_rn(x)); }
DEV_INLINE uint32_t pack_bf(float a, float b) {
    __nv_bfloat162 t = __floats2bfloat162_rn(a, b);
    return *reinterpret_cast<uint32_t*>(&t);
}
DEV_INLINE uint16_t bf_bits(float x) {
    __nv_bfloat16 t = __float2bfloat16_rn(x);
    return *reinterpret_cast<uint16_t*>(&t);
}

// ---------------- fast exp2 (FMA pipe) --------------------------------------
DEV_INLINE float fexp2(float x) {
    x = fmaxf(x, -125.0f);
    float r = rintf(x);
    float f = x - r;
    float p = 1.535336188319500e-4f;
    p = fmaf(p, f, 1.339887440266574e-3f);
    p = fmaf(p, f, 9.618437357674640e-3f);
    p = fmaf(p, f, 5.550332471162809e-2f);
    p = fmaf(p, f, 2.402264791363012e-1f);
    p = fmaf(p, f, 6.931472028550421e-1f);
    p = fmaf(p, f, 1.0f);
    return __int_as_float(((int)r + 127) << 23) * p;
}

// ---------------- weight split (single launch, range-dispatched) ------------
// Destinations bound in device code (host-side __device__ symbol args give the
// ATS-dereferenceable host shadow — the R7/R9 silent-zero bug).
__global__ void k_split_all(const float* __restrict__ wq, const float* __restrict__ wo,
                            const float* __restrict__ w1, const float* __restrict__ w2) {
    constexpr int n0 = E3_ * D2_;
    constexpr int n1 = n0 + D_ * D2_;
    constexpr int n2 = n1 + FF_ * D2_;
    constexpr int n3 = n2 + D_ * FF_ / 2;
    int i = blockIdx.x * 256 + threadIdx.x;
    const float* src; uint32_t* dh; uint32_t* dl; int off;
    if (i < n0)      { src = wq; dh = g_wqh; dl = g_wql; off = i; }
    else if (i < n1) { src = wo; dh = g_woh; dl = g_wol; off = i - n0; }
    else if (i < n2) { src = w1; dh = g_w1h; dl = g_w1l; off = i - n1; }
    else if (i < n3) { src = w2; dh = g_w2h; dl = g_w2l; off = i - n2; }
    else return;
    float2 v = *(const float2*)&src[(size_t)off * 2];
    float h0 = bf_hi(v.x), h1 = bf_hi(v.y);
    dh[off] = pack_bf(h0, h1);
    dl[off] = pack_bf(v.x - h0, v.y - h1);
}
constexpr int SPLIT_TOT = E3_ * D2_ + D_ * D2_ + FF_ * D2_ + D_ * FF_ / 2;

// ---------------- kernel 1: transpose + LN1 + coords ------------------------
__global__ void k_pre_ln(const float* __restrict__ pts,
                         const float* __restrict__ g1,
                         const float* __restrict__ b1,
                         float* __restrict__ out) {
    __shared__ float S[32][D_];
    int b  = blockIdx.x >> 6;
    int n0 = (blockIdx.x & 63) << 5;
    const float* base = pts + (size_t)b * CH_ * N_;
    int tid = threadIdx.x;

    for (int idx = tid; idx < 32 * D_; idx += 256) {
        int nl = idx & 31, d = idx >> 5;
        S[nl][d] = base[(size_t)(3 + d) * N_ + n0 + nl];
    }
    for (int idx = tid; idx < 96; idx += 256) {
        int nl = idx & 31, c = idx >> 5;
        out[(size_t)b * CH_ * N_ + (size_t)c * N_ + n0 + nl] = base[(size_t)c * N_ + n0 + nl];
    }
    __syncthreads();

    int w = tid >> 5, lane = tid & 31;
    #pragma unroll
    for (int i = 0; i < 4; i++) {
        int nl = w * 4 + i;
        float va[6], vb[6];
        float s = 0.f, ss = 0.f;
        #pragma unroll
        for (int j = 0; j < 6; j++) {
            int d = (lane + j * 32) * 2;
            va[j] = S[nl][d]; vb[j] = S[nl][d + 1];
            s += va[j] + vb[j];
            ss = fmaf(va[j], va[j], ss); ss = fmaf(vb[j], vb[j], ss);
        }
        #pragma unroll
        for (int o = 16; o; o >>= 1) {
            s  += __shfl_xor_sync(0xffffffffu, s,  o);
            ss += __shfl_xor_sync(0xffffffffu, ss, o);
        }
        float mu   = s * (1.0f / D_);
        float var  = ss * (1.0f / D_) - mu * mu;
        float rstd = rsqrtf(var + 1e-5f);
        size_t row = (size_t)b * N_ + n0 + nl;
        #pragma unroll
        for (int j = 0; j < 6; j++) {
            int d = (lane + j * 32) * 2;
            *(float2*)&g_feats[row * D_ + d] = make_float2(va[j], vb[j]);
            float2 gg = *(const float2*)&g1[d];
            float2 bb = *(const float2*)&b1[d];
            float ha = (va[j] - mu) * rstd * gg.x + bb.x;
            float hb = (vb[j] - mu) * rstd * gg.y + bb.y;
            float h0 = bf_hi(ha), h1 = bf_hi(hb);
            g_hh[row * D2_ + lane + j * 32] = pack_bf(h0, h1);
            g_hl[row * D2_ + lane + j * 32] = pack_bf(ha - h0, hb - h1);
        }
    }
}

// ---------------- bf16x3 GEMM, pre-split operands, double-buffered ----------
// C[m,e] = sum_k A[m,k] W[e,k]; tile 128x128, BK=32, 256 thr (8 warps m32n64)
constexpr int GEMM_SMEM = 2 * 4 * 2048 * 4;   // 65536 B

template <int KD, int EPI>
__global__ __launch_bounds__(256, 2) void k_gemm_mma(const float* __restrict__ bias,
                                                     float* __restrict__ out) {
    extern __shared__ uint32_t smu[];
    const uint32_t sb = smem_u32(smu);
    constexpr int KD2 = KD / 2;

    const uint32_t *Ahg, *Alg, *Bhg, *Blg;
    if constexpr (EPI == 0)      { Ahg = g_hh;   Alg = g_hl;   Bhg = g_wqh; Blg = g_wql; }
    else if constexpr (EPI == 1) { Ahg = g_ctxh; Alg = g_ctxl; Bhg = g_woh; Blg = g_wol; }
    else if constexpr (EPI == 2) { Ahg = g_hh;   Alg = g_hl;   Bhg = g_w1h; Blg = g_w1l; }
    else                         { Ahg = g_ffh;  Alg = g_ffl;  Bhg = g_w2h; Blg = g_w2l; }

    int m0 = blockIdx.y * 128;
    int e0 = blockIdx.x * 128;
    int tid = threadIdx.x;
    int wid = tid >> 5, l = tid & 31;
    int mq = wid & 3, nh = wid >> 2;
    int lr8 = l & 7, mat = l >> 3;

    float c[2][8][4];
    #pragma unroll
    for (int i = 0; i < 2; i++)
        #pragma unroll
        for (int j = 0; j < 8; j++)
            #pragma unroll
            for (int k = 0; k < 4; k++) c[i][j][k] = 0.f;

    constexpr int KT = KD / 32;

    uint2 pah[4], pal[4], pbh[4], pbl[4];
    #pragma unroll
    for (int i = 0; i < 4; i++) {
        int idx = tid + i * 256;
        int row = idx >> 3, c2 = (idx & 7) << 1;
        size_t ao = (size_t)(m0 + row) * KD2 + c2;
        size_t bo = (size_t)(e0 + row) * KD2 + c2;
        pah[i] = *(const uint2*)&Ahg[ao];
        pal[i] = *(const uint2*)&Alg[ao];
        pbh[i] = *(const uint2*)&Bhg[bo];
        pbl[i] = *(const uint2*)&Blg[bo];
    }

    for (int kt = 0; kt < KT; kt++) {
        uint32_t* Ah = smu + (kt & 1) * 8192;
        uint32_t* Al = Ah + 2048;
        uint32_t* Bh = Ah + 4096;
        uint32_t* Bl = Ah + 6144;
        #pragma unroll
        for (int i = 0; i < 4; i++) {
            int idx = tid + i * 256;
            int row = idx >> 3, c2 = (idx & 7) << 1;
            int u = row * 16 + (((c2 >> 2) ^ ((row >> 1) & 3)) << 2) + (c2 & 3);
            *(uint2*)&Ah[u] = pah[i];
            *(uint2*)&Al[u] = pal[i];
            *(uint2*)&Bh[u] = pbh[i];
            *(uint2*)&Bl[u] = pbl[i];
        }
        if (kt + 1 < KT) {
            int k2 = (kt + 1) * 16;
            #pragma unroll
            for (int i = 0; i < 4; i++) {
                int idx = tid + i * 256;
                int row = idx >> 3, c2 = (idx & 7) << 1;
                size_t ao = (size_t)(m0 + row) * KD2 + k2 + c2;
                size_t bo = (size_t)(e0 + row) * KD2 + k2 + c2;
                pah[i] = *(const uint2*)&Ahg[ao];
                pal[i] = *(const uint2*)&Alg[ao];
                pbh[i] = *(const uint2*)&Bhg[bo];
                pbl[i] = *(const uint2*)&Blg[bo];
            }
        }
        __syncthreads();

        uint32_t stg = sb + (uint32_t)(kt & 1) * 32768u;
        uint32_t ah_u = stg, al_u = stg + 8192, bh_u = stg + 16384, bl_u = stg + 24576;
        #pragma unroll
        for (int kc = 0; kc < 2; kc++) {
            uint32_t fah[2][4], fal[2][4];
            #pragma unroll
            for (int mt = 0; mt < 2; mt++) {
                int r = mq * 32 + mt * 16 + ((mat & 1) << 3) + lr8;
                int cch = kc * 2 + (mat >> 1);
                uint32_t off = (uint32_t)((r * 16 + ((cch ^ ((r >> 1) & 3)) << 2)) * 4);
                ldsm4(fah[mt], ah_u + off);
                ldsm4(fal[mt], al_u + off);
            }
            uint32_t fbh[4][4], fbl[4][4];
            #pragma unroll
            for (int g = 0; g < 4; g++) {
                int r = nh * 64 + g * 16 + ((mat >> 1) << 3) + lr8;
                int cch = kc * 2 + (mat & 1);
                uint32_t off = (uint32_t)((r * 16 + ((cch ^ ((r >> 1) & 3)) << 2)) * 4);
                ldsm4(fbh[g], bh_u + off);
                ldsm4(fbl[g], bl_u + off);
            }
            #pragma unroll
            for (int mt = 0; mt < 2; mt++)
                #pragma unroll
                for (int nt = 0; nt < 8; nt++) {
                    uint32_t b0h = fbh[nt >> 1][(nt & 1) * 2], b1h = fbh[nt >> 1][(nt & 1) * 2 + 1];
                    uint32_t b0l = fbl[nt >> 1][(nt & 1) * 2], b1l = fbl[nt >> 1][(nt & 1) * 2 + 1];
                    mma16(c[mt][nt], fah[mt], b0h, b1h);
                    mma16(c[mt][nt], fal[mt], b0h, b1h);
                    mma16(c[mt][nt], fah[mt], b0l, b1l);
                }
        }
    }

    // epilogue
    int r0 = l >> 2, cq = (l & 3) * 2;
    #pragma unroll
    for (int mt = 0; mt < 2; mt++) {
        #pragma unroll
        for (int mi = 0; mi < 2; mi++) {
            int m  = m0 + mq * 32 + mt * 16 + r0 + mi * 8;
            int bb = m >> 11;
            int n  = m & 2047;
            #pragma unroll
            for (int nt = 0; nt < 8; nt++) {
                int e = e0 + nh * 64 + nt * 8 + cq;
                float v0 = c[mt][nt][mi * 2 + 0];
                float v1 = c[mt][nt][mi * 2 + 1];
                if (EPI == 0) {
                    if (e < 2 * D_) {
                        float h0 = bf_hi(v0), h1 = bf_hi(v1);
                        uint32_t ph = pack_bf(h0, h1);
                        uint32_t pl = pack_bf(v0 - h0, v1 - h1);
                        if (e < D_) {
                            g_qh[(size_t)m * D2_ + (e >> 1)] = ph;
                            g_ql[(size_t)m * D2_ + (e >> 1)] = pl;
                        } else {
                            g_ksh[(size_t)m * D2_ + ((e - D_) >> 1)] = ph;
                            g_ksl[(size_t)m * D2_ + ((e - D_) >> 1)] = pl;
                        }
                    } else {
                        int eh = e - 2 * D_;
                        int hh = eh >> 6, dk = eh & 63;
                        size_t base = ((size_t)(bb * H_ + hh) * DK_ + dk) * N_ + n;
                        float h0 = bf_hi(v0);
                        g_vth[base] = bf_bits(v0);
                        g_vtl[base] = bf_bits(v0 - h0);
                        float h1 = bf_hi(v1);
                        g_vth[base + N_] = bf_bits(v1);
                        g_vtl[base + N_] = bf_bits(v1 - h1);
                    }
                } else if (EPI == 1) {
                    size_t idx = (size_t)m * D_ + e;
                    float2 f  = *(const float2*)&g_feats[idx];
                    float2 bv = *(const float2*)&bias[e];
                    *(float2*)&g_x[idx] = make_float2(v0 + bv.x + f.x, v1 + bv.y + f.y);
                } else if (EPI == 2) {
                    float2 bv = *(const float2*)&bias[e];
                    float t0 = v0 + bv.x, t1 = v1 + bv.y;
                    float u0 = 0.5f * t0 * (1.0f + erff(t0 * 0.70710678118f));
                    float u1 = 0.5f * t1 * (1.0f + erff(t1 * 0.70710678118f));
                    float h0 = bf_hi(u0), h1 = bf_hi(u1);
                    g_ffh[(size_t)m * (FF_/2) + (e >> 1)] = pack_bf(h0, h1);
                    g_ffl[(size_t)m * (FF_/2) + (e >> 1)] = pack_bf(u0 - h0, u1 - h1);
                } else {
                    size_t idx = (size_t)m * D_ + e;
                    float2 xv = *(const float2*)&g_x[idx];
                    float2 bv = *(const float2*)&bias[e];
                    size_t ob = (size_t)bb * CH_ * N_;
                    out[ob + (size_t)(3 + e)     * N_ + n] = v0 + bv.x + xv.x;
                    out[ob + (size_t)(3 + e + 1) * N_ + n] = v1 + bv.y + xv.y;
                }
            }
        }
    }
}

// ---------------- flash attention: cp.async 2-stage, bf16 P, dedicated Ps ---
// grid (N/64, B*H), 128 thr (4 warps); warp = 16 query rows.
// smem u32 map (stage s in {0,1}):
//   Kh[s] = s*4096,  Kl[s] = s*4096 + 2048
//   Vh[s] = 8192 + s*4096,  Vl[s] = 8192 + s*4096 + 2048
//   Psh    = 16384 .. 18432 (dedicated; per-warp-private rows)
constexpr int ATT_SMEM = 18432 * 4;   // 72 KB

__global__ __launch_bounds__(128, 3) void k_attn_mma() {
    extern __shared__ uint32_t smu[];
    const uint32_t sb = smem_u32(smu);
    uint32_t* Psh = smu + 16384;
    const uint32_t ps_u = sb + 65536u;

    int bh = blockIdx.y;
    int b  = bh / H_, h = bh - b * H_;
    int q0 = blockIdx.x * 64;
    int tid = threadIdx.x;
    int wid = tid >> 5, l = tid & 31;
    int lr8 = l & 7, mat = l >> 3;
    int r0 = l >> 2, cq = (l & 3) * 2;

    const float SC = 0.125f * 1.44269504f;
    const size_t vtb = (size_t)(b * H_ + h) * DK_ * N_;

    auto load_tile = [&](int kt0, int s) {
        uint32_t kb = sb + (uint32_t)s * 16384u;
        uint32_t vb = sb + 32768u + (uint32_t)s * 16384u;
        #pragma unroll
        for (int t = 0; t < 4; t++) {
            int idx = tid + t * 128;          // 0..511
            int row = idx >> 3, ch = idx & 7;
            uint32_t du = (uint32_t)((row * 32 + ((ch ^ (row & 7)) << 2)) * 4);
            size_t so = (size_t)(b * N_ + kt0 + row) * D2_ + h * 32 + ch * 4;
            cp16(kb + du,        g_ksh + so);
            cp16(kb + 8192 + du, g_ksl + so);
            size_t vo = vtb + (size_t)row * N_ + kt0 + ch * 8;
            cp16(vb + du,        g_vth + vo);
            cp16(vb + 8192 + du, g_vtl + vo);
        }
    };

    // ---- prologue: tile 0 async; Q staged via stage-1 K region -------------
    load_tile(0, 0);
    CP_COMMIT();
    {
        uint32_t* Qh = smu + 4096;
        uint32_t* Ql = smu + 6144;
        #pragma unroll
        for (int i = 0; i < 8; i++) {
            int idx = tid + i * 128;
            int row = idx >> 4, c2 = (idx & 15) << 1;
            int u = row * 32 + (((c2 >> 2) ^ (row & 7)) << 2) + (c2 & 3);
            size_t so = (size_t)(b * N_ + q0 + row) * D2_ + h * 32 + c2;
            *(uint2*)&Qh[u] = *(const uint2*)&g_qh[so];
            *(uint2*)&Ql[u] = *(const uint2*)&g_ql[so];
        }
    }
    __syncthreads();
    uint32_t qh[4][4], ql[4][4];
    #pragma unroll
    for (int kc = 0; kc < 4; kc++) {
        int r = wid * 16 + ((mat & 1) << 3) + lr8;
        int cch = kc * 2 + (mat >> 1);
        uint32_t off = (uint32_t)((r * 32 + ((cch ^ (r & 7)) << 2)) * 4);
        ldsm4(qh[kc], sb + 16384u + off);
        ldsm4(ql[kc], sb + 24576u + off);
    }
    __syncthreads();   // stage-1 K region now free for tile-1 cp.async

    float o[8][4];
    #pragma unroll
    for (int i = 0; i < 8; i++)
        #pragma unroll
        for (int j = 0; j < 4; j++) o[i][j] = 0.f;
    float m0 = -1e30f, m1 = -1e30f, l0 = 0.f, l1 = 0.f;

    constexpr int NT = N_ / 64;   // 32 tiles
    for (int it = 0; it < NT; it++) {
        int p = it & 1;
        if (it + 1 < NT) { load_tile((it + 1) * 64, p ^ 1); CP_COMMIT(); CP_WAIT1(); }
        else             { CP_WAIT0(); }
        __syncthreads();   // tile 'it' visible

        uint32_t khs = sb + (uint32_t)p * 16384u;
        uint32_t kls = khs + 8192u;

        // ---- S = Q K^T (3xBF16) --------------------------------------------
        float s[8][4];
        #pragma unroll
        for (int i = 0; i < 8; i++)
            #pragma unroll
            for (int j = 0; j < 4; j++) s[i][j] = 0.f;
        #pragma unroll
        for (int kc = 0; kc < 4; kc++) {
            uint32_t fbh[4][4], fbl[4][4];
            #pragma unroll
            for (int g = 0; g < 4; g++) {
                int r = g * 16 + ((mat >> 1) << 3) + lr8;
                int cch = kc * 2 + (mat & 1);
                uint32_t off = (uint32_t)((r * 32 + ((cch ^ (r & 7)) << 2)) * 4);
                ldsm4(fbh[g], khs + off);
                ldsm4(fbl[g], kls + off);
            }
            #pragma unroll
            for (int nt = 0; nt < 8; nt++) {
                uint32_t b0h = fbh[nt >> 1][(nt & 1) * 2], b1h = fbh[nt >> 1][(nt & 1) * 2 + 1];
                uint32_t b0l = fbl[nt >> 1][(nt & 1) * 2], b1l = fbl[nt >> 1][(nt & 1) * 2 + 1];
                mma16(s[nt], qh[kc], b0h, b1h);
                mma16(s[nt], ql[kc], b0h, b1h);
                mma16(s[nt], qh[kc], b0l, b1l);
            }
        }
        #pragma unroll
        for (int nt = 0; nt < 8; nt++) {
            s[nt][0] *= SC; s[nt][1] *= SC; s[nt][2] *= SC; s[nt][3] *= SC;
        }

        // ---- online softmax; P stored bf16 (hi only, dedicated buffer) -----
        float mx0 = -1e30f, mx1 = -1e30f;
        #pragma unroll
        for (int nt = 0; nt < 8; nt++) {
            mx0 = fmaxf(mx0, fmaxf(s[nt][0], s[nt][1]));
            mx1 = fmaxf(mx1, fmaxf(s[nt][2], s[nt][3]));
        }
        mx0 = fmaxf(mx0, __shfl_xor_sync(0xffffffffu, mx0, 1));
        mx0 = fmaxf(mx0, __shfl_xor_sync(0xffffffffu, mx0, 2));
        mx1 = fmaxf(mx1, __shfl_xor_sync(0xffffffffu, mx1, 1));
        mx1 = fmaxf(mx1, __shfl_xor_sync(0xffffffffu, mx1, 2));
        float nm0 = fmaxf(m0, mx0), nm1 = fmaxf(m1, mx1);
        float f0 = fexp2(m0 - nm0), f1 = fexp2(m1 - nm1);
        m0 = nm0; m1 = nm1;
        float sum0 = 0.f, sum1 = 0.f;
        int wbase = wid * 512;
        int u0 = wbase + r0 * 32 + (l & 3);
        int u1 = wbase + (r0 + 8) * 32 + (l & 3);
        #pragma unroll
        for (int nt = 0; nt < 8; nt++) {
            float p0 = fexp2(s[nt][0] - m0);
            float p1 = fexp2(s[nt][1] - m0);
            float p2 = fexp2(s[nt][2] - m1);
            float p3 = fexp2(s[nt][3] - m1);
            sum0 += p0 + p1; sum1 += p2 + p3;
            int sw0 = (nt ^ (r0 & 7)) << 2;
            Psh[u0 + sw0] = pack_bf(p0, p1);
            Psh[u1 + sw0] = pack_bf(p2, p3);
            o[nt][0] *= f0; o[nt][1] *= f0; o[nt][2] *= f1; o[nt][3] *= f1;
        }
        sum0 += __shfl_xor_sync(0xffffffffu, sum0, 1);
        sum0 += __shfl_xor_sync(0xffffffffu, sum0, 2);
        sum1 += __shfl_xor_sync(0xffffffffu, sum1, 1);
        sum1 += __shfl_xor_sync(0xffffffffu, sum1, 2);
        l0 = l0 * f0 + sum0;
        l1 = l1 * f1 + sum1;
        __syncwarp();      // Ps rows are per-warp-private

        // ---- O += P (V_hi + V_lo): 2 MMA sets ------------------------------
        uint32_t vhs = sb + 32768u + (uint32_t)p * 16384u;
        uint32_t vls = vhs + 8192u;
        #pragma unroll
        for (int kc = 0; kc < 4; kc++) {
            int rl = ((mat & 1) << 3) + lr8;
            int cch = kc * 2 + (mat >> 1);
            uint32_t poff = (uint32_t)((wbase + rl * 32 + ((cch ^ (rl & 7)) << 2)) * 4);
            uint32_t fph[4];
            ldsm4(fph, ps_u + poff);
            uint32_t fvh[4][4], fvl[4][4];
            #pragma unroll
            for (int g = 0; g < 4; g++) {
                int r = g * 16 + ((mat >> 1) << 3) + lr8;
                int cc2 = kc * 2 + (mat & 1);
                uint32_t off = (uint32_t)((r * 32 + ((cc2 ^ (r & 7)) << 2)) * 4);
                ldsm4(fvh[g], vhs + off);
                ldsm4(fvl[g], vls + off);
            }
            #pragma unroll
            for (int nt = 0; nt < 8; nt++) {
                uint32_t b0h = fvh[nt >> 1][(nt & 1) * 2], b1h = fvh[nt >> 1][(nt & 1) * 2 + 1];
                uint32_t b0l = fvl[nt >> 1][(nt & 1) * 2], b1l = fvl[nt >> 1][(nt & 1) * 2 + 1];
                mma16(o[nt], fph, b0h, b1h);
                mma16(o[nt], fph, b0l, b1l);
            }
        }
        __syncthreads();   // tail: stage p^1 free for next iteration's cp.async
    }

    // ---- finalize: write split ctx -----------------------------------------
    float inv0 = 1.0f / l0, inv1 = 1.0f / l1;
    int qa = q0 + wid * 16 + r0;
    #pragma unroll
    for (int nt = 0; nt < 8; nt++) {
        int d2 = (h * 64 + nt * 8 + cq) >> 1;
        float a0 = o[nt][0] * inv0, a1 = o[nt][1] * inv0;
        float h0 = bf_hi(a0), h1 = bf_hi(a1);
        g_ctxh[(size_t)(b * N_ + qa) * D2_ + d2] = pack_bf(h0, h1);
        g_ctxl[(size_t)(b * N_ + qa) * D2_ + d2] = pack_bf(a0 - h0, a1 - h1);
        float a2 = o[nt][2] * inv1, a3 = o[nt][3] * inv1;
        float h2 = bf_hi(a2), h3 = bf_hi(a3);
        g_ctxh[(size_t)(b * N_ + qa + 8) * D2_ + d2] = pack_bf(h2, h3);
        g_ctxl[(size_t)(b * N_ + qa + 8) * D2_ + d2] = pack_bf(a2 - h2, a3 - h3);
    }
}

// ---------------- LN2: read g_x f32, write split ----------------------------
__global__ void k_ln2(const float* __restrict__ g2, const float* __restrict__ b2) {
    int row  = blockIdx.x * 8 + (threadIdx.x >> 5);
    int lane = threadIdx.x & 31;
    const float* xr = g_x + (size_t)row * D_;
    float va[6], vb[6];
    float s = 0.f, ss = 0.f;
    #pragma unroll
    for (int j = 0; j < 6; j++) {
        float2 t = *(const float2*)&xr[(lane + j * 32) * 2];
        va[j] = t.x; vb[j] = t.y;
        s += t.x + t.y;
        ss = fmaf(t.x, t.x, ss); ss = fmaf(t.y, t.y, ss);
    }
    #pragma unroll
    for (int o = 16; o; o >>= 1) {
        s  += __shfl_xor_sync(0xffffffffu, s,  o);
        ss += __shfl_xor_sync(0xffffffffu, ss, o);
    }
    float mu   = s * (1.0f / D_);
    float var  = ss * (1.0f / D_) - mu * mu;
    float rstd = rsqrtf(var + 1e-5f);
    #pragma unroll
    for (int j = 0; j < 6; j++) {
        int d = (lane + j * 32) * 2;
        float2 gg = *(const float2*)&g2[d];
        float2 bb = *(const float2*)&b2[d];
        float ha = (va[j] - mu) * rstd * gg.x + bb.x;
        float hb = (vb[j] - mu) * rstd * gg.y + bb.y;
        float h0 = bf_hi(ha), h1 = bf_hi(hb);
        g_hh[(size_t)row * D2_ + lane + j * 32] = pack_bf(h0, h1);
        g_hl[(size_t)row * D2_ + lane + j * 32] = pack_bf(ha - h0, hb - h1);
    }
}

// ---------------- launch ----------------------------------------------------
extern "C" void kernel_launch(void* const* d_in, const int* in_sizes, int n_in,
                              void* d_out, int out_size) {
    const float* pts   = (const float*)d_in[0];
    const float* ln1_g = (const float*)d_in[1];
    const float* ln1_b = (const float*)d_in[2];
    const float* w_qkv = (const float*)d_in[3];
    const float* w_o   = (const float*)d_in[4];
    const float* b_o   = (const float*)d_in[5];
    const float* ln2_g = (const float*)d_in[6];
    const float* ln2_b = (const float*)d_in[7];
    const float* w1    = (const float*)d_in[8];
    const float* b1    = (const float*)d_in[9];
    const float* w2    = (const float*)d_in[10];
    const float* b2    = (const float*)d_in[11];
    float* out = (float*)d_out;

    cudaFuncSetAttribute(k_gemm_mma<D_, 0>,  cudaFuncAttributeMaxDynamicSharedMemorySize, GEMM_SMEM);
    cudaFuncSetAttribute(k_gemm_mma<D_, 1>,  cudaFuncAttributeMaxDynamicSharedMemorySize, GEMM_SMEM);
    cudaFuncSetAttribute(k_gemm_mma<D_, 2>,  cudaFuncAttributeMaxDynamicSharedMemorySize, GEMM_SMEM);
    cudaFuncSetAttribute(k_gemm_mma<FF_, 3>, cudaFuncAttributeMaxDynamicSharedMemorySize, GEMM_SMEM);
    cudaFuncSetAttribute(k_attn_mma,         cudaFuncAttributeMaxDynamicSharedMemorySize, ATT_SMEM);

    k_split_all<<<(SPLIT_TOT + 255) / 256, 256>>>(w_qkv, w_o, w1, w2);
    k_pre_ln<<<512, 256>>>(pts, ln1_g, ln1_b, out);
    k_gemm_mma<D_, 0><<<dim3(E3_ / 128, BN_ / 128), 256, GEMM_SMEM>>>(nullptr, nullptr);
    k_attn_mma<<<dim3(N_ / 64, B_ * H_), 128, ATT_SMEM>>>();
    k_gemm_mma<D_, 1><<<dim3(D_ / 128, BN_ / 128), 256, GEMM_SMEM>>>(b_o, nullptr);
    k_ln2<<<BN_ / 8, 256>>>(ln2_g, ln2_b);
    k_gemm_mma<D_, 2><<<dim3(FF_ / 128, BN_ / 128), 256, GEMM_SMEM>>>(b1, nullptr);
    k_gemm_mma<FF_, 3><<<dim3(D_ / 128, BN_ / 128), 256, GEMM_SMEM>>>(b2, out);
}

// round 15
// speedup vs baseline: 1.3244x; 1.0494x over previous
#include <cuda_runtime.h>
#include <cuda_bf16.h>
#include <math.h>
#include <cstdint>

#define DEV_INLINE __device__ __forceinline__

constexpr int B_  = 8;
constexpr int N_  = 2048;
constexpr int D_  = 384;
constexpr int H_  = 6;
constexpr int DK_ = 64;
constexpr int BN_ = B_ * N_;       // 16384
constexpr int E3_ = 3 * D_;        // 1152
constexpr int FF_ = 2 * D_;        // 768
constexpr int CH_ = 3 + D_;        // 387
constexpr int D2_ = D_ / 2;        // 192 u32 per row

// ---------------- scratch (device globals) ----------------------------------
__device__ float    g_feats[BN_ * D_];
__device__ float    g_x[BN_ * D_];
__device__ uint32_t g_hh[BN_ * D2_],   g_hl[BN_ * D2_];       // LN out split
__device__ uint32_t g_qh[BN_ * D2_],   g_ql[BN_ * D2_];       // Q split (ql unused now)
__device__ __align__(16) uint32_t g_ksh[BN_ * D2_];           // K split (16B for cp.async)
__device__ __align__(16) uint32_t g_ksl[BN_ * D2_];
__device__ __align__(16) uint16_t g_vth[(size_t)B_ * H_ * DK_ * N_];  // V^T hi [bh][dk][n]
__device__ __align__(16) uint16_t g_vtl[(size_t)B_ * H_ * DK_ * N_];  // V^T lo
__device__ uint32_t g_ctxh[BN_ * D2_], g_ctxl[BN_ * D2_];     // attn ctx split
__device__ uint32_t g_ffh[BN_ * FF_ / 2], g_ffl[BN_ * FF_ / 2];
__device__ uint32_t g_wqh[E3_ * D2_],  g_wql[E3_ * D2_];
__device__ uint32_t g_woh[D_ * D2_],   g_wol[D_ * D2_];
__device__ uint32_t g_w1h[FF_ * D2_],  g_w1l[FF_ * D2_];
__device__ uint32_t g_w2h[D_ * FF_/2], g_w2l[D_ * FF_/2];

// ---------------- PTX helpers (sm_80-level only: target-safe) ---------------
DEV_INLINE uint32_t smem_u32(const void* p) {
    uint32_t a;
    asm("{ .reg .u64 t; cvta.to.shared.u64 t, %1; cvt.u32.u64 %0, t; }" : "=r"(a) : "l"(p));
    return a;
}
DEV_INLINE void ldsm4(uint32_t* r, uint32_t addr) {
    asm volatile("ldmatrix.sync.aligned.m8n8.x4.shared.b16 {%0,%1,%2,%3}, [%4];"
        : "=r"(r[0]), "=r"(r[1]), "=r"(r[2]), "=r"(r[3]) : "r"(addr));
}
DEV_INLINE void mma16(float* c, const uint32_t* a, uint32_t b0, uint32_t b1) {
    asm volatile("mma.sync.aligned.m16n8k16.row.col.f32.bf16.bf16.f32 "
        "{%0,%1,%2,%3}, {%4,%5,%6,%7}, {%8,%9}, {%0,%1,%2,%3};"
        : "+f"(c[0]), "+f"(c[1]), "+f"(c[2]), "+f"(c[3])
        : "r"(a[0]), "r"(a[1]), "r"(a[2]), "r"(a[3]), "r"(b0), "r"(b1));
}
DEV_INLINE void cp16(uint32_t saddr, const void* gptr) {
    asm volatile("cp.async.ca.shared.global [%0], [%1], 16;" :: "r"(saddr), "l"(gptr));
}
#define CP_COMMIT() asm volatile("cp.async.commit_group;" ::: "memory")
#define CP_WAIT0()  asm volatile("cp.async.wait_group 0;" ::: "memory")
#define CP_WAIT1()  asm volatile("cp.async.wait_group 1;" ::: "memory")

DEV_INLINE float bf_hi(float x) { return __bfloat162float(__float2bfloat16_rn(x)); }
DEV_INLINE uint32_t pack_bf(float a, float b) {
    __nv_bfloat162 t = __floats2bfloat162_rn(a, b);
    return *reinterpret_cast<uint32_t*>(&t);
}
DEV_INLINE uint16_t bf_bits(float x) {
    __nv_bfloat16 t = __float2bfloat16_rn(x);
    return *reinterpret_cast<uint16_t*>(&t);
}

// ---------------- fast exp2 (FMA pipe) --------------------------------------
DEV_INLINE float fexp2(float x) {
    x = fmaxf(x, -125.0f);
    float r = rintf(x);
    float f = x - r;
    float p = 1.535336188319500e-4f;
    p = fmaf(p, f, 1.339887440266574e-3f);
    p = fmaf(p, f, 9.618437357674640e-3f);
    p = fmaf(p, f, 5.550332471162809e-2f);
    p = fmaf(p, f, 2.402264791363012e-1f);
    p = fmaf(p, f, 6.931472028550421e-1f);
    p = fmaf(p, f, 1.0f);
    return __int_as_float(((int)r + 127) << 23) * p;
}

// ---------------- weight split (single launch, range-dispatched) ------------
// Destinations bound in device code (host-side __device__ symbol args give the
// ATS-dereferenceable host shadow — the R7/R9 silent-zero bug).
__global__ void k_split_all(const float* __restrict__ wq, const float* __restrict__ wo,
                            const float* __restrict__ w1, const float* __restrict__ w2) {
    constexpr int n0 = E3_ * D2_;
    constexpr int n1 = n0 + D_ * D2_;
    constexpr int n2 = n1 + FF_ * D2_;
    constexpr int n3 = n2 + D_ * FF_ / 2;
    int i = blockIdx.x * 256 + threadIdx.x;
    const float* src; uint32_t* dh; uint32_t* dl; int off;
    if (i < n0)      { src = wq; dh = g_wqh; dl = g_wql; off = i; }
    else if (i < n1) { src = wo; dh = g_woh; dl = g_wol; off = i - n0; }
    else if (i < n2) { src = w1; dh = g_w1h; dl = g_w1l; off = i - n1; }
    else if (i < n3) { src = w2; dh = g_w2h; dl = g_w2l; off = i - n2; }
    else return;
    float2 v = *(const float2*)&src[(size_t)off * 2];
    float h0 = bf_hi(v.x), h1 = bf_hi(v.y);
    dh[off] = pack_bf(h0, h1);
    dl[off] = pack_bf(v.x - h0, v.y - h1);
}
constexpr int SPLIT_TOT = E3_ * D2_ + D_ * D2_ + FF_ * D2_ + D_ * FF_ / 2;

// ---------------- kernel 1: transpose + LN1 + coords ------------------------
__global__ void k_pre_ln(const float* __restrict__ pts,
                         const float* __restrict__ g1,
                         const float* __restrict__ b1,
                         float* __restrict__ out) {
    __shared__ float S[32][D_];
    int b  = blockIdx.x >> 6;
    int n0 = (blockIdx.x & 63) << 5;
    const float* base = pts + (size_t)b * CH_ * N_;
    int tid = threadIdx.x;

    for (int idx = tid; idx < 32 * D_; idx += 256) {
        int nl = idx & 31, d = idx >> 5;
        S[nl][d] = base[(size_t)(3 + d) * N_ + n0 + nl];
    }
    for (int idx = tid; idx < 96; idx += 256) {
        int nl = idx & 31, c = idx >> 5;
        out[(size_t)b * CH_ * N_ + (size_t)c * N_ + n0 + nl] = base[(size_t)c * N_ + n0 + nl];
    }
    __syncthreads();

    int w = tid >> 5, lane = tid & 31;
    #pragma unroll
    for (int i = 0; i < 4; i++) {
        int nl = w * 4 + i;
        float va[6], vb[6];
        float s = 0.f, ss = 0.f;
        #pragma unroll
        for (int j = 0; j < 6; j++) {
            int d = (lane + j * 32) * 2;
            va[j] = S[nl][d]; vb[j] = S[nl][d + 1];
            s += va[j] + vb[j];
            ss = fmaf(va[j], va[j], ss); ss = fmaf(vb[j], vb[j], ss);
        }
        #pragma unroll
        for (int o = 16; o; o >>= 1) {
            s  += __shfl_xor_sync(0xffffffffu, s,  o);
            ss += __shfl_xor_sync(0xffffffffu, ss, o);
        }
        float mu   = s * (1.0f / D_);
        float var  = ss * (1.0f / D_) - mu * mu;
        float rstd = rsqrtf(var + 1e-5f);
        size_t row = (size_t)b * N_ + n0 + nl;
        #pragma unroll
        for (int j = 0; j < 6; j++) {
            int d = (lane + j * 32) * 2;
            *(float2*)&g_feats[row * D_ + d] = make_float2(va[j], vb[j]);
            float2 gg = *(const float2*)&g1[d];
            float2 bb = *(const float2*)&b1[d];
            float ha = (va[j] - mu) * rstd * gg.x + bb.x;
            float hb = (vb[j] - mu) * rstd * gg.y + bb.y;
            float h0 = bf_hi(ha), h1 = bf_hi(hb);
            g_hh[row * D2_ + lane + j * 32] = pack_bf(h0, h1);
            g_hl[row * D2_ + lane + j * 32] = pack_bf(ha - h0, hb - h1);
        }
    }
}

// ---------------- bf16x3 GEMM, pre-split operands, double-buffered ----------
// C[m,e] = sum_k A[m,k] W[e,k]; tile 128x128, BK=32, 256 thr (8 warps m32n64)
constexpr int GEMM_SMEM = 2 * 4 * 2048 * 4;   // 65536 B

template <int KD, int EPI>
__global__ __launch_bounds__(256, 2) void k_gemm_mma(const float* __restrict__ bias,
                                                     float* __restrict__ out) {
    extern __shared__ uint32_t smu[];
    const uint32_t sb = smem_u32(smu);
    constexpr int KD2 = KD / 2;

    const uint32_t *Ahg, *Alg, *Bhg, *Blg;
    if constexpr (EPI == 0)      { Ahg = g_hh;   Alg = g_hl;   Bhg = g_wqh; Blg = g_wql; }
    else if constexpr (EPI == 1) { Ahg = g_ctxh; Alg = g_ctxl; Bhg = g_woh; Blg = g_wol; }
    else if constexpr (EPI == 2) { Ahg = g_hh;   Alg = g_hl;   Bhg = g_w1h; Blg = g_w1l; }
    else                         { Ahg = g_ffh;  Alg = g_ffl;  Bhg = g_w2h; Blg = g_w2l; }

    int m0 = blockIdx.y * 128;
    int e0 = blockIdx.x * 128;
    int tid = threadIdx.x;
    int wid = tid >> 5, l = tid & 31;
    int mq = wid & 3, nh = wid >> 2;
    int lr8 = l & 7, mat = l >> 3;

    float c[2][8][4];
    #pragma unroll
    for (int i = 0; i < 2; i++)
        #pragma unroll
        for (int j = 0; j < 8; j++)
            #pragma unroll
            for (int k = 0; k < 4; k++) c[i][j][k] = 0.f;

    constexpr int KT = KD / 32;

    uint2 pah[4], pal[4], pbh[4], pbl[4];
    #pragma unroll
    for (int i = 0; i < 4; i++) {
        int idx = tid + i * 256;
        int row = idx >> 3, c2 = (idx & 7) << 1;
        size_t ao = (size_t)(m0 + row) * KD2 + c2;
        size_t bo = (size_t)(e0 + row) * KD2 + c2;
        pah[i] = *(const uint2*)&Ahg[ao];
        pal[i] = *(const uint2*)&Alg[ao];
        pbh[i] = *(const uint2*)&Bhg[bo];
        pbl[i] = *(const uint2*)&Blg[bo];
    }

    for (int kt = 0; kt < KT; kt++) {
        uint32_t* Ah = smu + (kt & 1) * 8192;
        uint32_t* Al = Ah + 2048;
        uint32_t* Bh = Ah + 4096;
        uint32_t* Bl = Ah + 6144;
        #pragma unroll
        for (int i = 0; i < 4; i++) {
            int idx = tid + i * 256;
            int row = idx >> 3, c2 = (idx & 7) << 1;
            int u = row * 16 + (((c2 >> 2) ^ ((row >> 1) & 3)) << 2) + (c2 & 3);
            *(uint2*)&Ah[u] = pah[i];
            *(uint2*)&Al[u] = pal[i];
            *(uint2*)&Bh[u] = pbh[i];
            *(uint2*)&Bl[u] = pbl[i];
        }
        if (kt + 1 < KT) {
            int k2 = (kt + 1) * 16;
            #pragma unroll
            for (int i = 0; i < 4; i++) {
                int idx = tid + i * 256;
                int row = idx >> 3, c2 = (idx & 7) << 1;
                size_t ao = (size_t)(m0 + row) * KD2 + k2 + c2;
                size_t bo = (size_t)(e0 + row) * KD2 + k2 + c2;
                pah[i] = *(const uint2*)&Ahg[ao];
                pal[i] = *(const uint2*)&Alg[ao];
                pbh[i] = *(const uint2*)&Bhg[bo];
                pbl[i] = *(const uint2*)&Blg[bo];
            }
        }
        __syncthreads();

        uint32_t stg = sb + (uint32_t)(kt & 1) * 32768u;
        uint32_t ah_u = stg, al_u = stg + 8192, bh_u = stg + 16384, bl_u = stg + 24576;
        #pragma unroll
        for (int kc = 0; kc < 2; kc++) {
            uint32_t fah[2][4], fal[2][4];
            #pragma unroll
            for (int mt = 0; mt < 2; mt++) {
                int r = mq * 32 + mt * 16 + ((mat & 1) << 3) + lr8;
                int cch = kc * 2 + (mat >> 1);
                uint32_t off = (uint32_t)((r * 16 + ((cch ^ ((r >> 1) & 3)) << 2)) * 4);
                ldsm4(fah[mt], ah_u + off);
                ldsm4(fal[mt], al_u + off);
            }
            uint32_t fbh[4][4], fbl[4][4];
            #pragma unroll
            for (int g = 0; g < 4; g++) {
                int r = nh * 64 + g * 16 + ((mat >> 1) << 3) + lr8;
                int cch = kc * 2 + (mat & 1);
                uint32_t off = (uint32_t)((r * 16 + ((cch ^ ((r >> 1) & 3)) << 2)) * 4);
                ldsm4(fbh[g], bh_u + off);
                ldsm4(fbl[g], bl_u + off);
            }
            #pragma unroll
            for (int mt = 0; mt < 2; mt++)
                #pragma unroll
                for (int nt = 0; nt < 8; nt++) {
                    uint32_t b0h = fbh[nt >> 1][(nt & 1) * 2], b1h = fbh[nt >> 1][(nt & 1) * 2 + 1];
                    uint32_t b0l = fbl[nt >> 1][(nt & 1) * 2], b1l = fbl[nt >> 1][(nt & 1) * 2 + 1];
                    mma16(c[mt][nt], fah[mt], b0h, b1h);
                    mma16(c[mt][nt], fal[mt], b0h, b1h);
                    mma16(c[mt][nt], fah[mt], b0l, b1l);
                }
        }
    }

    // epilogue
    int r0 = l >> 2, cq = (l & 3) * 2;
    #pragma unroll
    for (int mt = 0; mt < 2; mt++) {
        #pragma unroll
        for (int mi = 0; mi < 2; mi++) {
            int m  = m0 + mq * 32 + mt * 16 + r0 + mi * 8;
            int bb = m >> 11;
            int n  = m & 2047;
            #pragma unroll
            for (int nt = 0; nt < 8; nt++) {
                int e = e0 + nh * 64 + nt * 8 + cq;
                float v0 = c[mt][nt][mi * 2 + 0];
                float v1 = c[mt][nt][mi * 2 + 1];
                if (EPI == 0) {
                    if (e < 2 * D_) {
                        float h0 = bf_hi(v0), h1 = bf_hi(v1);
                        uint32_t ph = pack_bf(h0, h1);
                        uint32_t pl = pack_bf(v0 - h0, v1 - h1);
                        if (e < D_) {
                            g_qh[(size_t)m * D2_ + (e >> 1)] = ph;
                            g_ql[(size_t)m * D2_ + (e >> 1)] = pl;
                        } else {
                            g_ksh[(size_t)m * D2_ + ((e - D_) >> 1)] = ph;
                            g_ksl[(size_t)m * D2_ + ((e - D_) >> 1)] = pl;
                        }
                    } else {
                        int eh = e - 2 * D_;
                        int hh = eh >> 6, dk = eh & 63;
                        size_t base = ((size_t)(bb * H_ + hh) * DK_ + dk) * N_ + n;
                        float h0 = bf_hi(v0);
                        g_vth[base] = bf_bits(v0);
                        g_vtl[base] = bf_bits(v0 - h0);
                        float h1 = bf_hi(v1);
                        g_vth[base + N_] = bf_bits(v1);
                        g_vtl[base + N_] = bf_bits(v1 - h1);
                    }
                } else if (EPI == 1) {
                    size_t idx = (size_t)m * D_ + e;
                    float2 f  = *(const float2*)&g_feats[idx];
                    float2 bv = *(const float2*)&bias[e];
                    *(float2*)&g_x[idx] = make_float2(v0 + bv.x + f.x, v1 + bv.y + f.y);
                } else if (EPI == 2) {
                    float2 bv = *(const float2*)&bias[e];
                    float t0 = v0 + bv.x, t1 = v1 + bv.y;
                    float u0 = 0.5f * t0 * (1.0f + erff(t0 * 0.70710678118f));
                    float u1 = 0.5f * t1 * (1.0f + erff(t1 * 0.70710678118f));
                    float h0 = bf_hi(u0), h1 = bf_hi(u1);
                    g_ffh[(size_t)m * (FF_/2) + (e >> 1)] = pack_bf(h0, h1);
                    g_ffl[(size_t)m * (FF_/2) + (e >> 1)] = pack_bf(u0 - h0, u1 - h1);
                } else {
                    size_t idx = (size_t)m * D_ + e;
                    float2 xv = *(const float2*)&g_x[idx];
                    float2 bv = *(const float2*)&bias[e];
                    size_t ob = (size_t)bb * CH_ * N_;
                    out[ob + (size_t)(3 + e)     * N_ + n] = v0 + bv.x + xv.x;
                    out[ob + (size_t)(3 + e + 1) * N_ + n] = v1 + bv.y + xv.y;
                }
            }
        }
    }
}

// ---------------- flash attention: cp.async 2-stage, 2-term QK & PV ---------
// grid (N/64, B*H), 128 thr (4 warps); warp = 16 query rows.
// S = q_hi·(K_hi + K_lo);  O += P_bf16·(V_hi + V_lo)
// smem u32 map (stage s in {0,1}):
//   Kh[s] = s*4096,  Kl[s] = s*4096 + 2048
//   Vh[s] = 8192 + s*4096,  Vl[s] = 8192 + s*4096 + 2048
//   Psh    = 16384 .. 18432 (dedicated; per-warp-private rows)
constexpr int ATT_SMEM = 18432 * 4;   // 72 KB

__global__ __launch_bounds__(128, 3) void k_attn_mma() {
    extern __shared__ uint32_t smu[];
    const uint32_t sb = smem_u32(smu);
    uint32_t* Psh = smu + 16384;
    const uint32_t ps_u = sb + 65536u;

    int bh = blockIdx.y;
    int b  = bh / H_, h = bh - b * H_;
    int q0 = blockIdx.x * 64;
    int tid = threadIdx.x;
    int wid = tid >> 5, l = tid & 31;
    int lr8 = l & 7, mat = l >> 3;
    int r0 = l >> 2, cq = (l & 3) * 2;

    const float SC = 0.125f * 1.44269504f;
    const size_t vtb = (size_t)(b * H_ + h) * DK_ * N_;

    auto load_tile = [&](int kt0, int s) {
        uint32_t kb = sb + (uint32_t)s * 16384u;
        uint32_t vb = sb + 32768u + (uint32_t)s * 16384u;
        #pragma unroll
        for (int t = 0; t < 4; t++) {
            int idx = tid + t * 128;          // 0..511
            int row = idx >> 3, ch = idx & 7;
            uint32_t du = (uint32_t)((row * 32 + ((ch ^ (row & 7)) << 2)) * 4);
            size_t so = (size_t)(b * N_ + kt0 + row) * D2_ + h * 32 + ch * 4;
            cp16(kb + du,        g_ksh + so);
            cp16(kb + 8192 + du, g_ksl + so);
            size_t vo = vtb + (size_t)row * N_ + kt0 + ch * 8;
            cp16(vb + du,        g_vth + vo);
            cp16(vb + 8192 + du, g_vtl + vo);
        }
    };

    // ---- prologue: tile 0 async; Q_hi staged via stage-1 K region ----------
    load_tile(0, 0);
    CP_COMMIT();
    {
        uint32_t* Qh = smu + 4096;
        #pragma unroll
        for (int i = 0; i < 8; i++) {
            int idx = tid + i * 128;
            int row = idx >> 4, c2 = (idx & 15) << 1;
            int u = row * 32 + (((c2 >> 2) ^ (row & 7)) << 2) + (c2 & 3);
            size_t so = (size_t)(b * N_ + q0 + row) * D2_ + h * 32 + c2;
            *(uint2*)&Qh[u] = *(const uint2*)&g_qh[so];
        }
    }
    __syncthreads();
    uint32_t qh[4][4];
    #pragma unroll
    for (int kc = 0; kc < 4; kc++) {
        int r = wid * 16 + ((mat & 1) << 3) + lr8;
        int cch = kc * 2 + (mat >> 1);
        uint32_t off = (uint32_t)((r * 32 + ((cch ^ (r & 7)) << 2)) * 4);
        ldsm4(qh[kc], sb + 16384u + off);
    }
    __syncthreads();   // stage-1 K region now free for tile-1 cp.async

    float o[8][4];
    #pragma unroll
    for (int i = 0; i < 8; i++)
        #pragma unroll
        for (int j = 0; j < 4; j++) o[i][j] = 0.f;
    float m0 = -1e30f, m1 = -1e30f, l0 = 0.f, l1 = 0.f;

    constexpr int NT = N_ / 64;   // 32 tiles
    for (int it = 0; it < NT; it++) {
        int p = it & 1;
        if (it + 1 < NT) { load_tile((it + 1) * 64, p ^ 1); CP_COMMIT(); CP_WAIT1(); }
        else             { CP_WAIT0(); }
        __syncthreads();   // tile 'it' visible

        uint32_t khs = sb + (uint32_t)p * 16384u;
        uint32_t kls = khs + 8192u;

        // ---- S = q_hi (K_hi + K_lo): 2 MMA sets ----------------------------
        float s[8][4];
        #pragma unroll
        for (int i = 0; i < 8; i++)
            #pragma unroll
            for (int j = 0; j < 4; j++) s[i][j] = 0.f;
        #pragma unroll
        for (int kc = 0; kc < 4; kc++) {
            uint32_t fbh[4][4], fbl[4][4];
            #pragma unroll
            for (int g = 0; g < 4; g++) {
                int r = g * 16 + ((mat >> 1) << 3) + lr8;
                int cch = kc * 2 + (mat & 1);
                uint32_t off = (uint32_t)((r * 32 + ((cch ^ (r & 7)) << 2)) * 4);
                ldsm4(fbh[g], khs + off);
                ldsm4(fbl[g], kls + off);
            }
            #pragma unroll
            for (int nt = 0; nt < 8; nt++) {
                uint32_t b0h = fbh[nt >> 1][(nt & 1) * 2], b1h = fbh[nt >> 1][(nt & 1) * 2 + 1];
                uint32_t b0l = fbl[nt >> 1][(nt & 1) * 2], b1l = fbl[nt >> 1][(nt & 1) * 2 + 1];
                mma16(s[nt], qh[kc], b0h, b1h);
                mma16(s[nt], qh[kc], b0l, b1l);
            }
        }
        #pragma unroll
        for (int nt = 0; nt < 8; nt++) {
            s[nt][0] *= SC; s[nt][1] *= SC; s[nt][2] *= SC; s[nt][3] *= SC;
        }

        // ---- online softmax; P stored bf16 (hi only, dedicated buffer) -----
        float mx0 = -1e30f, mx1 = -1e30f;
        #pragma unroll
        for (int nt = 0; nt < 8; nt++) {
            mx0 = fmaxf(mx0, fmaxf(s[nt][0], s[nt][1]));
            mx1 = fmaxf(mx1, fmaxf(s[nt][2], s[nt][3]));
        }
        mx0 = fmaxf(mx0, __shfl_xor_sync(0xffffffffu, mx0, 1));
        mx0 = fmaxf(mx0, __shfl_xor_sync(0xffffffffu, mx0, 2));
        mx1 = fmaxf(mx1, __shfl_xor_sync(0xffffffffu, mx1, 1));
        mx1 = fmaxf(mx1, __shfl_xor_sync(0xffffffffu, mx1, 2));
        float nm0 = fmaxf(m0, mx0), nm1 = fmaxf(m1, mx1);
        float f0 = fexp2(m0 - nm0), f1 = fexp2(m1 - nm1);
        m0 = nm0; m1 = nm1;
        float sum0 = 0.f, sum1 = 0.f;
        int wbase = wid * 512;
        int u0 = wbase + r0 * 32 + (l & 3);
        int u1 = wbase + (r0 + 8) * 32 + (l & 3);
        #pragma unroll
        for (int nt = 0; nt < 8; nt++) {
            float p0 = fexp2(s[nt][0] - m0);
            float p1 = fexp2(s[nt][1] - m0);
            float p2 = fexp2(s[nt][2] - m1);
            float p3 = fexp2(s[nt][3] - m1);
            sum0 += p0 + p1; sum1 += p2 + p3;
            int sw0 = (nt ^ (r0 & 7)) << 2;
            Psh[u0 + sw0] = pack_bf(p0, p1);
            Psh[u1 + sw0] = pack_bf(p2, p3);
            o[nt][0] *= f0; o[nt][1] *= f0; o[nt][2] *= f1; o[nt][3] *= f1;
        }
        sum0 += __shfl_xor_sync(0xffffffffu, sum0, 1);
        sum0 += __shfl_xor_sync(0xffffffffu, sum0, 2);
        sum1 += __shfl_xor_sync(0xffffffffu, sum1, 1);
        sum1 += __shfl_xor_sync(0xffffffffu, sum1, 2);
        l0 = l0 * f0 + sum0;
        l1 = l1 * f1 + sum1;
        __syncwarp();      // Ps rows are per-warp-private

        // ---- O += P (V_hi + V_lo): 2 MMA sets ------------------------------
        uint32_t vhs = sb + 32768u + (uint32_t)p * 16384u;
        uint32_t vls = vhs + 8192u;
        #pragma unroll
        for (int kc = 0; kc < 4; kc++) {
            int rl = ((mat & 1) << 3) + lr8;
            int cch = kc * 2 + (mat >> 1);
            uint32_t poff = (uint32_t)((wbase + rl * 32 + ((cch ^ (rl & 7)) << 2)) * 4);
            uint32_t fph[4];
            ldsm4(fph, ps_u + poff);
            uint32_t fvh[4][4], fvl[4][4];
            #pragma unroll
            for (int g = 0; g < 4; g++) {
                int r = g * 16 + ((mat >> 1) << 3) + lr8;
                int cc2 = kc * 2 + (mat & 1);
                uint32_t off = (uint32_t)((r * 32 + ((cc2 ^ (r & 7)) << 2)) * 4);
                ldsm4(fvh[g], vhs + off);
                ldsm4(fvl[g], vls + off);
            }
            #pragma unroll
            for (int nt = 0; nt < 8; nt++) {
                uint32_t b0h = fvh[nt >> 1][(nt & 1) * 2], b1h = fvh[nt >> 1][(nt & 1) * 2 + 1];
                uint32_t b0l = fvl[nt >> 1][(nt & 1) * 2], b1l = fvl[nt >> 1][(nt & 1) * 2 + 1];
                mma16(o[nt], fph, b0h, b1h);
                mma16(o[nt], fph, b0l, b1l);
            }
        }
        __syncthreads();   // tail: stage p^1 free for next iteration's cp.async
    }

    // ---- finalize: write split ctx -----------------------------------------
    float inv0 = 1.0f / l0, inv1 = 1.0f / l1;
    int qa = q0 + wid * 16 + r0;
    #pragma unroll
    for (int nt = 0; nt < 8; nt++) {
        int d2 = (h * 64 + nt * 8 + cq) >> 1;
        float a0 = o[nt][0] * inv0, a1 = o[nt][1] * inv0;
        float h0 = bf_hi(a0), h1 = bf_hi(a1);
        g_ctxh[(size_t)(b * N_ + qa) * D2_ + d2] = pack_bf(h0, h1);
        g_ctxl[(size_t)(b * N_ + qa) * D2_ + d2] = pack_bf(a0 - h0, a1 - h1);
        float a2 = o[nt][2] * inv1, a3 = o[nt][3] * inv1;
        float h2 = bf_hi(a2), h3 = bf_hi(a3);
        g_ctxh[(size_t)(b * N_ + qa + 8) * D2_ + d2] = pack_bf(h2, h3);
        g_ctxl[(size_t)(b * N_ + qa + 8) * D2_ + d2] = pack_bf(a2 - h2, a3 - h3);
    }
}

// ---------------- LN2: read g_x f32, write split ----------------------------
__global__ void k_ln2(const float* __restrict__ g2, const float* __restrict__ b2) {
    int row  = blockIdx.x * 8 + (threadIdx.x >> 5);
    int lane = threadIdx.x & 31;
    const float* xr = g_x + (size_t)row * D_;
    float va[6], vb[6];
    float s = 0.f, ss = 0.f;
    #pragma unroll
    for (int j = 0; j < 6; j++) {
        float2 t = *(const float2*)&xr[(lane + j * 32) * 2];
        va[j] = t.x; vb[j] = t.y;
        s += t.x + t.y;
        ss = fmaf(t.x, t.x, ss); ss = fmaf(t.y, t.y, ss);
    }
    #pragma unroll
    for (int o = 16; o; o >>= 1) {
        s  += __shfl_xor_sync(0xffffffffu, s,  o);
        ss += __shfl_xor_sync(0xffffffffu, ss, o);
    }
    float mu   = s * (1.0f / D_);
    float var  = ss * (1.0f / D_) - mu * mu;
    float rstd = rsqrtf(var + 1e-5f);
    #pragma unroll
    for (int j = 0; j < 6; j++) {
        int d = (lane + j * 32) * 2;
        float2 gg = *(const float2*)&g2[d];
        float2 bb = *(const float2*)&b2[d];
        float ha = (va[j] - mu) * rstd * gg.x + bb.x;
        float hb = (vb[j] - mu) * rstd * gg.y + bb.y;
        float h0 = bf_hi(ha), h1 = bf_hi(hb);
        g_hh[(size_t)row * D2_ + lane + j * 32] = pack_bf(h0, h1);
        g_hl[(size_t)row * D2_ + lane + j * 32] = pack_bf(ha - h0, hb - h1);
    }
}

// ---------------- launch ----------------------------------------------------
extern "C" void kernel_launch(void* const* d_in, const int* in_sizes, int n_in,
                              void* d_out, int out_size) {
    const float* pts   = (const float*)d_in[0];
    const float* ln1_g = (const float*)d_in[1];
    const float* ln1_b = (const float*)d_in[2];
    const float* w_qkv = (const float*)d_in[3];
    const float* w_o   = (const float*)d_in[4];
    const float* b_o   = (const float*)d_in[5];
    const float* ln2_g = (const float*)d_in[6];
    const float* ln2_b = (const float*)d_in[7];
    const float* w1    = (const float*)d_in[8];
    const float* b1    = (const float*)d_in[9];
    const float* w2    = (const float*)d_in[10];
    const float* b2    = (const float*)d_in[11];
    float* out = (float*)d_out;

    cudaFuncSetAttribute(k_gemm_mma<D_, 0>,  cudaFuncAttributeMaxDynamicSharedMemorySize, GEMM_SMEM);
    cudaFuncSetAttribute(k_gemm_mma<D_, 1>,  cudaFuncAttributeMaxDynamicSharedMemorySize, GEMM_SMEM);
    cudaFuncSetAttribute(k_gemm_mma<D_, 2>,  cudaFuncAttributeMaxDynamicSharedMemorySize, GEMM_SMEM);
    cudaFuncSetAttribute(k_gemm_mma<FF_, 3>, cudaFuncAttributeMaxDynamicSharedMemorySize, GEMM_SMEM);
    cudaFuncSetAttribute(k_attn_mma,         cudaFuncAttributeMaxDynamicSharedMemorySize, ATT_SMEM);

    k_split_all<<<(SPLIT_TOT + 255) / 256, 256>>>(w_qkv, w_o, w1, w2);
    k_pre_ln<<<512, 256>>>(pts, ln1_g, ln1_b, out);
    k_gemm_mma<D_, 0><<<dim3(E3_ / 128, BN_ / 128), 256, GEMM_SMEM>>>(nullptr, nullptr);
    k_attn_mma<<<dim3(N_ / 64, B_ * H_), 128, ATT_SMEM>>>();
    k_gemm_mma<D_, 1><<<dim3(D_ / 128, BN_ / 128), 256, GEMM_SMEM>>>(b_o, nullptr);
    k_ln2<<<BN_ / 8, 256>>>(ln2_g, ln2_b);
    k_gemm_mma<D_, 2><<<dim3(FF_ / 128, BN_ / 128), 256, GEMM_SMEM>>>(b1, nullptr);
    k_gemm_mma<FF_, 3><<<dim3(D_ / 128, BN_ / 128), 256, GEMM_SMEM>>>(b2, out);
}

// round 16
// speedup vs baseline: 1.4778x; 1.1159x over previous
#include <cuda_runtime.h>
#include <cuda_bf16.h>
#include <math.h>
#include <cstdint>

#define DEV_INLINE __device__ __forceinline__

constexpr int B_  = 8;
constexpr int N_  = 2048;
constexpr int D_  = 384;
constexpr int H_  = 6;
constexpr int DK_ = 64;
constexpr int BN_ = B_ * N_;       // 16384
constexpr int E3_ = 3 * D_;        // 1152
constexpr int FF_ = 2 * D_;        // 768
constexpr int CH_ = 3 + D_;        // 387
constexpr int D2_ = D_ / 2;        // 192 u32 per row

// ---------------- scratch (device globals) ----------------------------------
__device__ float    g_feats[BN_ * D_];
__device__ float    g_x[BN_ * D_];
__device__ uint32_t g_hh[BN_ * D2_],   g_hl[BN_ * D2_];       // LN out split
__device__ uint32_t g_qh[BN_ * D2_];                          // Q hi (bf16x2)
__device__ __align__(16) uint32_t g_ksh[BN_ * D2_];           // K hi (16B for cp.async)
__device__ __align__(16) uint16_t g_vth[(size_t)B_ * H_ * DK_ * N_];  // V^T hi [bh][dk][n]
__device__ __align__(16) uint16_t g_vtl[(size_t)B_ * H_ * DK_ * N_];  // V^T lo
__device__ uint32_t g_ctxh[BN_ * D2_], g_ctxl[BN_ * D2_];     // attn ctx split
__device__ uint32_t g_ffh[BN_ * FF_ / 2], g_ffl[BN_ * FF_ / 2];
__device__ uint32_t g_wqh[E3_ * D2_],  g_wql[E3_ * D2_];
__device__ uint32_t g_woh[D_ * D2_],   g_wol[D_ * D2_];
__device__ uint32_t g_w1h[FF_ * D2_],  g_w1l[FF_ * D2_];
__device__ uint32_t g_w2h[D_ * FF_/2], g_w2l[D_ * FF_/2];

// ---------------- PTX helpers (sm_80-level only: target-safe) ---------------
DEV_INLINE uint32_t smem_u32(const void* p) {
    uint32_t a;
    asm("{ .reg .u64 t; cvta.to.shared.u64 t, %1; cvt.u32.u64 %0, t; }" : "=r"(a) : "l"(p));
    return a;
}
DEV_INLINE void ldsm4(uint32_t* r, uint32_t addr) {
    asm volatile("ldmatrix.sync.aligned.m8n8.x4.shared.b16 {%0,%1,%2,%3}, [%4];"
        : "=r"(r[0]), "=r"(r[1]), "=r"(r[2]), "=r"(r[3]) : "r"(addr));
}
DEV_INLINE void mma16(float* c, const uint32_t* a, uint32_t b0, uint32_t b1) {
    asm volatile("mma.sync.aligned.m16n8k16.row.col.f32.bf16.bf16.f32 "
        "{%0,%1,%2,%3}, {%4,%5,%6,%7}, {%8,%9}, {%0,%1,%2,%3};"
        : "+f"(c[0]), "+f"(c[1]), "+f"(c[2]), "+f"(c[3])
        : "r"(a[0]), "r"(a[1]), "r"(a[2]), "r"(a[3]), "r"(b0), "r"(b1));
}
DEV_INLINE void cp16(uint32_t saddr, const void* gptr) {
    asm volatile("cp.async.ca.shared.global [%0], [%1], 16;" :: "r"(saddr), "l"(gptr));
}
#define CP_COMMIT() asm volatile("cp.async.commit_group;" ::: "memory")
#define CP_WAIT0()  asm volatile("cp.async.wait_group 0;" ::: "memory")
#define CP_WAIT1()  asm volatile("cp.async.wait_group 1;" ::: "memory")

DEV_INLINE float bf_hi(float x) { return __bfloat162float(__float2bfloat16_rn(x)); }
DEV_INLINE uint32_t pack_bf(float a, float b) {
    __nv_bfloat162 t = __floats2bfloat162_rn(a, b);
    return *reinterpret_cast<uint32_t*>(&t);
}
DEV_INLINE uint16_t bf_bits(float x) {
    __nv_bfloat16 t = __float2bfloat16_rn(x);
    return *reinterpret_cast<uint16_t*>(&t);
}

// ---------------- fast exp2 (FMA pipe) --------------------------------------
DEV_INLINE float fexp2(float x) {
    x = fmaxf(x, -125.0f);
    float r = rintf(x);
    float f = x - r;
    float p = 1.535336188319500e-4f;
    p = fmaf(p, f, 1.339887440266574e-3f);
    p = fmaf(p, f, 9.618437357674640e-3f);
    p = fmaf(p, f, 5.550332471162809e-2f);
    p = fmaf(p, f, 2.402264791363012e-1f);
    p = fmaf(p, f, 6.931472028550421e-1f);
    p = fmaf(p, f, 1.0f);
    return __int_as_float(((int)r + 127) << 23) * p;
}

// ---------------- weight split (single launch, range-dispatched) ------------
// Destinations bound in device code (host-side __device__ symbol args give the
// ATS-dereferenceable host shadow — the R7/R9 silent-zero bug).
__global__ void k_split_all(const float* __restrict__ wq, const float* __restrict__ wo,
                            const float* __restrict__ w1, const float* __restrict__ w2) {
    constexpr int n0 = E3_ * D2_;
    constexpr int n1 = n0 + D_ * D2_;
    constexpr int n2 = n1 + FF_ * D2_;
    constexpr int n3 = n2 + D_ * FF_ / 2;
    int i = blockIdx.x * 256 + threadIdx.x;
    const float* src; uint32_t* dh; uint32_t* dl; int off;
    if (i < n0)      { src = wq; dh = g_wqh; dl = g_wql; off = i; }
    else if (i < n1) { src = wo; dh = g_woh; dl = g_wol; off = i - n0; }
    else if (i < n2) { src = w1; dh = g_w1h; dl = g_w1l; off = i - n1; }
    else if (i < n3) { src = w2; dh = g_w2h; dl = g_w2l; off = i - n2; }
    else return;
    float2 v = *(const float2*)&src[(size_t)off * 2];
    float h0 = bf_hi(v.x), h1 = bf_hi(v.y);
    dh[off] = pack_bf(h0, h1);
    dl[off] = pack_bf(v.x - h0, v.y - h1);
}
constexpr int SPLIT_TOT = E3_ * D2_ + D_ * D2_ + FF_ * D2_ + D_ * FF_ / 2;

// ---------------- kernel 1: transpose + LN1 + coords ------------------------
__global__ void k_pre_ln(const float* __restrict__ pts,
                         const float* __restrict__ g1,
                         const float* __restrict__ b1,
                         float* __restrict__ out) {
    __shared__ float S[32][D_];
    int b  = blockIdx.x >> 6;
    int n0 = (blockIdx.x & 63) << 5;
    const float* base = pts + (size_t)b * CH_ * N_;
    int tid = threadIdx.x;

    for (int idx = tid; idx < 32 * D_; idx += 256) {
        int nl = idx & 31, d = idx >> 5;
        S[nl][d] = base[(size_t)(3 + d) * N_ + n0 + nl];
    }
    for (int idx = tid; idx < 96; idx += 256) {
        int nl = idx & 31, c = idx >> 5;
        out[(size_t)b * CH_ * N_ + (size_t)c * N_ + n0 + nl] = base[(size_t)c * N_ + n0 + nl];
    }
    __syncthreads();

    int w = tid >> 5, lane = tid & 31;
    #pragma unroll
    for (int i = 0; i < 4; i++) {
        int nl = w * 4 + i;
        float va[6], vb[6];
        float s = 0.f, ss = 0.f;
        #pragma unroll
        for (int j = 0; j < 6; j++) {
            int d = (lane + j * 32) * 2;
            va[j] = S[nl][d]; vb[j] = S[nl][d + 1];
            s += va[j] + vb[j];
            ss = fmaf(va[j], va[j], ss); ss = fmaf(vb[j], vb[j], ss);
        }
        #pragma unroll
        for (int o = 16; o; o >>= 1) {
            s  += __shfl_xor_sync(0xffffffffu, s,  o);
            ss += __shfl_xor_sync(0xffffffffu, ss, o);
        }
        float mu   = s * (1.0f / D_);
        float var  = ss * (1.0f / D_) - mu * mu;
        float rstd = rsqrtf(var + 1e-5f);
        size_t row = (size_t)b * N_ + n0 + nl;
        #pragma unroll
        for (int j = 0; j < 6; j++) {
            int d = (lane + j * 32) * 2;
            *(float2*)&g_feats[row * D_ + d] = make_float2(va[j], vb[j]);
            float2 gg = *(const float2*)&g1[d];
            float2 bb = *(const float2*)&b1[d];
            float ha = (va[j] - mu) * rstd * gg.x + bb.x;
            float hb = (vb[j] - mu) * rstd * gg.y + bb.y;
            float h0 = bf_hi(ha), h1 = bf_hi(hb);
            g_hh[row * D2_ + lane + j * 32] = pack_bf(h0, h1);
            g_hl[row * D2_ + lane + j * 32] = pack_bf(ha - h0, hb - h1);
        }
    }
}

// ---------------- bf16x3 GEMM, pre-split operands, double-buffered ----------
// C[m,e] = sum_k A[m,k] W[e,k]; tile 128x128, BK=32, 256 thr (8 warps m32n64)
constexpr int GEMM_SMEM = 2 * 4 * 2048 * 4;   // 65536 B

template <int KD, int EPI>
__global__ __launch_bounds__(256, 2) void k_gemm_mma(const float* __restrict__ bias,
                                                     float* __restrict__ out) {
    extern __shared__ uint32_t smu[];
    const uint32_t sb = smem_u32(smu);
    constexpr int KD2 = KD / 2;

    const uint32_t *Ahg, *Alg, *Bhg, *Blg;
    if constexpr (EPI == 0)      { Ahg = g_hh;   Alg = g_hl;   Bhg = g_wqh; Blg = g_wql; }
    else if constexpr (EPI == 1) { Ahg = g_ctxh; Alg = g_ctxl; Bhg = g_woh; Blg = g_wol; }
    else if constexpr (EPI == 2) { Ahg = g_hh;   Alg = g_hl;   Bhg = g_w1h; Blg = g_w1l; }
    else                         { Ahg = g_ffh;  Alg = g_ffl;  Bhg = g_w2h; Blg = g_w2l; }

    int m0 = blockIdx.y * 128;
    int e0 = blockIdx.x * 128;
    int tid = threadIdx.x;
    int wid = tid >> 5, l = tid & 31;
    int mq = wid & 3, nh = wid >> 2;
    int lr8 = l & 7, mat = l >> 3;

    float c[2][8][4];
    #pragma unroll
    for (int i = 0; i < 2; i++)
        #pragma unroll
        for (int j = 0; j < 8; j++)
            #pragma unroll
            for (int k = 0; k < 4; k++) c[i][j][k] = 0.f;

    constexpr int KT = KD / 32;

    uint2 pah[4], pal[4], pbh[4], pbl[4];
    #pragma unroll
    for (int i = 0; i < 4; i++) {
        int idx = tid + i * 256;
        int row = idx >> 3, c2 = (idx & 7) << 1;
        size_t ao = (size_t)(m0 + row) * KD2 + c2;
        size_t bo = (size_t)(e0 + row) * KD2 + c2;
        pah[i] = *(const uint2*)&Ahg[ao];
        pal[i] = *(const uint2*)&Alg[ao];
        pbh[i] = *(const uint2*)&Bhg[bo];
        pbl[i] = *(const uint2*)&Blg[bo];
    }

    for (int kt = 0; kt < KT; kt++) {
        uint32_t* Ah = smu + (kt & 1) * 8192;
        uint32_t* Al = Ah + 2048;
        uint32_t* Bh = Ah + 4096;
        uint32_t* Bl = Ah + 6144;
        #pragma unroll
        for (int i = 0; i < 4; i++) {
            int idx = tid + i * 256;
            int row = idx >> 3, c2 = (idx & 7) << 1;
            int u = row * 16 + (((c2 >> 2) ^ ((row >> 1) & 3)) << 2) + (c2 & 3);
            *(uint2*)&Ah[u] = pah[i];
            *(uint2*)&Al[u] = pal[i];
            *(uint2*)&Bh[u] = pbh[i];
            *(uint2*)&Bl[u] = pbl[i];
        }
        if (kt + 1 < KT) {
            int k2 = (kt + 1) * 16;
            #pragma unroll
            for (int i = 0; i < 4; i++) {
                int idx = tid + i * 256;
                int row = idx >> 3, c2 = (idx & 7) << 1;
                size_t ao = (size_t)(m0 + row) * KD2 + k2 + c2;
                size_t bo = (size_t)(e0 + row) * KD2 + k2 + c2;
                pah[i] = *(const uint2*)&Ahg[ao];
                pal[i] = *(const uint2*)&Alg[ao];
                pbh[i] = *(const uint2*)&Bhg[bo];
                pbl[i] = *(const uint2*)&Blg[bo];
            }
        }
        __syncthreads();

        uint32_t stg = sb + (uint32_t)(kt & 1) * 32768u;
        uint32_t ah_u = stg, al_u = stg + 8192, bh_u = stg + 16384, bl_u = stg + 24576;
        #pragma unroll
        for (int kc = 0; kc < 2; kc++) {
            uint32_t fah[2][4], fal[2][4];
            #pragma unroll
            for (int mt = 0; mt < 2; mt++) {
                int r = mq * 32 + mt * 16 + ((mat & 1) << 3) + lr8;
                int cch = kc * 2 + (mat >> 1);
                uint32_t off = (uint32_t)((r * 16 + ((cch ^ ((r >> 1) & 3)) << 2)) * 4);
                ldsm4(fah[mt], ah_u + off);
                ldsm4(fal[mt], al_u + off);
            }
            uint32_t fbh[4][4], fbl[4][4];
            #pragma unroll
            for (int g = 0; g < 4; g++) {
                int r = nh * 64 + g * 16 + ((mat >> 1) << 3) + lr8;
                int cch = kc * 2 + (mat & 1);
                uint32_t off = (uint32_t)((r * 16 + ((cch ^ ((r >> 1) & 3)) << 2)) * 4);
                ldsm4(fbh[g], bh_u + off);
                ldsm4(fbl[g], bl_u + off);
            }
            #pragma unroll
            for (int mt = 0; mt < 2; mt++)
                #pragma unroll
                for (int nt = 0; nt < 8; nt++) {
                    uint32_t b0h = fbh[nt >> 1][(nt & 1) * 2], b1h = fbh[nt >> 1][(nt & 1) * 2 + 1];
                    uint32_t b0l = fbl[nt >> 1][(nt & 1) * 2], b1l = fbl[nt >> 1][(nt & 1) * 2 + 1];
                    mma16(c[mt][nt], fah[mt], b0h, b1h);
                    mma16(c[mt][nt], fal[mt], b0h, b1h);
                    mma16(c[mt][nt], fah[mt], b0l, b1l);
                }
        }
    }

    // epilogue
    int r0 = l >> 2, cq = (l & 3) * 2;
    #pragma unroll
    for (int mt = 0; mt < 2; mt++) {
        #pragma unroll
        for (int mi = 0; mi < 2; mi++) {
            int m  = m0 + mq * 32 + mt * 16 + r0 + mi * 8;
            int bb = m >> 11;
            int n  = m & 2047;
            #pragma unroll
            for (int nt = 0; nt < 8; nt++) {
                int e = e0 + nh * 64 + nt * 8 + cq;
                float v0 = c[mt][nt][mi * 2 + 0];
                float v1 = c[mt][nt][mi * 2 + 1];
                if (EPI == 0) {
                    if (e < D_) {
                        g_qh[(size_t)m * D2_ + (e >> 1)] = pack_bf(bf_hi(v0), bf_hi(v1));
                    } else if (e < 2 * D_) {
                        g_ksh[(size_t)m * D2_ + ((e - D_) >> 1)] = pack_bf(bf_hi(v0), bf_hi(v1));
                    } else {
                        int eh = e - 2 * D_;
                        int hh = eh >> 6, dk = eh & 63;
                        size_t base = ((size_t)(bb * H_ + hh) * DK_ + dk) * N_ + n;
                        float h0 = bf_hi(v0);
                        g_vth[base] = bf_bits(v0);
                        g_vtl[base] = bf_bits(v0 - h0);
                        float h1 = bf_hi(v1);
                        g_vth[base + N_] = bf_bits(v1);
                        g_vtl[base + N_] = bf_bits(v1 - h1);
                    }
                } else if (EPI == 1) {
                    size_t idx = (size_t)m * D_ + e;
                    float2 f  = *(const float2*)&g_feats[idx];
                    float2 bv = *(const float2*)&bias[e];
                    *(float2*)&g_x[idx] = make_float2(v0 + bv.x + f.x, v1 + bv.y + f.y);
                } else if (EPI == 2) {
                    float2 bv = *(const float2*)&bias[e];
                    float t0 = v0 + bv.x, t1 = v1 + bv.y;
                    float u0 = 0.5f * t0 * (1.0f + erff(t0 * 0.70710678118f));
                    float u1 = 0.5f * t1 * (1.0f + erff(t1 * 0.70710678118f));
                    float h0 = bf_hi(u0), h1 = bf_hi(u1);
                    g_ffh[(size_t)m * (FF_/2) + (e >> 1)] = pack_bf(h0, h1);
                    g_ffl[(size_t)m * (FF_/2) + (e >> 1)] = pack_bf(u0 - h0, u1 - h1);
                } else {
                    size_t idx = (size_t)m * D_ + e;
                    float2 xv = *(const float2*)&g_x[idx];
                    float2 bv = *(const float2*)&bias[e];
                    size_t ob = (size_t)bb * CH_ * N_;
                    out[ob + (size_t)(3 + e)     * N_ + n] = v0 + bv.x + xv.x;
                    out[ob + (size_t)(3 + e + 1) * N_ + n] = v1 + bv.y + xv.y;
                }
            }
        }
    }
}

// ---------------- flash attention: cp.async 2-stage, bf16 QK, 2-term PV -----
// grid (N/64, B*H), 128 thr (4 warps); warp = 16 query rows.
// S = q_hi·K_hi;  O += P_bf16·(V_hi + V_lo)
// smem bytes (stage s in {0,1}):
//   Kh[s] = s*8192                          [0 .. 16384)
//   Vh[s] = 16384 + s*16384, Vl[s] = +8192  [16384 .. 49152)
//   Psh   = 49152 .. 57344 (dedicated; per-warp-private rows)
constexpr int ATT_SMEM = 57344;   // 56 KB

__global__ __launch_bounds__(128, 3) void k_attn_mma() {
    extern __shared__ uint32_t smu[];
    const uint32_t sb = smem_u32(smu);
    uint32_t* Psh = smu + 12288;
    const uint32_t ps_u = sb + 49152u;

    int bh = blockIdx.y;
    int b  = bh / H_, h = bh - b * H_;
    int q0 = blockIdx.x * 64;
    int tid = threadIdx.x;
    int wid = tid >> 5, l = tid & 31;
    int lr8 = l & 7, mat = l >> 3;
    int r0 = l >> 2, cq = (l & 3) * 2;

    const float SC = 0.125f * 1.44269504f;
    const size_t vtb = (size_t)(b * H_ + h) * DK_ * N_;

    auto load_tile = [&](int kt0, int s) {
        uint32_t kb = sb + (uint32_t)s * 8192u;
        uint32_t vb = sb + 16384u + (uint32_t)s * 16384u;
        #pragma unroll
        for (int t = 0; t < 4; t++) {
            int idx = tid + t * 128;          // 0..511
            int row = idx >> 3, ch = idx & 7;
            uint32_t du = (uint32_t)((row * 32 + ((ch ^ (row & 7)) << 2)) * 4);
            size_t so = (size_t)(b * N_ + kt0 + row) * D2_ + h * 32 + ch * 4;
            cp16(kb + du, g_ksh + so);
            size_t vo = vtb + (size_t)row * N_ + kt0 + ch * 8;
            cp16(vb + du,         g_vth + vo);
            cp16(vb + 8192u + du, g_vtl + vo);
        }
    };

    // ---- prologue: tile 0 async; Q_hi staged via stage-1 K region ----------
    load_tile(0, 0);
    CP_COMMIT();
    {
        uint32_t* Qh = smu + 2048;            // Kh[1] region
        #pragma unroll
        for (int i = 0; i < 8; i++) {
            int idx = tid + i * 128;
            int row = idx >> 4, c2 = (idx & 15) << 1;
            int u = row * 32 + (((c2 >> 2) ^ (row & 7)) << 2) + (c2 & 3);
            size_t so = (size_t)(b * N_ + q0 + row) * D2_ + h * 32 + c2;
            *(uint2*)&Qh[u] = *(const uint2*)&g_qh[so];
        }
    }
    __syncthreads();
    uint32_t qh[4][4];
    #pragma unroll
    for (int kc = 0; kc < 4; kc++) {
        int r = wid * 16 + ((mat & 1) << 3) + lr8;
        int cch = kc * 2 + (mat >> 1);
        uint32_t off = (uint32_t)((r * 32 + ((cch ^ (r & 7)) << 2)) * 4);
        ldsm4(qh[kc], sb + 8192u + off);
    }
    __syncthreads();   // stage-1 K region now free for tile-1 cp.async

    float o[8][4];
    #pragma unroll
    for (int i = 0; i < 8; i++)
        #pragma unroll
        for (int j = 0; j < 4; j++) o[i][j] = 0.f;
    float m0 = -1e30f, m1 = -1e30f, l0 = 0.f, l1 = 0.f;

    constexpr int NT = N_ / 64;   // 32 tiles
    for (int it = 0; it < NT; it++) {
        int p = it & 1;
        if (it + 1 < NT) { load_tile((it + 1) * 64, p ^ 1); CP_COMMIT(); CP_WAIT1(); }
        else             { CP_WAIT0(); }
        __syncthreads();   // tile 'it' visible

        uint32_t khs = sb + (uint32_t)p * 8192u;

        // ---- S = q_hi K_hi: 1 MMA set --------------------------------------
        float s[8][4];
        #pragma unroll
        for (int i = 0; i < 8; i++)
            #pragma unroll
            for (int j = 0; j < 4; j++) s[i][j] = 0.f;
        #pragma unroll
        for (int kc = 0; kc < 4; kc++) {
            uint32_t fbh[4][4];
            #pragma unroll
            for (int g = 0; g < 4; g++) {
                int r = g * 16 + ((mat >> 1) << 3) + lr8;
                int cch = kc * 2 + (mat & 1);
                uint32_t off = (uint32_t)((r * 32 + ((cch ^ (r & 7)) << 2)) * 4);
                ldsm4(fbh[g], khs + off);
            }
            #pragma unroll
            for (int nt = 0; nt < 8; nt++) {
                uint32_t b0h = fbh[nt >> 1][(nt & 1) * 2], b1h = fbh[nt >> 1][(nt & 1) * 2 + 1];
                mma16(s[nt], qh[kc], b0h, b1h);
            }
        }
        #pragma unroll
        for (int nt = 0; nt < 8; nt++) {
            s[nt][0] *= SC; s[nt][1] *= SC; s[nt][2] *= SC; s[nt][3] *= SC;
        }

        // ---- online softmax; P stored bf16 (dedicated buffer) --------------
        float mx0 = -1e30f, mx1 = -1e30f;
        #pragma unroll
        for (int nt = 0; nt < 8; nt++) {
            mx0 = fmaxf(mx0, fmaxf(s[nt][0], s[nt][1]));
            mx1 = fmaxf(mx1, fmaxf(s[nt][2], s[nt][3]));
        }
        mx0 = fmaxf(mx0, __shfl_xor_sync(0xffffffffu, mx0, 1));
        mx0 = fmaxf(mx0, __shfl_xor_sync(0xffffffffu, mx0, 2));
        mx1 = fmaxf(mx1, __shfl_xor_sync(0xffffffffu, mx1, 1));
        mx1 = fmaxf(mx1, __shfl_xor_sync(0xffffffffu, mx1, 2));
        float nm0 = fmaxf(m0, mx0), nm1 = fmaxf(m1, mx1);
        float f0 = fexp2(m0 - nm0), f1 = fexp2(m1 - nm1);
        m0 = nm0; m1 = nm1;
        float sum0 = 0.f, sum1 = 0.f;
        int wbase = wid * 512;
        int u0 = wbase + r0 * 32 + (l & 3);
        int u1 = wbase + (r0 + 8) * 32 + (l & 3);
        #pragma unroll
        for (int nt = 0; nt < 8; nt++) {
            float p0 = fexp2(s[nt][0] - m0);
            float p1 = fexp2(s[nt][1] - m0);
            float p2 = fexp2(s[nt][2] - m1);
            float p3 = fexp2(s[nt][3] - m1);
            sum0 += p0 + p1; sum1 += p2 + p3;
            int sw0 = (nt ^ (r0 & 7)) << 2;
            Psh[u0 + sw0] = pack_bf(p0, p1);
            Psh[u1 + sw0] = pack_bf(p2, p3);
            o[nt][0] *= f0; o[nt][1] *= f0; o[nt][2] *= f1; o[nt][3] *= f1;
        }
        sum0 += __shfl_xor_sync(0xffffffffu, sum0, 1);
        sum0 += __shfl_xor_sync(0xffffffffu, sum0, 2);
        sum1 += __shfl_xor_sync(0xffffffffu, sum1, 1);
        sum1 += __shfl_xor_sync(0xffffffffu, sum1, 2);
        l0 = l0 * f0 + sum0;
        l1 = l1 * f1 + sum1;
        __syncwarp();      // Ps rows are per-warp-private

        // ---- O += P (V_hi + V_lo): 2 MMA sets ------------------------------
        uint32_t vhs = sb + 16384u + (uint32_t)p * 16384u;
        uint32_t vls = vhs + 8192u;
        #pragma unroll
        for (int kc = 0; kc < 4; kc++) {
            int rl = ((mat & 1) << 3) + lr8;
            int cch = kc * 2 + (mat >> 1);
            uint32_t poff = (uint32_t)((wbase + rl * 32 + ((cch ^ (rl & 7)) << 2)) * 4);
            uint32_t fph[4];
            ldsm4(fph, ps_u + poff);
            uint32_t fvh[4][4], fvl[4][4];
            #pragma unroll
            for (int g = 0; g < 4; g++) {
                int r = g * 16 + ((mat >> 1) << 3) + lr8;
                int cc2 = kc * 2 + (mat & 1);
                uint32_t off = (uint32_t)((r * 32 + ((cc2 ^ (r & 7)) << 2)) * 4);
                ldsm4(fvh[g], vhs + off);
                ldsm4(fvl[g], vls + off);
            }
            #pragma unroll
            for (int nt = 0; nt < 8; nt++) {
                uint32_t b0h = fvh[nt >> 1][(nt & 1) * 2], b1h = fvh[nt >> 1][(nt & 1) * 2 + 1];
                uint32_t b0l = fvl[nt >> 1][(nt & 1) * 2], b1l = fvl[nt >> 1][(nt & 1) * 2 + 1];
                mma16(o[nt], fph, b0h, b1h);
                mma16(o[nt], fph, b0l, b1l);
            }
        }
        __syncthreads();   // tail: stage p^1 free for next iteration's cp.async
    }

    // ---- finalize: write split ctx -----------------------------------------
    float inv0 = 1.0f / l0, inv1 = 1.0f / l1;
    int qa = q0 + wid * 16 + r0;
    #pragma unroll
    for (int nt = 0; nt < 8; nt++) {
        int d2 = (h * 64 + nt * 8 + cq) >> 1;
        float a0 = o[nt][0] * inv0, a1 = o[nt][1] * inv0;
        float h0 = bf_hi(a0), h1 = bf_hi(a1);
        g_ctxh[(size_t)(b * N_ + qa) * D2_ + d2] = pack_bf(h0, h1);
        g_ctxl[(size_t)(b * N_ + qa) * D2_ + d2] = pack_bf(a0 - h0, a1 - h1);
        float a2 = o[nt][2] * inv1, a3 = o[nt][3] * inv1;
        float h2 = bf_hi(a2), h3 = bf_hi(a3);
        g_ctxh[(size_t)(b * N_ + qa + 8) * D2_ + d2] = pack_bf(h2, h3);
        g_ctxl[(size_t)(b * N_ + qa + 8) * D2_ + d2] = pack_bf(a2 - h2, a3 - h3);
    }
}

// ---------------- LN2: read g_x f32, write split ----------------------------
__global__ void k_ln2(const float* __restrict__ g2, const float* __restrict__ b2) {
    int row  = blockIdx.x * 8 + (threadIdx.x >> 5);
    int lane = threadIdx.x & 31;
    const float* xr = g_x + (size_t)row * D_;
    float va[6], vb[6];
    float s = 0.f, ss = 0.f;
    #pragma unroll
    for (int j = 0; j < 6; j++) {
        float2 t = *(const float2*)&xr[(lane + j * 32) * 2];
        va[j] = t.x; vb[j] = t.y;
        s += t.x + t.y;
        ss = fmaf(t.x, t.x, ss); ss = fmaf(t.y, t.y, ss);
    }
    #pragma unroll
    for (int o = 16; o; o >>= 1) {
        s  += __shfl_xor_sync(0xffffffffu, s,  o);
        ss += __shfl_xor_sync(0xffffffffu, ss, o);
    }
    float mu   = s * (1.0f / D_);
    float var  = ss * (1.0f / D_) - mu * mu;
    float rstd = rsqrtf(var + 1e-5f);
    #pragma unroll
    for (int j = 0; j < 6; j++) {
        int d = (lane + j * 32) * 2;
        float2 gg = *(const float2*)&g2[d];
        float2 bb = *(const float2*)&b2[d];
        float ha = (va[j] - mu) * rstd * gg.x + bb.x;
        float hb = (vb[j] - mu) * rstd * gg.y + bb.y;
        float h0 = bf_hi(ha), h1 = bf_hi(hb);
        g_hh[(size_t)row * D2_ + lane + j * 32] = pack_bf(h0, h1);
        g_hl[(size_t)row * D2_ + lane + j * 32] = pack_bf(ha - h0, hb - h1);
    }
}

// ---------------- launch ----------------------------------------------------
extern "C" void kernel_launch(void* const* d_in, const int* in_sizes, int n_in,
                              void* d_out, int out_size) {
    const float* pts   = (const float*)d_in[0];
    const float* ln1_g = (const float*)d_in[1];
    const float* ln1_b = (const float*)d_in[2];
    const float* w_qkv = (const float*)d_in[3];
    const float* w_o   = (const float*)d_in[4];
    const float* b_o   = (const float*)d_in[5];
    const float* ln2_g = (const float*)d_in[6];
    const float* ln2_b = (const float*)d_in[7];
    const float* w1    = (const float*)d_in[8];
    const float* b1    = (const float*)d_in[9];
    const float* w2    = (const float*)d_in[10];
    const float* b2    = (const float*)d_in[11];
    float* out = (float*)d_out;

    cudaFuncSetAttribute(k_gemm_mma<D_, 0>,  cudaFuncAttributeMaxDynamicSharedMemorySize, GEMM_SMEM);
    cudaFuncSetAttribute(k_gemm_mma<D_, 1>,  cudaFuncAttributeMaxDynamicSharedMemorySize, GEMM_SMEM);
    cudaFuncSetAttribute(k_gemm_mma<D_, 2>,  cudaFuncAttributeMaxDynamicSharedMemorySize, GEMM_SMEM);
    cudaFuncSetAttribute(k_gemm_mma<FF_, 3>, cudaFuncAttributeMaxDynamicSharedMemorySize, GEMM_SMEM);
    cudaFuncSetAttribute(k_attn_mma,         cudaFuncAttributeMaxDynamicSharedMemorySize, ATT_SMEM);

    k_split_all<<<(SPLIT_TOT + 255) / 256, 256>>>(w_qkv, w_o, w1, w2);
    k_pre_ln<<<512, 256>>>(pts, ln1_g, ln1_b, out);
    k_gemm_mma<D_, 0><<<dim3(E3_ / 128, BN_ / 128), 256, GEMM_SMEM>>>(nullptr, nullptr);
    k_attn_mma<<<dim3(N_ / 64, B_ * H_), 128, ATT_SMEM>>>();
    k_gemm_mma<D_, 1><<<dim3(D_ / 128, BN_ / 128), 256, GEMM_SMEM>>>(b_o, nullptr);
    k_ln2<<<BN_ / 8, 256>>>(ln2_g, ln2_b);
    k_gemm_mma<D_, 2><<<dim3(FF_ / 128, BN_ / 128), 256, GEMM_SMEM>>>(b1, nullptr);
    k_gemm_mma<FF_, 3><<<dim3(D_ / 128, BN_ / 128), 256, GEMM_SMEM>>>(b2, out);
}

// round 17
// speedup vs baseline: 1.6642x; 1.1261x over previous
#include <cuda_runtime.h>
#include <cuda_bf16.h>
#include <math.h>
#include <cstdint>

#define DEV_INLINE __device__ __forceinline__

constexpr int B_  = 8;
constexpr int N_  = 2048;
constexpr int D_  = 384;
constexpr int H_  = 6;
constexpr int DK_ = 64;
constexpr int BN_ = B_ * N_;       // 16384
constexpr int E3_ = 3 * D_;        // 1152
constexpr int FF_ = 2 * D_;        // 768
constexpr int CH_ = 3 + D_;        // 387
constexpr int D2_ = D_ / 2;        // 192 u32 per row

// ---------------- scratch (device globals) ----------------------------------
__device__ float    g_feats[BN_ * D_];
__device__ float    g_x[BN_ * D_];
__device__ uint32_t g_hh[BN_ * D2_],   g_hl[BN_ * D2_];       // LN out split
__device__ uint32_t g_qh[BN_ * D2_];                          // Q hi (bf16x2)
__device__ __align__(16) uint32_t g_ksh[BN_ * D2_];           // K hi (16B for cp.async)
__device__ __align__(16) uint16_t g_vth[(size_t)B_ * H_ * DK_ * N_];  // V^T hi [bh][dk][n]
__device__ uint32_t g_ctxh[BN_ * D2_], g_ctxl[BN_ * D2_];     // attn ctx split
__device__ uint32_t g_ffh[BN_ * FF_ / 2], g_ffl[BN_ * FF_ / 2];
__device__ uint32_t g_wqh[E3_ * D2_],  g_wql[E3_ * D2_];
__device__ uint32_t g_woh[D_ * D2_],   g_wol[D_ * D2_];
__device__ uint32_t g_w1h[FF_ * D2_],  g_w1l[FF_ * D2_];
__device__ uint32_t g_w2h[D_ * FF_/2], g_w2l[D_ * FF_/2];

// ---------------- PTX helpers (sm_80-level only: target-safe) ---------------
DEV_INLINE uint32_t smem_u32(const void* p) {
    uint32_t a;
    asm("{ .reg .u64 t; cvta.to.shared.u64 t, %1; cvt.u32.u64 %0, t; }" : "=r"(a) : "l"(p));
    return a;
}
DEV_INLINE void ldsm4(uint32_t* r, uint32_t addr) {
    asm volatile("ldmatrix.sync.aligned.m8n8.x4.shared.b16 {%0,%1,%2,%3}, [%4];"
        : "=r"(r[0]), "=r"(r[1]), "=r"(r[2]), "=r"(r[3]) : "r"(addr));
}
DEV_INLINE void mma16(float* c, const uint32_t* a, uint32_t b0, uint32_t b1) {
    asm volatile("mma.sync.aligned.m16n8k16.row.col.f32.bf16.bf16.f32 "
        "{%0,%1,%2,%3}, {%4,%5,%6,%7}, {%8,%9}, {%0,%1,%2,%3};"
        : "+f"(c[0]), "+f"(c[1]), "+f"(c[2]), "+f"(c[3])
        : "r"(a[0]), "r"(a[1]), "r"(a[2]), "r"(a[3]), "r"(b0), "r"(b1));
}
DEV_INLINE void cp16(uint32_t saddr, const void* gptr) {
    asm volatile("cp.async.ca.shared.global [%0], [%1], 16;" :: "r"(saddr), "l"(gptr));
}
#define CP_COMMIT() asm volatile("cp.async.commit_group;" ::: "memory")
#define CP_WAIT0()  asm volatile("cp.async.wait_group 0;" ::: "memory")
#define CP_WAIT1()  asm volatile("cp.async.wait_group 1;" ::: "memory")

DEV_INLINE float bf_hi(float x) { return __bfloat162float(__float2bfloat16_rn(x)); }
DEV_INLINE uint32_t pack_bf(float a, float b) {
    __nv_bfloat162 t = __floats2bfloat162_rn(a, b);
    return *reinterpret_cast<uint32_t*>(&t);
}
DEV_INLINE uint16_t bf_bits(float x) {
    __nv_bfloat16 t = __float2bfloat16_rn(x);
    return *reinterpret_cast<uint16_t*>(&t);
}

// ---------------- fast exp2 (FMA pipe) --------------------------------------
DEV_INLINE float fexp2(float x) {
    x = fmaxf(x, -125.0f);
    float r = rintf(x);
    float f = x - r;
    float p = 1.535336188319500e-4f;
    p = fmaf(p, f, 1.339887440266574e-3f);
    p = fmaf(p, f, 9.618437357674640e-3f);
    p = fmaf(p, f, 5.550332471162809e-2f);
    p = fmaf(p, f, 2.402264791363012e-1f);
    p = fmaf(p, f, 6.931472028550421e-1f);
    p = fmaf(p, f, 1.0f);
    return __int_as_float(((int)r + 127) << 23) * p;
}

// ---------------- weight split (single launch, range-dispatched) ------------
// Destinations bound in device code (host-side __device__ symbol args give the
// ATS-dereferenceable host shadow — the R7/R9 silent-zero bug).
__global__ void k_split_all(const float* __restrict__ wq, const float* __restrict__ wo,
                            const float* __restrict__ w1, const float* __restrict__ w2) {
    constexpr int n0 = E3_ * D2_;
    constexpr int n1 = n0 + D_ * D2_;
    constexpr int n2 = n1 + FF_ * D2_;
    constexpr int n3 = n2 + D_ * FF_ / 2;
    int i = blockIdx.x * 256 + threadIdx.x;
    const float* src; uint32_t* dh; uint32_t* dl; int off;
    if (i < n0)      { src = wq; dh = g_wqh; dl = g_wql; off = i; }
    else if (i < n1) { src = wo; dh = g_woh; dl = g_wol; off = i - n0; }
    else if (i < n2) { src = w1; dh = g_w1h; dl = g_w1l; off = i - n1; }
    else if (i < n3) { src = w2; dh = g_w2h; dl = g_w2l; off = i - n2; }
    else return;
    float2 v = *(const float2*)&src[(size_t)off * 2];
    float h0 = bf_hi(v.x), h1 = bf_hi(v.y);
    dh[off] = pack_bf(h0, h1);
    dl[off] = pack_bf(v.x - h0, v.y - h1);
}
constexpr int SPLIT_TOT = E3_ * D2_ + D_ * D2_ + FF_ * D2_ + D_ * FF_ / 2;

// ---------------- kernel 1: transpose + LN1 + coords ------------------------
__global__ void k_pre_ln(const float* __restrict__ pts,
                         const float* __restrict__ g1,
                         const float* __restrict__ b1,
                         float* __restrict__ out) {
    __shared__ float S[32][D_];
    int b  = blockIdx.x >> 6;
    int n0 = (blockIdx.x & 63) << 5;
    const float* base = pts + (size_t)b * CH_ * N_;
    int tid = threadIdx.x;

    for (int idx = tid; idx < 32 * D_; idx += 256) {
        int nl = idx & 31, d = idx >> 5;
        S[nl][d] = base[(size_t)(3 + d) * N_ + n0 + nl];
    }
    for (int idx = tid; idx < 96; idx += 256) {
        int nl = idx & 31, c = idx >> 5;
        out[(size_t)b * CH_ * N_ + (size_t)c * N_ + n0 + nl] = base[(size_t)c * N_ + n0 + nl];
    }
    __syncthreads();

    int w = tid >> 5, lane = tid & 31;
    #pragma unroll
    for (int i = 0; i < 4; i++) {
        int nl = w * 4 + i;
        float va[6], vb[6];
        float s = 0.f, ss = 0.f;
        #pragma unroll
        for (int j = 0; j < 6; j++) {
            int d = (lane + j * 32) * 2;
            va[j] = S[nl][d]; vb[j] = S[nl][d + 1];
            s += va[j] + vb[j];
            ss = fmaf(va[j], va[j], ss); ss = fmaf(vb[j], vb[j], ss);
        }
        #pragma unroll
        for (int o = 16; o; o >>= 1) {
            s  += __shfl_xor_sync(0xffffffffu, s,  o);
            ss += __shfl_xor_sync(0xffffffffu, ss, o);
        }
        float mu   = s * (1.0f / D_);
        float var  = ss * (1.0f / D_) - mu * mu;
        float rstd = rsqrtf(var + 1e-5f);
        size_t row = (size_t)b * N_ + n0 + nl;
        #pragma unroll
        for (int j = 0; j < 6; j++) {
            int d = (lane + j * 32) * 2;
            *(float2*)&g_feats[row * D_ + d] = make_float2(va[j], vb[j]);
            float2 gg = *(const float2*)&g1[d];
            float2 bb = *(const float2*)&b1[d];
            float ha = (va[j] - mu) * rstd * gg.x + bb.x;
            float hb = (vb[j] - mu) * rstd * gg.y + bb.y;
            float h0 = bf_hi(ha), h1 = bf_hi(hb);
            g_hh[row * D2_ + lane + j * 32] = pack_bf(h0, h1);
            g_hl[row * D2_ + lane + j * 32] = pack_bf(ha - h0, hb - h1);
        }
    }
}

// ---------------- bf16x3 GEMM, pre-split operands, double-buffered ----------
// C[m,e] = sum_k A[m,k] W[e,k]; tile 128x128, BK=32, 256 thr (8 warps m32n64)
constexpr int GEMM_SMEM = 2 * 4 * 2048 * 4;   // 65536 B

template <int KD, int EPI>
__global__ __launch_bounds__(256, 2) void k_gemm_mma(const float* __restrict__ bias,
                                                     float* __restrict__ out) {
    extern __shared__ uint32_t smu[];
    const uint32_t sb = smem_u32(smu);
    constexpr int KD2 = KD / 2;

    const uint32_t *Ahg, *Alg, *Bhg, *Blg;
    if constexpr (EPI == 0)      { Ahg = g_hh;   Alg = g_hl;   Bhg = g_wqh; Blg = g_wql; }
    else if constexpr (EPI == 1) { Ahg = g_ctxh; Alg = g_ctxl; Bhg = g_woh; Blg = g_wol; }
    else if constexpr (EPI == 2) { Ahg = g_hh;   Alg = g_hl;   Bhg = g_w1h; Blg = g_w1l; }
    else                         { Ahg = g_ffh;  Alg = g_ffl;  Bhg = g_w2h; Blg = g_w2l; }

    int m0 = blockIdx.y * 128;
    int e0 = blockIdx.x * 128;
    int tid = threadIdx.x;
    int wid = tid >> 5, l = tid & 31;
    int mq = wid & 3, nh = wid >> 2;
    int lr8 = l & 7, mat = l >> 3;

    float c[2][8][4];
    #pragma unroll
    for (int i = 0; i < 2; i++)
        #pragma unroll
        for (int j = 0; j < 8; j++)
            #pragma unroll
            for (int k = 0; k < 4; k++) c[i][j][k] = 0.f;

    constexpr int KT = KD / 32;

    uint2 pah[4], pal[4], pbh[4], pbl[4];
    #pragma unroll
    for (int i = 0; i < 4; i++) {
        int idx = tid + i * 256;
        int row = idx >> 3, c2 = (idx & 7) << 1;
        size_t ao = (size_t)(m0 + row) * KD2 + c2;
        size_t bo = (size_t)(e0 + row) * KD2 + c2;
        pah[i] = *(const uint2*)&Ahg[ao];
        pal[i] = *(const uint2*)&Alg[ao];
        pbh[i] = *(const uint2*)&Bhg[bo];
        pbl[i] = *(const uint2*)&Blg[bo];
    }

    for (int kt = 0; kt < KT; kt++) {
        uint32_t* Ah = smu + (kt & 1) * 8192;
        uint32_t* Al = Ah + 2048;
        uint32_t* Bh = Ah + 4096;
        uint32_t* Bl = Ah + 6144;
        #pragma unroll
        for (int i = 0; i < 4; i++) {
            int idx = tid + i * 256;
            int row = idx >> 3, c2 = (idx & 7) << 1;
            int u = row * 16 + (((c2 >> 2) ^ ((row >> 1) & 3)) << 2) + (c2 & 3);
            *(uint2*)&Ah[u] = pah[i];
            *(uint2*)&Al[u] = pal[i];
            *(uint2*)&Bh[u] = pbh[i];
            *(uint2*)&Bl[u] = pbl[i];
        }
        if (kt + 1 < KT) {
            int k2 = (kt + 1) * 16;
            #pragma unroll
            for (int i = 0; i < 4; i++) {
                int idx = tid + i * 256;
                int row = idx >> 3, c2 = (idx & 7) << 1;
                size_t ao = (size_t)(m0 + row) * KD2 + k2 + c2;
                size_t bo = (size_t)(e0 + row) * KD2 + k2 + c2;
                pah[i] = *(const uint2*)&Ahg[ao];
                pal[i] = *(const uint2*)&Alg[ao];
                pbh[i] = *(const uint2*)&Bhg[bo];
                pbl[i] = *(const uint2*)&Blg[bo];
            }
        }
        __syncthreads();

        uint32_t stg = sb + (uint32_t)(kt & 1) * 32768u;
        uint32_t ah_u = stg, al_u = stg + 8192, bh_u = stg + 16384, bl_u = stg + 24576;
        #pragma unroll
        for (int kc = 0; kc < 2; kc++) {
            uint32_t fah[2][4], fal[2][4];
            #pragma unroll
            for (int mt = 0; mt < 2; mt++) {
                int r = mq * 32 + mt * 16 + ((mat & 1) << 3) + lr8;
                int cch = kc * 2 + (mat >> 1);
                uint32_t off = (uint32_t)((r * 16 + ((cch ^ ((r >> 1) & 3)) << 2)) * 4);
                ldsm4(fah[mt], ah_u + off);
                ldsm4(fal[mt], al_u + off);
            }
            uint32_t fbh[4][4], fbl[4][4];
            #pragma unroll
            for (int g = 0; g < 4; g++) {
                int r = nh * 64 + g * 16 + ((mat >> 1) << 3) + lr8;
                int cch = kc * 2 + (mat & 1);
                uint32_t off = (uint32_t)((r * 16 + ((cch ^ ((r >> 1) & 3)) << 2)) * 4);
                ldsm4(fbh[g], bh_u + off);
                ldsm4(fbl[g], bl_u + off);
            }
            #pragma unroll
            for (int mt = 0; mt < 2; mt++)
                #pragma unroll
                for (int nt = 0; nt < 8; nt++) {
                    uint32_t b0h = fbh[nt >> 1][(nt & 1) * 2], b1h = fbh[nt >> 1][(nt & 1) * 2 + 1];
                    uint32_t b0l = fbl[nt >> 1][(nt & 1) * 2], b1l = fbl[nt >> 1][(nt & 1) * 2 + 1];
                    mma16(c[mt][nt], fah[mt], b0h, b1h);
                    mma16(c[mt][nt], fal[mt], b0h, b1h);
                    mma16(c[mt][nt], fah[mt], b0l, b1l);
                }
        }
    }

    // epilogue
    int r0 = l >> 2, cq = (l & 3) * 2;
    #pragma unroll
    for (int mt = 0; mt < 2; mt++) {
        #pragma unroll
        for (int mi = 0; mi < 2; mi++) {
            int m  = m0 + mq * 32 + mt * 16 + r0 + mi * 8;
            int bb = m >> 11;
            int n  = m & 2047;
            #pragma unroll
            for (int nt = 0; nt < 8; nt++) {
                int e = e0 + nh * 64 + nt * 8 + cq;
                float v0 = c[mt][nt][mi * 2 + 0];
                float v1 = c[mt][nt][mi * 2 + 1];
                if (EPI == 0) {
                    if (e < D_) {
                        g_qh[(size_t)m * D2_ + (e >> 1)] = pack_bf(bf_hi(v0), bf_hi(v1));
                    } else if (e < 2 * D_) {
                        g_ksh[(size_t)m * D2_ + ((e - D_) >> 1)] = pack_bf(bf_hi(v0), bf_hi(v1));
                    } else {
                        int eh = e - 2 * D_;
                        int hh = eh >> 6, dk = eh & 63;
                        size_t base = ((size_t)(bb * H_ + hh) * DK_ + dk) * N_ + n;
                        g_vth[base]      = bf_bits(v0);
                        g_vth[base + N_] = bf_bits(v1);
                    }
                } else if (EPI == 1) {
                    size_t idx = (size_t)m * D_ + e;
                    float2 f  = *(const float2*)&g_feats[idx];
                    float2 bv = *(const float2*)&bias[e];
                    *(float2*)&g_x[idx] = make_float2(v0 + bv.x + f.x, v1 + bv.y + f.y);
                } else if (EPI == 2) {
                    float2 bv = *(const float2*)&bias[e];
                    float t0 = v0 + bv.x, t1 = v1 + bv.y;
                    float u0 = 0.5f * t0 * (1.0f + erff(t0 * 0.70710678118f));
                    float u1 = 0.5f * t1 * (1.0f + erff(t1 * 0.70710678118f));
                    float h0 = bf_hi(u0), h1 = bf_hi(u1);
                    g_ffh[(size_t)m * (FF_/2) + (e >> 1)] = pack_bf(h0, h1);
                    g_ffl[(size_t)m * (FF_/2) + (e >> 1)] = pack_bf(u0 - h0, u1 - h1);
                } else {
                    size_t idx = (size_t)m * D_ + e;
                    float2 xv = *(const float2*)&g_x[idx];
                    float2 bv = *(const float2*)&bias[e];
                    size_t ob = (size_t)bb * CH_ * N_;
                    out[ob + (size_t)(3 + e)     * N_ + n] = v0 + bv.x + xv.x;
                    out[ob + (size_t)(3 + e + 1) * N_ + n] = v1 + bv.y + xv.y;
                }
            }
        }
    }
}

// ---------------- flash attention: cp.async 2-stage, all-bf16 ---------------
// grid (N/64, B*H), 128 thr (4 warps); warp = 16 query rows.
// S = q_hi·K_hi;  O += P_bf16·V_hi
// smem bytes (stage s in {0,1}):
//   Kh[s] = s*8192               [0 .. 16384)
//   Vh[s] = 16384 + s*8192       [16384 .. 32768)
//   Psh   = 32768 .. 40960 (dedicated; per-warp-private rows)
constexpr int ATT_SMEM = 40960;   // 40 KB

__global__ __launch_bounds__(128, 3) void k_attn_mma() {
    extern __shared__ uint32_t smu[];
    const uint32_t sb = smem_u32(smu);
    uint32_t* Psh = smu + 8192;
    const uint32_t ps_u = sb + 32768u;

    int bh = blockIdx.y;
    int b  = bh / H_, h = bh - b * H_;
    int q0 = blockIdx.x * 64;
    int tid = threadIdx.x;
    int wid = tid >> 5, l = tid & 31;
    int lr8 = l & 7, mat = l >> 3;
    int r0 = l >> 2, cq = (l & 3) * 2;

    const float SC = 0.125f * 1.44269504f;
    const size_t vtb = (size_t)(b * H_ + h) * DK_ * N_;

    auto load_tile = [&](int kt0, int s) {
        uint32_t kb = sb + (uint32_t)s * 8192u;
        uint32_t vb = sb + 16384u + (uint32_t)s * 8192u;
        #pragma unroll
        for (int t = 0; t < 4; t++) {
            int idx = tid + t * 128;          // 0..511
            int row = idx >> 3, ch = idx & 7;
            uint32_t du = (uint32_t)((row * 32 + ((ch ^ (row & 7)) << 2)) * 4);
            size_t so = (size_t)(b * N_ + kt0 + row) * D2_ + h * 32 + ch * 4;
            cp16(kb + du, g_ksh + so);
            size_t vo = vtb + (size_t)row * N_ + kt0 + ch * 8;
            cp16(vb + du, g_vth + vo);
        }
    };

    // ---- prologue: tile 0 async; Q_hi staged via stage-1 K region ----------
    load_tile(0, 0);
    CP_COMMIT();
    {
        uint32_t* Qh = smu + 2048;            // Kh[1] region
        #pragma unroll
        for (int i = 0; i < 8; i++) {
            int idx = tid + i * 128;
            int row = idx >> 4, c2 = (idx & 15) << 1;
            int u = row * 32 + (((c2 >> 2) ^ (row & 7)) << 2) + (c2 & 3);
            size_t so = (size_t)(b * N_ + q0 + row) * D2_ + h * 32 + c2;
            *(uint2*)&Qh[u] = *(const uint2*)&g_qh[so];
        }
    }
    __syncthreads();
    uint32_t qh[4][4];
    #pragma unroll
    for (int kc = 0; kc < 4; kc++) {
        int r = wid * 16 + ((mat & 1) << 3) + lr8;
        int cch = kc * 2 + (mat >> 1);
        uint32_t off = (uint32_t)((r * 32 + ((cch ^ (r & 7)) << 2)) * 4);
        ldsm4(qh[kc], sb + 8192u + off);
    }
    __syncthreads();   // stage-1 K region now free for tile-1 cp.async

    float o[8][4];
    #pragma unroll
    for (int i = 0; i < 8; i++)
        #pragma unroll
        for (int j = 0; j < 4; j++) o[i][j] = 0.f;
    float m0 = -1e30f, m1 = -1e30f, l0 = 0.f, l1 = 0.f;

    constexpr int NT = N_ / 64;   // 32 tiles
    for (int it = 0; it < NT; it++) {
        int p = it & 1;
        if (it + 1 < NT) { load_tile((it + 1) * 64, p ^ 1); CP_COMMIT(); CP_WAIT1(); }
        else             { CP_WAIT0(); }
        __syncthreads();   // tile 'it' visible

        uint32_t khs = sb + (uint32_t)p * 8192u;

        // ---- S = q_hi K_hi: 1 MMA set --------------------------------------
        float s[8][4];
        #pragma unroll
        for (int i = 0; i < 8; i++)
            #pragma unroll
            for (int j = 0; j < 4; j++) s[i][j] = 0.f;
        #pragma unroll
        for (int kc = 0; kc < 4; kc++) {
            uint32_t fbh[4][4];
            #pragma unroll
            for (int g = 0; g < 4; g++) {
                int r = g * 16 + ((mat >> 1) << 3) + lr8;
                int cch = kc * 2 + (mat & 1);
                uint32_t off = (uint32_t)((r * 32 + ((cch ^ (r & 7)) << 2)) * 4);
                ldsm4(fbh[g], khs + off);
            }
            #pragma unroll
            for (int nt = 0; nt < 8; nt++) {
                uint32_t b0h = fbh[nt >> 1][(nt & 1) * 2], b1h = fbh[nt >> 1][(nt & 1) * 2 + 1];
                mma16(s[nt], qh[kc], b0h, b1h);
            }
        }
        #pragma unroll
        for (int nt = 0; nt < 8; nt++) {
            s[nt][0] *= SC; s[nt][1] *= SC; s[nt][2] *= SC; s[nt][3] *= SC;
        }

        // ---- online softmax; P stored bf16 (dedicated buffer) --------------
        float mx0 = -1e30f, mx1 = -1e30f;
        #pragma unroll
        for (int nt = 0; nt < 8; nt++) {
            mx0 = fmaxf(mx0, fmaxf(s[nt][0], s[nt][1]));
            mx1 = fmaxf(mx1, fmaxf(s[nt][2], s[nt][3]));
        }
        mx0 = fmaxf(mx0, __shfl_xor_sync(0xffffffffu, mx0, 1));
        mx0 = fmaxf(mx0, __shfl_xor_sync(0xffffffffu, mx0, 2));
        mx1 = fmaxf(mx1, __shfl_xor_sync(0xffffffffu, mx1, 1));
        mx1 = fmaxf(mx1, __shfl_xor_sync(0xffffffffu, mx1, 2));
        float nm0 = fmaxf(m0, mx0), nm1 = fmaxf(m1, mx1);
        float f0 = fexp2(m0 - nm0), f1 = fexp2(m1 - nm1);
        m0 = nm0; m1 = nm1;
        float sum0 = 0.f, sum1 = 0.f;
        int wbase = wid * 512;
        int u0 = wbase + r0 * 32 + (l & 3);
        int u1 = wbase + (r0 + 8) * 32 + (l & 3);
        #pragma unroll
        for (int nt = 0; nt < 8; nt++) {
            float p0 = fexp2(s[nt][0] - m0);
            float p1 = fexp2(s[nt][1] - m0);
            float p2 = fexp2(s[nt][2] - m1);
            float p3 = fexp2(s[nt][3] - m1);
            sum0 += p0 + p1; sum1 += p2 + p3;
            int sw0 = (nt ^ (r0 & 7)) << 2;
            Psh[u0 + sw0] = pack_bf(p0, p1);
            Psh[u1 + sw0] = pack_bf(p2, p3);
            o[nt][0] *= f0; o[nt][1] *= f0; o[nt][2] *= f1; o[nt][3] *= f1;
        }
        sum0 += __shfl_xor_sync(0xffffffffu, sum0, 1);
        sum0 += __shfl_xor_sync(0xffffffffu, sum0, 2);
        sum1 += __shfl_xor_sync(0xffffffffu, sum1, 1);
        sum1 += __shfl_xor_sync(0xffffffffu, sum1, 2);
        l0 = l0 * f0 + sum0;
        l1 = l1 * f1 + sum1;
        __syncwarp();      // Ps rows are per-warp-private

        // ---- O += P V_hi: 1 MMA set ----------------------------------------
        uint32_t vhs = sb + 16384u + (uint32_t)p * 8192u;
        #pragma unroll
        for (int kc = 0; kc < 4; kc++) {
            int rl = ((mat & 1) << 3) + lr8;
            int cch = kc * 2 + (mat >> 1);
            uint32_t poff = (uint32_t)((wbase + rl * 32 + ((cch ^ (rl & 7)) << 2)) * 4);
            uint32_t fph[4];
            ldsm4(fph, ps_u + poff);
            uint32_t fvh[4][4];
            #pragma unroll
            for (int g = 0; g < 4; g++) {
                int r = g * 16 + ((mat >> 1) << 3) + lr8;
                int cc2 = kc * 2 + (mat & 1);
                uint32_t off = (uint32_t)((r * 32 + ((cc2 ^ (r & 7)) << 2)) * 4);
                ldsm4(fvh[g], vhs + off);
            }
            #pragma unroll
            for (int nt = 0; nt < 8; nt++) {
                uint32_t b0h = fvh[nt >> 1][(nt & 1) * 2], b1h = fvh[nt >> 1][(nt & 1) * 2 + 1];
                mma16(o[nt], fph, b0h, b1h);
            }
        }
        __syncthreads();   // tail: stage p^1 free for next iteration's cp.async
    }

    // ---- finalize: write split ctx -----------------------------------------
    float inv0 = 1.0f / l0, inv1 = 1.0f / l1;
    int qa = q0 + wid * 16 + r0;
    #pragma unroll
    for (int nt = 0; nt < 8; nt++) {
        int d2 = (h * 64 + nt * 8 + cq) >> 1;
        float a0 = o[nt][0] * inv0, a1 = o[nt][1] * inv0;
        float h0 = bf_hi(a0), h1 = bf_hi(a1);
        g_ctxh[(size_t)(b * N_ + qa) * D2_ + d2] = pack_bf(h0, h1);
        g_ctxl[(size_t)(b * N_ + qa) * D2_ + d2] = pack_bf(a0 - h0, a1 - h1);
        float a2 = o[nt][2] * inv1, a3 = o[nt][3] * inv1;
        float h2 = bf_hi(a2), h3 = bf_hi(a3);
        g_ctxh[(size_t)(b * N_ + qa + 8) * D2_ + d2] = pack_bf(h2, h3);
        g_ctxl[(size_t)(b * N_ + qa + 8) * D2_ + d2] = pack_bf(a2 - h2, a3 - h3);
    }
}

// ---------------- LN2: read g_x f32, write split ----------------------------
__global__ void k_ln2(const float* __restrict__ g2, const float* __restrict__ b2) {
    int row  = blockIdx.x * 8 + (threadIdx.x >> 5);
    int lane = threadIdx.x & 31;
    const float* xr = g_x + (size_t)row * D_;
    float va[6], vb[6];
    float s = 0.f, ss = 0.f;
    #pragma unroll
    for (int j = 0; j < 6; j++) {
        float2 t = *(const float2*)&xr[(lane + j * 32) * 2];
        va[j] = t.x; vb[j] = t.y;
        s += t.x + t.y;
        ss = fmaf(t.x, t.x, ss); ss = fmaf(t.y, t.y, ss);
    }
    #pragma unroll
    for (int o = 16; o; o >>= 1) {
        s  += __shfl_xor_sync(0xffffffffu, s,  o);
        ss += __shfl_xor_sync(0xffffffffu, ss, o);
    }
    float mu   = s * (1.0f / D_);
    float var  = ss * (1.0f / D_) - mu * mu;
    float rstd = rsqrtf(var + 1e-5f);
    #pragma unroll
    for (int j = 0; j < 6; j++) {
        int d = (lane + j * 32) * 2;
        float2 gg = *(const float2*)&g2[d];
        float2 bb = *(const float2*)&b2[d];
        float ha = (va[j] - mu) * rstd * gg.x + bb.x;
        float hb = (vb[j] - mu) * rstd * gg.y + bb.y;
        float h0 = bf_hi(ha), h1 = bf_hi(hb);
        g_hh[(size_t)row * D2_ + lane + j * 32] = pack_bf(h0, h1);
        g_hl[(size_t)row * D2_ + lane + j * 32] = pack_bf(ha - h0, hb - h1);
    }
}

// ---------------- launch ----------------------------------------------------
extern "C" void kernel_launch(void* const* d_in, const int* in_sizes, int n_in,
                              void* d_out, int out_size) {
    const float* pts   = (const float*)d_in[0];
    const float* ln1_g = (const float*)d_in[1];
    const float* ln1_b = (const float*)d_in[2];
    const float* w_qkv = (const float*)d_in[3];
    const float* w_o   = (const float*)d_in[4];
    const float* b_o   = (const float*)d_in[5];
    const float* ln2_g = (const float*)d_in[6];
    const float* ln2_b = (const float*)d_in[7];
    const float* w1    = (const float*)d_in[8];
    const float* b1    = (const float*)d_in[9];
    const float* w2    = (const float*)d_in[10];
    const float* b2    = (const float*)d_in[11];
    float* out = (float*)d_out;

    cudaFuncSetAttribute(k_gemm_mma<D_, 0>,  cudaFuncAttributeMaxDynamicSharedMemorySize, GEMM_SMEM);
    cudaFuncSetAttribute(k_gemm_mma<D_, 1>,  cudaFuncAttributeMaxDynamicSharedMemorySize, GEMM_SMEM);
    cudaFuncSetAttribute(k_gemm_mma<D_, 2>,  cudaFuncAttributeMaxDynamicSharedMemorySize, GEMM_SMEM);
    cudaFuncSetAttribute(k_gemm_mma<FF_, 3>, cudaFuncAttributeMaxDynamicSharedMemorySize, GEMM_SMEM);
    cudaFuncSetAttribute(k_attn_mma,         cudaFuncAttributeMaxDynamicSharedMemorySize, ATT_SMEM);

    k_split_all<<<(SPLIT_TOT + 255) / 256, 256>>>(w_qkv, w_o, w1, w2);
    k_pre_ln<<<512, 256>>>(pts, ln1_g, ln1_b, out);
    k_gemm_mma<D_, 0><<<dim3(E3_ / 128, BN_ / 128), 256, GEMM_SMEM>>>(nullptr, nullptr);
    k_attn_mma<<<dim3(N_ / 64, B_ * H_), 128, ATT_SMEM>>>();
    k_gemm_mma<D_, 1><<<dim3(D_ / 128, BN_ / 128), 256, GEMM_SMEM>>>(b_o, nullptr);
    k_ln2<<<BN_ / 8, 256>>>(ln2_g, ln2_b);
    k_gemm_mma<D_, 2><<<dim3(FF_ / 128, BN_ / 128), 256, GEMM_SMEM>>>(b1, nullptr);
    k_gemm_mma<FF_, 3><<<dim3(D_ / 128, BN_ / 128), 256, GEMM_SMEM>>>(b2, out);
}